// round 1
// baseline (speedup 1.0000x reference)
#include <cuda_runtime.h>
#include <math.h>
#include <float.h>

#define HW    65536
#define CIN   512
#define HALF  256
#define NUM   64
#define NPP   1024
#define W_IMG 256
#define DPAD  68

// scratch (device globals: allocation-free rule)
__device__ float g_q[NUM * NPP * HALF];       // (pn, ch) q, scaled
__device__ float g_kp[HALF * NUM];            // (ch, patch) pooled k
__device__ float g_vp[NUM * HALF];            // (patch, ch) pooled v
__device__ float g_attn[NUM * NPP * NUM];     // (pn, m)
__device__ float g_mid[NUM * NPP * HALF];     // (pn, ch) attention output
__device__ float g_pscale[1280];              // fused BN scale (q,k,v,o)
__device__ float g_pbias[1280];               // fused BN bias

// ---------------------------------------------------------------------------
// prep: fused BN params + zero pooled accumulators (must re-zero every launch)
// ---------------------------------------------------------------------------
__global__ void prep_kernel(
    const float* qg, const float* qb, const float* qm, const float* qv,
    const float* kg, const float* kb, const float* km, const float* kv,
    const float* vg, const float* vb, const float* vm, const float* vv,
    const float* og, const float* ob, const float* om, const float* ov)
{
    int i = blockIdx.x * blockDim.x + threadIdx.x;
    if (i < 1280) {
        const float *G, *B, *M, *V; float f; int r;
        if (i < 256)      { G = qg; B = qb; M = qm; V = qv; f = 0.044194173824159216f; r = i; }       // 1/sqrt(512)
        else if (i < 512) { G = kg; B = kb; M = km; V = kv; f = 1.0f / 1024.0f;        r = i - 256; } // pool mean
        else if (i < 768) { G = vg; B = vb; M = vm; V = vv; f = 1.0f / 1024.0f;        r = i - 512; }
        else              { G = og; B = ob; M = om; V = ov; f = 1.0f;                  r = i - 768; }
        float s = G[r] * rsqrtf(V[r] + 1e-5f);
        g_pscale[i] = s * f;
        g_pbias[i]  = (B[r] - M[r] * s) * f;
    }
    int z = i - 1280;
    if (z >= 0 && z < HALF * NUM) g_kp[z] = 0.0f;
    z -= HALF * NUM;
    if (z >= 0 && z < NUM * HALF) g_vp[z] = 0.0f;
}

// ---------------------------------------------------------------------------
// QKV: Y[pix][oc] = sum_c x[c][pix] * W[oc][c], fused BN+ReLU epilogue.
// oc in [0,256): q (write patch layout); [256,512): k pool; [512,768): v pool.
// grid (12 oc-tiles fast, 1024 pix-tiles) for L2 reuse of x tiles.
// ---------------------------------------------------------------------------
__global__ void __launch_bounds__(256) qkv_kernel(
    const float* __restrict__ x, const float* __restrict__ qw,
    const float* __restrict__ kw, const float* __restrict__ vw)
{
    __shared__ float As[16][64];   // x tile   [kk][pix_l]
    __shared__ float Bs[16][65];   // W tile   [kk][oc_l] (padded vs transposed-store conflicts)
    __shared__ float red[64][2];

    const int t  = threadIdx.x;
    const int tx = t & 15, ty = t >> 4;
    const int oc0  = blockIdx.x * 64;
    const int pix0 = blockIdx.y * 64;

    const float* Wp; int ocr;
    if (oc0 < 256)      { Wp = qw; ocr = oc0; }
    else if (oc0 < 512) { Wp = kw; ocr = oc0 - 256; }
    else                { Wp = vw; ocr = oc0 - 512; }

    float acc[4][4];
#pragma unroll
    for (int i = 0; i < 4; i++)
#pragma unroll
        for (int j = 0; j < 4; j++) acc[i][j] = 0.0f;

    for (int k0 = 0; k0 < CIN; k0 += 16) {
#pragma unroll
        for (int u = 0; u < 4; u++) {
            int e = t + u * 256;
            As[e >> 6][e & 63] = x[(k0 + (e >> 6)) * HW + pix0 + (e & 63)];
            Bs[e & 15][e >> 4] = Wp[(ocr + (e >> 4)) * CIN + k0 + (e & 15)];
        }
        __syncthreads();
#pragma unroll
        for (int kk = 0; kk < 16; kk++) {
            float av[4], bv[4];
#pragma unroll
            for (int i = 0; i < 4; i++) av[i] = As[kk][i * 16 + ty];
#pragma unroll
            for (int j = 0; j < 4; j++) bv[j] = Bs[kk][j * 16 + tx];
#pragma unroll
            for (int i = 0; i < 4; i++)
#pragma unroll
                for (int j = 0; j < 4; j++) acc[i][j] = fmaf(av[i], bv[j], acc[i][j]);
        }
        __syncthreads();
    }

    if (oc0 < 256) {
        // q: BN+ReLU (scale includes c^-0.5), write (pn, oc)
#pragma unroll
        for (int i = 0; i < 4; i++) {
            int pix = pix0 + i * 16 + ty;
            int h = pix >> 8, w = pix & 255;
            int pn = (((h >> 5) << 3) + (w >> 5)) * NPP + ((h & 31) << 5) + (w & 31);
#pragma unroll
            for (int j = 0; j < 4; j++) {
                int oc = oc0 + j * 16 + tx;
                g_q[pn * HALF + oc] =
                    fmaxf(fmaf(acc[i][j], g_pscale[oc], g_pbias[oc]), 0.0f);
            }
        }
    } else {
        // k/v: BN+ReLU then patch-pool (1/1024 folded into scale/bias)
        if (t < 128) red[t >> 1][t & 1] = 0.0f;
        __syncthreads();
#pragma unroll
        for (int i = 0; i < 4; i++) {
            int pl = (i * 16 + ty) >> 5;   // which of the 2 patches this pixel-tile spans
#pragma unroll
            for (int j = 0; j < 4; j++) {
                int ocl = j * 16 + tx;
                int oc  = oc0 + ocl;
                float v = fmaxf(fmaf(acc[i][j], g_pscale[oc], g_pbias[oc]), 0.0f);
                atomicAdd(&red[ocl][pl], v);
            }
        }
        __syncthreads();
        if (t < 128) {
            int ocl = t >> 1, pl = t & 1;
            int h = pix0 >> 8;
            int p = ((h >> 5) << 3) + ((pix0 & 255) >> 5) + pl;
            float v = red[ocl][pl];
            if (oc0 < 512) atomicAdd(&g_kp[(oc0 - 256 + ocl) * NUM + p], v);
            else           atomicAdd(&g_vp[p * HALF + (oc0 - 512 + ocl)], v);
        }
    }
}

// ---------------------------------------------------------------------------
// attn[pn][m] = sum_ch q[pn][ch] * kp[ch][m]   (per patch, 1024x64, K=256)
// ---------------------------------------------------------------------------
__global__ void __launch_bounds__(256) attnqk_kernel()
{
    __shared__ float As[16][65];   // q  [kk][n_l]
    __shared__ float Bs[16][64];   // kp [kk][m]

    const int t  = threadIdx.x;
    const int tx = t & 15, ty = t >> 4;
    const int n0 = blockIdx.x * 64;
    const int p  = blockIdx.y;
    const float* qb = g_q + (p * NPP + n0) * HALF;

    float acc[4][4];
#pragma unroll
    for (int i = 0; i < 4; i++)
#pragma unroll
        for (int j = 0; j < 4; j++) acc[i][j] = 0.0f;

    for (int k0 = 0; k0 < HALF; k0 += 16) {
#pragma unroll
        for (int u = 0; u < 4; u++) {
            int e = t + u * 256;
            As[e & 15][e >> 4] = qb[(e >> 4) * HALF + k0 + (e & 15)];
            Bs[e >> 6][e & 63] = g_kp[(k0 + (e >> 6)) * NUM + (e & 63)];
        }
        __syncthreads();
#pragma unroll
        for (int kk = 0; kk < 16; kk++) {
            float av[4], bv[4];
#pragma unroll
            for (int i = 0; i < 4; i++) av[i] = As[kk][i * 16 + ty];
#pragma unroll
            for (int j = 0; j < 4; j++) bv[j] = Bs[kk][j * 16 + tx];
#pragma unroll
            for (int i = 0; i < 4; i++)
#pragma unroll
                for (int j = 0; j < 4; j++) acc[i][j] = fmaf(av[i], bv[j], acc[i][j]);
        }
        __syncthreads();
    }

#pragma unroll
    for (int i = 0; i < 4; i++) {
        int n = n0 + i * 16 + ty;
#pragma unroll
        for (int j = 0; j < 4; j++)
            g_attn[(p * NPP + n) * NUM + j * 16 + tx] = acc[i][j];
    }
}

// ---------------------------------------------------------------------------
// Per patch: flash self-attention on attn (Q=K=V=attn, seq 1024, dim 64),
// then final softmax(attn + corr_map) over 64, then out = F @ vp -> g_mid.
// One block = 64 rows of one patch. Dynamic smem: 4 x 64 x 68 floats.
// ---------------------------------------------------------------------------
__global__ void __launch_bounds__(256) corr_kernel()
{
    extern __shared__ float sm[];
    float* Qs = sm;                 // [64][DPAD] transposed: Qs[d][n_l]
    float* Ks = Qs + 64 * DPAD;     // [64][DPAD] transposed: Ks[d][j_l]
    float* Vs = Ks + 64 * DPAD;     // [64][DPAD] natural:    Vs[j_l][d]
    float* Ps = Vs + 64 * DPAD;     // [64][DPAD] natural:    Ps[n_l][j_l]

    const int t  = threadIdx.x;
    const int tx = t & 15, ty = t >> 4;
    const int n0 = blockIdx.x * 64;
    const int p  = blockIdx.y;
    const float* ab = g_attn + p * NPP * NUM;

    // load Q tile transposed
#pragma unroll
    for (int u = 0; u < 16; u++) {
        int e = t + u * 256;
        int nl = e >> 6, d = e & 63;
        Qs[d * DPAD + nl] = ab[(n0 + nl) * NUM + d];
    }

    float mi[4], li[4], o[4][4];
#pragma unroll
    for (int i = 0; i < 4; i++) {
        mi[i] = -FLT_MAX; li[i] = 0.0f;
#pragma unroll
        for (int l = 0; l < 4; l++) o[i][l] = 0.0f;
    }

    for (int jt = 0; jt < 16; jt++) {
        __syncthreads();
#pragma unroll
        for (int u = 0; u < 16; u++) {
            int e = t + u * 256;
            int jl = e >> 6, d = e & 63;
            float v = ab[(jt * 64 + jl) * NUM + d];
            Ks[d * DPAD + jl] = v;
            Vs[jl * DPAD + d] = v;
        }
        __syncthreads();

        // scores S[n][j] = sum_d a[n][d] a[j][d]
        float s[4][4];
#pragma unroll
        for (int i = 0; i < 4; i++)
#pragma unroll
            for (int j = 0; j < 4; j++) s[i][j] = 0.0f;
#pragma unroll 16
        for (int d = 0; d < 64; d++) {
            float4 q4 = *(const float4*)&Qs[d * DPAD + ty * 4];
            float4 k4 = *(const float4*)&Ks[d * DPAD + tx * 4];
            float qa[4] = {q4.x, q4.y, q4.z, q4.w};
            float kb[4] = {k4.x, k4.y, k4.z, k4.w};
#pragma unroll
            for (int i = 0; i < 4; i++)
#pragma unroll
                for (int j = 0; j < 4; j++) s[i][j] = fmaf(qa[i], kb[j], s[i][j]);
        }

        // online softmax (row stats across 16 tx lanes; shfl width 16)
#pragma unroll
        for (int i = 0; i < 4; i++) {
            float rmax = fmaxf(fmaxf(s[i][0], s[i][1]), fmaxf(s[i][2], s[i][3]));
#pragma unroll
            for (int m_ = 8; m_ >= 1; m_ >>= 1)
                rmax = fmaxf(rmax, __shfl_xor_sync(0xffffffffu, rmax, m_));
            float nm = fmaxf(mi[i], rmax);
            float sc = __expf(mi[i] - nm);
            mi[i] = nm;
            li[i] *= sc;
#pragma unroll
            for (int l = 0; l < 4; l++) o[i][l] *= sc;
            float rs = 0.0f;
#pragma unroll
            for (int j = 0; j < 4; j++) { s[i][j] = __expf(s[i][j] - nm); rs += s[i][j]; }
#pragma unroll
            for (int m_ = 8; m_ >= 1; m_ >>= 1)
                rs += __shfl_xor_sync(0xffffffffu, rs, m_);
            li[i] += rs;
#pragma unroll
            for (int j = 0; j < 4; j++) Ps[(ty * 4 + i) * DPAD + tx * 4 + j] = s[i][j];
        }
        __syncthreads();

        // O += P @ V
#pragma unroll 8
        for (int j = 0; j < 64; j++) {
            float4 v4 = *(const float4*)&Vs[j * DPAD + tx * 4];
#pragma unroll
            for (int i = 0; i < 4; i++) {
                float pv = Ps[(ty * 4 + i) * DPAD + j];
                o[i][0] = fmaf(pv, v4.x, o[i][0]);
                o[i][1] = fmaf(pv, v4.y, o[i][1]);
                o[i][2] = fmaf(pv, v4.z, o[i][2]);
                o[i][3] = fmaf(pv, v4.w, o[i][3]);
            }
        }
    }
    __syncthreads();

    // t = attn + corr_map; softmax over 64 dims -> F
    float f[4][4];
#pragma unroll
    for (int i = 0; i < 4; i++) {
        int n = n0 + ty * 4 + i;
        float inv = 1.0f / li[i];
        float tv[4];
#pragma unroll
        for (int l = 0; l < 4; l++) {
            int d = tx * 4 + l;
            tv[l] = ab[n * NUM + d] + o[i][l] * inv;
        }
        float rmax = fmaxf(fmaxf(tv[0], tv[1]), fmaxf(tv[2], tv[3]));
#pragma unroll
        for (int m_ = 8; m_ >= 1; m_ >>= 1)
            rmax = fmaxf(rmax, __shfl_xor_sync(0xffffffffu, rmax, m_));
        float rs = 0.0f;
#pragma unroll
        for (int l = 0; l < 4; l++) { f[i][l] = __expf(tv[l] - rmax); rs += f[i][l]; }
#pragma unroll
        for (int m_ = 8; m_ >= 1; m_ >>= 1)
            rs += __shfl_xor_sync(0xffffffffu, rs, m_);
        float is = 1.0f / rs;
#pragma unroll
        for (int l = 0; l < 4; l++) f[i][l] *= is;
    }

#pragma unroll
    for (int i = 0; i < 4; i++)
#pragma unroll
        for (int l = 0; l < 4; l++)
            Ps[(ty * 4 + i) * DPAD + tx * 4 + l] = f[i][l];
    __syncthreads();

    // out = F @ vp (256 dims, 4 chunks of 64)
    for (int ch = 0; ch < 4; ch++) {
#pragma unroll
        for (int u = 0; u < 16; u++) {
            int e = t + u * 256;
            int m = e >> 6, ocl = e & 63;
            Vs[m * DPAD + ocl] = g_vp[m * HALF + ch * 64 + ocl];
        }
        __syncthreads();
        float a[4][4];
#pragma unroll
        for (int i = 0; i < 4; i++)
#pragma unroll
            for (int l = 0; l < 4; l++) a[i][l] = 0.0f;
#pragma unroll 8
        for (int m = 0; m < 64; m++) {
            float4 v4 = *(const float4*)&Vs[m * DPAD + tx * 4];
#pragma unroll
            for (int i = 0; i < 4; i++) {
                float pv = Ps[(ty * 4 + i) * DPAD + m];
                a[i][0] = fmaf(pv, v4.x, a[i][0]);
                a[i][1] = fmaf(pv, v4.y, a[i][1]);
                a[i][2] = fmaf(pv, v4.z, a[i][2]);
                a[i][3] = fmaf(pv, v4.w, a[i][3]);
            }
        }
#pragma unroll
        for (int i = 0; i < 4; i++) {
            int pn = p * NPP + n0 + ty * 4 + i;
            float4 r = make_float4(a[i][0], a[i][1], a[i][2], a[i][3]);
            *(float4*)&g_mid[pn * HALF + ch * 64 + tx * 4] = r;
        }
        __syncthreads();
    }
}

// ---------------------------------------------------------------------------
// o-proj + BN + ReLU + residual: out[oc][hw] = relu(bn(oW @ mid)) + x
// Pixel dim iterated in (p,n) order so mid reads and out writes coalesce.
// grid (8 oc-tiles fast, 1024 pn-tiles) for L2 reuse of mid tiles.
// ---------------------------------------------------------------------------
__global__ void __launch_bounds__(256) oproj_kernel(
    const float* __restrict__ x, const float* __restrict__ ow,
    float* __restrict__ out)
{
    __shared__ float As[16][65];   // oW  [kk][oc_l]
    __shared__ float Bs[16][65];   // mid [kk][pn_l]

    const int t  = threadIdx.x;
    const int tx = t & 15, ty = t >> 4;
    const int oc0 = blockIdx.x * 64;
    const int pn0 = blockIdx.y * 64;

    float acc[4][4];
#pragma unroll
    for (int i = 0; i < 4; i++)
#pragma unroll
        for (int j = 0; j < 4; j++) acc[i][j] = 0.0f;

    for (int k0 = 0; k0 < HALF; k0 += 16) {
#pragma unroll
        for (int u = 0; u < 4; u++) {
            int e = t + u * 256;
            As[e & 15][e >> 4] = ow[(oc0 + (e >> 4)) * HALF + k0 + (e & 15)];
            Bs[e & 15][e >> 4] = g_mid[(pn0 + (e >> 4)) * HALF + k0 + (e & 15)];
        }
        __syncthreads();
#pragma unroll
        for (int kk = 0; kk < 16; kk++) {
            float av[4], bv[4];
#pragma unroll
            for (int i = 0; i < 4; i++) av[i] = As[kk][i * 16 + ty];
#pragma unroll
            for (int j = 0; j < 4; j++) bv[j] = Bs[kk][j * 16 + tx];
#pragma unroll
            for (int i = 0; i < 4; i++)
#pragma unroll
                for (int j = 0; j < 4; j++) acc[i][j] = fmaf(av[i], bv[j], acc[i][j]);
        }
        __syncthreads();
    }

#pragma unroll
    for (int i = 0; i < 4; i++) {
        int oc = oc0 + i * 16 + ty;
        float s = g_pscale[768 + oc];
        float b = g_pbias[768 + oc];
#pragma unroll
        for (int j = 0; j < 4; j++) {
            int pn = pn0 + j * 16 + tx;
            int p = pn >> 10, n = pn & 1023;
            int h = ((p >> 3) << 5) + (n >> 5);
            int w = ((p & 7) << 5) + (n & 31);
            int idx = oc * HW + h * W_IMG + w;
            out[idx] = fmaxf(fmaf(acc[i][j], s, b), 0.0f) + x[idx];
        }
    }
}

// ---------------------------------------------------------------------------
extern "C" void kernel_launch(void* const* d_in, const int* in_sizes, int n_in,
                              void* d_out, int out_size)
{
    (void)in_sizes; (void)n_in; (void)out_size;
    const float* x  = (const float*)d_in[0];
    const float* qw = (const float*)d_in[1];
    const float* kw = (const float*)d_in[6];
    const float* vw = (const float*)d_in[11];
    const float* ow = (const float*)d_in[16];

    cudaFuncSetAttribute(corr_kernel,
                         cudaFuncAttributeMaxDynamicSharedMemorySize,
                         4 * 64 * DPAD * (int)sizeof(float));

    prep_kernel<<<134, 256>>>(
        (const float*)d_in[2],  (const float*)d_in[3],  (const float*)d_in[4],  (const float*)d_in[5],
        (const float*)d_in[7],  (const float*)d_in[8],  (const float*)d_in[9],  (const float*)d_in[10],
        (const float*)d_in[12], (const float*)d_in[13], (const float*)d_in[14], (const float*)d_in[15],
        (const float*)d_in[17], (const float*)d_in[18], (const float*)d_in[19], (const float*)d_in[20]);

    qkv_kernel<<<dim3(12, 1024), 256>>>(x, qw, kw, vw);
    attnqk_kernel<<<dim3(16, 64), 256>>>();
    corr_kernel<<<dim3(16, 64), 256, 4 * 64 * DPAD * sizeof(float)>>>();
    oproj_kernel<<<dim3(8, 1024), 256>>>(x, ow, (float*)d_out);
}

// round 2
// speedup vs baseline: 1.8488x; 1.8488x over previous
#include <cuda_runtime.h>
#include <math.h>
#include <float.h>

#define HW    65536
#define CIN   512
#define HALF  256
#define NUM   64
#define NPP   1024
#define W_IMG 256
#define DPAD  68

// scratch (device globals: allocation-free rule)
__device__ float g_q[NUM * NPP * HALF];       // (pn, ch) q, scaled
__device__ float g_kp[HALF * NUM];            // (ch, patch) pooled k
__device__ float g_vp[NUM * HALF];            // (patch, ch) pooled v
__device__ float g_attn[NUM * NPP * NUM];     // (pn, m)
__device__ float g_mid[NUM * NPP * HALF];     // (pn, ch) attention output
__device__ float g_pscale[1280];              // fused BN scale (q,k,v,o)
__device__ float g_pbias[1280];               // fused BN bias

// ---------------------------------------------------------------------------
__device__ __forceinline__ float t32(float x) {
    asm("cvt.rna.tf32.f32 %0, %0;" : "+f"(x));
    return x;
}
__device__ __forceinline__ void mma8(float* d,
    unsigned a0, unsigned a1, unsigned a2, unsigned a3,
    unsigned b0, unsigned b1)
{
    asm volatile(
        "mma.sync.aligned.m16n8k8.row.col.f32.tf32.tf32.f32 "
        "{%0,%1,%2,%3},{%4,%5,%6,%7},{%8,%9},{%0,%1,%2,%3};"
        : "+f"(d[0]), "+f"(d[1]), "+f"(d[2]), "+f"(d[3])
        : "r"(a0), "r"(a1), "r"(a2), "r"(a3), "r"(b0), "r"(b1));
}

// ---------------------------------------------------------------------------
// prep: fused BN params + zero pooled accumulators (must re-zero every launch)
// ---------------------------------------------------------------------------
__global__ void prep_kernel(
    const float* qg, const float* qb, const float* qm, const float* qv,
    const float* kg, const float* kb, const float* km, const float* kv,
    const float* vg, const float* vb, const float* vm, const float* vv,
    const float* og, const float* ob, const float* om, const float* ov)
{
    int i = blockIdx.x * blockDim.x + threadIdx.x;
    if (i < 1280) {
        const float *G, *B, *M, *V; float f; int r;
        if (i < 256)      { G = qg; B = qb; M = qm; V = qv; f = 0.044194173824159216f; r = i; }
        else if (i < 512) { G = kg; B = kb; M = km; V = kv; f = 1.0f / 1024.0f;        r = i - 256; }
        else if (i < 768) { G = vg; B = vb; M = vm; V = vv; f = 1.0f / 1024.0f;        r = i - 512; }
        else              { G = og; B = ob; M = om; V = ov; f = 1.0f;                  r = i - 768; }
        float s = G[r] * rsqrtf(V[r] + 1e-5f);
        g_pscale[i] = s * f;
        g_pbias[i]  = (B[r] - M[r] * s) * f;
    }
    int z = i - 1280;
    if (z >= 0 && z < HALF * NUM) g_kp[z] = 0.0f;
    z -= HALF * NUM;
    if (z >= 0 && z < NUM * HALF) g_vp[z] = 0.0f;
}

// ---------------------------------------------------------------------------
// QKV via tf32 mma: Y[pix][oc] = sum_c x[c][pix]*W[oc][c]; BN+ReLU epilogue.
// Block tile 128(pix) x 64(oc), K-tile 32. 8 warps: 4(m) x 2(n), warp 32x32.
// oc0<256: q (write patch layout). Else: k/v patch-pool (per-warp = 1 patch).
// ---------------------------------------------------------------------------
__global__ void __launch_bounds__(256) qkv_kernel(
    const float* __restrict__ x, const float* __restrict__ qw,
    const float* __restrict__ kw, const float* __restrict__ vw)
{
    __shared__ float As[32][132];
    __shared__ float Bs[32][68];

    const int t = threadIdx.x, lane = t & 31, warp = t >> 5;
    const int wm = (warp & 3) * 32, wn = (warp >> 2) * 32;
    const int g = lane >> 2, t4 = lane & 3;
    const int oc0  = blockIdx.x * 64;
    const int pix0 = blockIdx.y * 128;

    const float* Wp; int ocr;
    if (oc0 < 256)      { Wp = qw; ocr = oc0; }
    else if (oc0 < 512) { Wp = kw; ocr = oc0 - 256; }
    else                { Wp = vw; ocr = oc0 - 512; }

    float acc[2][4][4];
#pragma unroll
    for (int mi = 0; mi < 2; mi++)
#pragma unroll
        for (int nj = 0; nj < 4; nj++)
#pragma unroll
            for (int e = 0; e < 4; e++) acc[mi][nj][e] = 0.0f;

    const int am = (lane) * 4 ;      // m offset within 128 (by lane)
    const int ak = warp;             // base k row (0..7)
    const int boc = t & 63, bk = (t >> 6) * 8;

    for (int k0 = 0; k0 < CIN; k0 += 32) {
#pragma unroll
        for (int u = 0; u < 4; u++) {
            int kr = ak + u * 8;
            float4 v = *(const float4*)(x + (size_t)(k0 + kr) * HW + pix0 + am);
            As[kr][am]     = t32(v.x);
            As[kr][am + 1] = t32(v.y);
            As[kr][am + 2] = t32(v.z);
            As[kr][am + 3] = t32(v.w);
        }
#pragma unroll
        for (int u = 0; u < 2; u++) {
            float4 v = *(const float4*)(Wp + (size_t)(ocr + boc) * CIN + k0 + bk + u * 4);
            Bs[bk + u * 4][boc]     = t32(v.x);
            Bs[bk + u * 4 + 1][boc] = t32(v.y);
            Bs[bk + u * 4 + 2][boc] = t32(v.z);
            Bs[bk + u * 4 + 3][boc] = t32(v.w);
        }
        __syncthreads();
#pragma unroll
        for (int kk = 0; kk < 32; kk += 8) {
            unsigned a[2][4], b[4][2];
#pragma unroll
            for (int mi = 0; mi < 2; mi++) {
                int mb = wm + mi * 16 + g;
                a[mi][0] = __float_as_uint(As[kk + t4][mb]);
                a[mi][1] = __float_as_uint(As[kk + t4][mb + 8]);
                a[mi][2] = __float_as_uint(As[kk + t4 + 4][mb]);
                a[mi][3] = __float_as_uint(As[kk + t4 + 4][mb + 8]);
            }
#pragma unroll
            for (int nj = 0; nj < 4; nj++) {
                int nb = wn + nj * 8 + g;
                b[nj][0] = __float_as_uint(Bs[kk + t4][nb]);
                b[nj][1] = __float_as_uint(Bs[kk + t4 + 4][nb]);
            }
#pragma unroll
            for (int mi = 0; mi < 2; mi++)
#pragma unroll
                for (int nj = 0; nj < 4; nj++)
                    mma8(acc[mi][nj], a[mi][0], a[mi][1], a[mi][2], a[mi][3],
                         b[nj][0], b[nj][1]);
        }
        __syncthreads();
    }

    if (oc0 < 256) {
#pragma unroll
        for (int mi = 0; mi < 2; mi++)
#pragma unroll
            for (int h2 = 0; h2 < 2; h2++) {
                int pix = pix0 + wm + mi * 16 + g + h2 * 8;
                int h = pix >> 8, w = pix & 255;
                int pn = (((h >> 5) << 3) + (w >> 5)) * NPP + ((h & 31) << 5) + (w & 31);
#pragma unroll
                for (int nj = 0; nj < 4; nj++) {
                    int col = oc0 + wn + nj * 8 + t4 * 2;
                    float v0 = fmaxf(fmaf(acc[mi][nj][h2 * 2],     g_pscale[col],     g_pbias[col]),     0.0f);
                    float v1 = fmaxf(fmaf(acc[mi][nj][h2 * 2 + 1], g_pscale[col + 1], g_pbias[col + 1]), 0.0f);
                    *(float2*)&g_q[(size_t)pn * HALF + col] = make_float2(v0, v1);
                }
            }
    } else {
        // each warp's 32 rows lie entirely in ONE patch
        int h0 = pix0 >> 8;
        int p = ((h0 >> 5) << 3) + (((pix0 & 255) + wm) >> 5);
        float part[4][2];
#pragma unroll
        for (int nj = 0; nj < 4; nj++) {
            int col = oc0 + wn + nj * 8 + t4 * 2;
            float s0 = g_pscale[col], b0 = g_pbias[col];
            float s1 = g_pscale[col + 1], b1 = g_pbias[col + 1];
            float p0 = 0.0f, p1 = 0.0f;
#pragma unroll
            for (int mi = 0; mi < 2; mi++)
#pragma unroll
                for (int h2 = 0; h2 < 2; h2++) {
                    p0 += fmaxf(fmaf(acc[mi][nj][h2 * 2],     s0, b0), 0.0f);
                    p1 += fmaxf(fmaf(acc[mi][nj][h2 * 2 + 1], s1, b1), 0.0f);
                }
            part[nj][0] = p0; part[nj][1] = p1;
        }
#pragma unroll
        for (int m_ = 4; m_ <= 16; m_ <<= 1)
#pragma unroll
            for (int nj = 0; nj < 4; nj++) {
                part[nj][0] += __shfl_xor_sync(0xffffffffu, part[nj][0], m_);
                part[nj][1] += __shfl_xor_sync(0xffffffffu, part[nj][1], m_);
            }
        if (lane < 4) {
#pragma unroll
            for (int nj = 0; nj < 4; nj++) {
                int col = wn + nj * 8 + lane * 2;
                if (oc0 < 512) {
                    int o2 = oc0 - 256 + col;
                    atomicAdd(&g_kp[o2 * NUM + p],       part[nj][0]);
                    atomicAdd(&g_kp[(o2 + 1) * NUM + p], part[nj][1]);
                } else {
                    int o2 = oc0 - 512 + col;
                    atomicAdd(&g_vp[p * HALF + o2],     part[nj][0]);
                    atomicAdd(&g_vp[p * HALF + o2 + 1], part[nj][1]);
                }
            }
        }
    }
}

// ---------------------------------------------------------------------------
// attn[pn][m] = q[pn][:] . kp[:][m], tf32 mma. Block 128(pn) x 64(m), K=256.
// ---------------------------------------------------------------------------
__global__ void __launch_bounds__(256) attnqk_kernel()
{
    __shared__ float As[32][132];
    __shared__ float Bs[32][68];

    const int t = threadIdx.x, lane = t & 31, warp = t >> 5;
    const int wm = (warp & 3) * 32, wn = (warp >> 2) * 32;
    const int g = lane >> 2, t4 = lane & 3;
    const int pn0 = blockIdx.x * 128;

    float acc[2][4][4];
#pragma unroll
    for (int mi = 0; mi < 2; mi++)
#pragma unroll
        for (int nj = 0; nj < 4; nj++)
#pragma unroll
            for (int e = 0; e < 4; e++) acc[mi][nj][e] = 0.0f;

    const int am2 = t & 127, ac = (t >> 7) * 16;
    const int bn4 = (t & 15) * 4, bk2 = t >> 4;

    for (int k0 = 0; k0 < HALF; k0 += 32) {
#pragma unroll
        for (int u = 0; u < 4; u++) {
            float4 v = *(const float4*)(g_q + (size_t)(pn0 + am2) * HALF + k0 + ac + u * 4);
            As[ac + u * 4][am2]     = t32(v.x);
            As[ac + u * 4 + 1][am2] = t32(v.y);
            As[ac + u * 4 + 2][am2] = t32(v.z);
            As[ac + u * 4 + 3][am2] = t32(v.w);
        }
#pragma unroll
        for (int u = 0; u < 2; u++) {
            int kr = bk2 + u * 16;
            float4 v = *(const float4*)(g_kp + (size_t)(k0 + kr) * NUM + bn4);
            Bs[kr][bn4]     = t32(v.x);
            Bs[kr][bn4 + 1] = t32(v.y);
            Bs[kr][bn4 + 2] = t32(v.z);
            Bs[kr][bn4 + 3] = t32(v.w);
        }
        __syncthreads();
#pragma unroll
        for (int kk = 0; kk < 32; kk += 8) {
            unsigned a[2][4], b[4][2];
#pragma unroll
            for (int mi = 0; mi < 2; mi++) {
                int mb = wm + mi * 16 + g;
                a[mi][0] = __float_as_uint(As[kk + t4][mb]);
                a[mi][1] = __float_as_uint(As[kk + t4][mb + 8]);
                a[mi][2] = __float_as_uint(As[kk + t4 + 4][mb]);
                a[mi][3] = __float_as_uint(As[kk + t4 + 4][mb + 8]);
            }
#pragma unroll
            for (int nj = 0; nj < 4; nj++) {
                int nb = wn + nj * 8 + g;
                b[nj][0] = __float_as_uint(Bs[kk + t4][nb]);
                b[nj][1] = __float_as_uint(Bs[kk + t4 + 4][nb]);
            }
#pragma unroll
            for (int mi = 0; mi < 2; mi++)
#pragma unroll
                for (int nj = 0; nj < 4; nj++)
                    mma8(acc[mi][nj], a[mi][0], a[mi][1], a[mi][2], a[mi][3],
                         b[nj][0], b[nj][1]);
        }
        __syncthreads();
    }

#pragma unroll
    for (int mi = 0; mi < 2; mi++)
#pragma unroll
        for (int h2 = 0; h2 < 2; h2++) {
            int row = pn0 + wm + mi * 16 + g + h2 * 8;
#pragma unroll
            for (int nj = 0; nj < 4; nj++) {
                int col = wn + nj * 8 + t4 * 2;
                *(float2*)&g_attn[(size_t)row * NUM + col] =
                    make_float2(acc[mi][nj][h2 * 2], acc[mi][nj][h2 * 2 + 1]);
            }
        }
}

// ---------------------------------------------------------------------------
// Per patch: flash self-attention on attn (Q=K=V=attn, seq 1024, dim 64),
// then final softmax(attn + corr_map) over 64, then out = F @ vp -> g_mid.
// (scalar fp32 this round)
// ---------------------------------------------------------------------------
__global__ void __launch_bounds__(256) corr_kernel()
{
    extern __shared__ float sm[];
    float* Qs = sm;
    float* Ks = Qs + 64 * DPAD;
    float* Vs = Ks + 64 * DPAD;
    float* Ps = Vs + 64 * DPAD;

    const int t  = threadIdx.x;
    const int tx = t & 15, ty = t >> 4;
    const int n0 = blockIdx.x * 64;
    const int p  = blockIdx.y;
    const float* ab = g_attn + (size_t)p * NPP * NUM;

#pragma unroll
    for (int u = 0; u < 16; u++) {
        int e = t + u * 256;
        int nl = e >> 6, d = e & 63;
        Qs[d * DPAD + nl] = ab[(n0 + nl) * NUM + d];
    }

    float mi[4], li[4], o[4][4];
#pragma unroll
    for (int i = 0; i < 4; i++) {
        mi[i] = -FLT_MAX; li[i] = 0.0f;
#pragma unroll
        for (int l = 0; l < 4; l++) o[i][l] = 0.0f;
    }

    for (int jt = 0; jt < 16; jt++) {
        __syncthreads();
#pragma unroll
        for (int u = 0; u < 16; u++) {
            int e = t + u * 256;
            int jl = e >> 6, d = e & 63;
            float v = ab[(jt * 64 + jl) * NUM + d];
            Ks[d * DPAD + jl] = v;
            Vs[jl * DPAD + d] = v;
        }
        __syncthreads();

        float s[4][4];
#pragma unroll
        for (int i = 0; i < 4; i++)
#pragma unroll
            for (int j = 0; j < 4; j++) s[i][j] = 0.0f;
#pragma unroll 16
        for (int d = 0; d < 64; d++) {
            float4 q4 = *(const float4*)&Qs[d * DPAD + ty * 4];
            float4 k4 = *(const float4*)&Ks[d * DPAD + tx * 4];
            float qa[4] = {q4.x, q4.y, q4.z, q4.w};
            float kb[4] = {k4.x, k4.y, k4.z, k4.w};
#pragma unroll
            for (int i = 0; i < 4; i++)
#pragma unroll
                for (int j = 0; j < 4; j++) s[i][j] = fmaf(qa[i], kb[j], s[i][j]);
        }

#pragma unroll
        for (int i = 0; i < 4; i++) {
            float rmax = fmaxf(fmaxf(s[i][0], s[i][1]), fmaxf(s[i][2], s[i][3]));
#pragma unroll
            for (int m_ = 8; m_ >= 1; m_ >>= 1)
                rmax = fmaxf(rmax, __shfl_xor_sync(0xffffffffu, rmax, m_));
            float nm = fmaxf(mi[i], rmax);
            float sc = __expf(mi[i] - nm);
            mi[i] = nm;
            li[i] *= sc;
#pragma unroll
            for (int l = 0; l < 4; l++) o[i][l] *= sc;
            float rs = 0.0f;
#pragma unroll
            for (int j = 0; j < 4; j++) { s[i][j] = __expf(s[i][j] - nm); rs += s[i][j]; }
#pragma unroll
            for (int m_ = 8; m_ >= 1; m_ >>= 1)
                rs += __shfl_xor_sync(0xffffffffu, rs, m_);
            li[i] += rs;
#pragma unroll
            for (int j = 0; j < 4; j++) Ps[(ty * 4 + i) * DPAD + tx * 4 + j] = s[i][j];
        }
        __syncthreads();

#pragma unroll 8
        for (int j = 0; j < 64; j++) {
            float4 v4 = *(const float4*)&Vs[j * DPAD + tx * 4];
#pragma unroll
            for (int i = 0; i < 4; i++) {
                float pv = Ps[(ty * 4 + i) * DPAD + j];
                o[i][0] = fmaf(pv, v4.x, o[i][0]);
                o[i][1] = fmaf(pv, v4.y, o[i][1]);
                o[i][2] = fmaf(pv, v4.z, o[i][2]);
                o[i][3] = fmaf(pv, v4.w, o[i][3]);
            }
        }
    }
    __syncthreads();

    float f[4][4];
#pragma unroll
    for (int i = 0; i < 4; i++) {
        int n = n0 + ty * 4 + i;
        float inv = 1.0f / li[i];
        float tv[4];
#pragma unroll
        for (int l = 0; l < 4; l++) {
            int d = tx * 4 + l;
            tv[l] = ab[n * NUM + d] + o[i][l] * inv;
        }
        float rmax = fmaxf(fmaxf(tv[0], tv[1]), fmaxf(tv[2], tv[3]));
#pragma unroll
        for (int m_ = 8; m_ >= 1; m_ >>= 1)
            rmax = fmaxf(rmax, __shfl_xor_sync(0xffffffffu, rmax, m_));
        float rs = 0.0f;
#pragma unroll
        for (int l = 0; l < 4; l++) { f[i][l] = __expf(tv[l] - rmax); rs += f[i][l]; }
#pragma unroll
        for (int m_ = 8; m_ >= 1; m_ >>= 1)
            rs += __shfl_xor_sync(0xffffffffu, rs, m_);
        float is = 1.0f / rs;
#pragma unroll
        for (int l = 0; l < 4; l++) f[i][l] *= is;
    }

#pragma unroll
    for (int i = 0; i < 4; i++)
#pragma unroll
        for (int l = 0; l < 4; l++)
            Ps[(ty * 4 + i) * DPAD + tx * 4 + l] = f[i][l];
    __syncthreads();

    for (int ch = 0; ch < 4; ch++) {
#pragma unroll
        for (int u = 0; u < 16; u++) {
            int e = t + u * 256;
            int m = e >> 6, ocl = e & 63;
            Vs[m * DPAD + ocl] = g_vp[m * HALF + ch * 64 + ocl];
        }
        __syncthreads();
        float a[4][4];
#pragma unroll
        for (int i = 0; i < 4; i++)
#pragma unroll
            for (int l = 0; l < 4; l++) a[i][l] = 0.0f;
#pragma unroll 8
        for (int m = 0; m < 64; m++) {
            float4 v4 = *(const float4*)&Vs[m * DPAD + tx * 4];
#pragma unroll
            for (int i = 0; i < 4; i++) {
                float pv = Ps[(ty * 4 + i) * DPAD + m];
                a[i][0] = fmaf(pv, v4.x, a[i][0]);
                a[i][1] = fmaf(pv, v4.y, a[i][1]);
                a[i][2] = fmaf(pv, v4.z, a[i][2]);
                a[i][3] = fmaf(pv, v4.w, a[i][3]);
            }
        }
#pragma unroll
        for (int i = 0; i < 4; i++) {
            int pn = p * NPP + n0 + ty * 4 + i;
            float4 r = make_float4(a[i][0], a[i][1], a[i][2], a[i][3]);
            *(float4*)&g_mid[(size_t)pn * HALF + ch * 64 + tx * 4] = r;
        }
        __syncthreads();
    }
}

// ---------------------------------------------------------------------------
// o-proj + BN + ReLU + residual via tf32 mma. Block 128(pn) x 64(oc), K=256.
// ---------------------------------------------------------------------------
__global__ void __launch_bounds__(256) oproj_kernel(
    const float* __restrict__ x, const float* __restrict__ ow,
    float* __restrict__ out)
{
    __shared__ float As[32][132];  // mid [k][pn_l]
    __shared__ float Bs[32][68];   // ow  [k][oc_l]

    const int t = threadIdx.x, lane = t & 31, warp = t >> 5;
    const int wm = (warp & 3) * 32, wn = (warp >> 2) * 32;
    const int g = lane >> 2, t4 = lane & 3;
    const int oc0 = blockIdx.x * 64;
    const int pn0 = blockIdx.y * 128;

    float acc[2][4][4];
#pragma unroll
    for (int mi = 0; mi < 2; mi++)
#pragma unroll
        for (int nj = 0; nj < 4; nj++)
#pragma unroll
            for (int e = 0; e < 4; e++) acc[mi][nj][e] = 0.0f;

    const int am2 = t & 127, ac = (t >> 7) * 16;
    const int boc = t & 63, bk = (t >> 6) * 8;

    for (int k0 = 0; k0 < HALF; k0 += 32) {
#pragma unroll
        for (int u = 0; u < 4; u++) {
            float4 v = *(const float4*)(g_mid + (size_t)(pn0 + am2) * HALF + k0 + ac + u * 4);
            As[ac + u * 4][am2]     = t32(v.x);
            As[ac + u * 4 + 1][am2] = t32(v.y);
            As[ac + u * 4 + 2][am2] = t32(v.z);
            As[ac + u * 4 + 3][am2] = t32(v.w);
        }
#pragma unroll
        for (int u = 0; u < 2; u++) {
            float4 v = *(const float4*)(ow + (size_t)(oc0 + boc) * HALF + k0 + bk + u * 4);
            Bs[bk + u * 4][boc]     = t32(v.x);
            Bs[bk + u * 4 + 1][boc] = t32(v.y);
            Bs[bk + u * 4 + 2][boc] = t32(v.z);
            Bs[bk + u * 4 + 3][boc] = t32(v.w);
        }
        __syncthreads();
#pragma unroll
        for (int kk = 0; kk < 32; kk += 8) {
            unsigned a[2][4], b[4][2];
#pragma unroll
            for (int mi = 0; mi < 2; mi++) {
                int mb = wm + mi * 16 + g;
                a[mi][0] = __float_as_uint(As[kk + t4][mb]);
                a[mi][1] = __float_as_uint(As[kk + t4][mb + 8]);
                a[mi][2] = __float_as_uint(As[kk + t4 + 4][mb]);
                a[mi][3] = __float_as_uint(As[kk + t4 + 4][mb + 8]);
            }
#pragma unroll
            for (int nj = 0; nj < 4; nj++) {
                int nb = wn + nj * 8 + g;
                b[nj][0] = __float_as_uint(Bs[kk + t4][nb]);
                b[nj][1] = __float_as_uint(Bs[kk + t4 + 4][nb]);
            }
#pragma unroll
            for (int mi = 0; mi < 2; mi++)
#pragma unroll
                for (int nj = 0; nj < 4; nj++)
                    mma8(acc[mi][nj], a[mi][0], a[mi][1], a[mi][2], a[mi][3],
                         b[nj][0], b[nj][1]);
        }
        __syncthreads();
    }

#pragma unroll
    for (int mi = 0; mi < 2; mi++)
#pragma unroll
        for (int h2 = 0; h2 < 2; h2++) {
            int pn = pn0 + wm + mi * 16 + g + h2 * 8;
            int p = pn >> 10, n = pn & 1023;
            int h = ((p >> 3) << 5) + (n >> 5);
            int w = ((p & 7) << 5) + (n & 31);
            int base = h * W_IMG + w;
#pragma unroll
            for (int nj = 0; nj < 4; nj++) {
                int oc = oc0 + wn + nj * 8 + t4 * 2;
                float s0 = g_pscale[768 + oc],     b0 = g_pbias[768 + oc];
                float s1 = g_pscale[768 + oc + 1], b1 = g_pbias[768 + oc + 1];
                size_t i0 = (size_t)oc * HW + base;
                size_t i1 = i0 + HW;
                out[i0] = fmaxf(fmaf(acc[mi][nj][h2 * 2],     s0, b0), 0.0f) + x[i0];
                out[i1] = fmaxf(fmaf(acc[mi][nj][h2 * 2 + 1], s1, b1), 0.0f) + x[i1];
            }
        }
}

// ---------------------------------------------------------------------------
extern "C" void kernel_launch(void* const* d_in, const int* in_sizes, int n_in,
                              void* d_out, int out_size)
{
    (void)in_sizes; (void)n_in; (void)out_size;
    const float* x  = (const float*)d_in[0];
    const float* qw = (const float*)d_in[1];
    const float* kw = (const float*)d_in[6];
    const float* vw = (const float*)d_in[11];
    const float* ow = (const float*)d_in[16];

    cudaFuncSetAttribute(corr_kernel,
                         cudaFuncAttributeMaxDynamicSharedMemorySize,
                         4 * 64 * DPAD * (int)sizeof(float));

    prep_kernel<<<134, 256>>>(
        (const float*)d_in[2],  (const float*)d_in[3],  (const float*)d_in[4],  (const float*)d_in[5],
        (const float*)d_in[7],  (const float*)d_in[8],  (const float*)d_in[9],  (const float*)d_in[10],
        (const float*)d_in[12], (const float*)d_in[13], (const float*)d_in[14], (const float*)d_in[15],
        (const float*)d_in[17], (const float*)d_in[18], (const float*)d_in[19], (const float*)d_in[20]);

    qkv_kernel<<<dim3(12, 512), 256>>>(x, qw, kw, vw);
    attnqk_kernel<<<512, 256>>>();
    corr_kernel<<<dim3(16, 64), 256, 4 * 64 * DPAD * sizeof(float)>>>();
    oproj_kernel<<<dim3(8, 512), 256>>>(x, ow, (float*)d_out);
}

// round 3
// speedup vs baseline: 2.0637x; 1.1162x over previous
#include <cuda_runtime.h>
#include <math.h>
#include <float.h>

#define HW    65536
#define CIN   512
#define HALF  256
#define NUM   64
#define NPP   1024
#define W_IMG 256
#define CDP   68
#define QSTR  132

// scratch (device globals: allocation-free rule)
__device__ float g_q[NUM * NPP * HALF];       // (pn, ch) q, scaled
__device__ float g_kp[HALF * NUM];            // (ch, patch) pooled k
__device__ float g_vp[NUM * HALF];            // (patch, ch) pooled v
__device__ float g_attn[NUM * NPP * NUM];     // (pn, m)
__device__ float g_mid[NUM * NPP * HALF];     // (pn, ch) attention output
__device__ float g_pscale[1280];              // fused BN scale (q,k,v,o)
__device__ float g_pbias[1280];               // fused BN bias

// ---------------------------------------------------------------------------
__device__ __forceinline__ float t32(float x) {
    asm("cvt.rna.tf32.f32 %0, %0;" : "+f"(x));
    return x;
}
__device__ __forceinline__ void mma8(float* d,
    unsigned a0, unsigned a1, unsigned a2, unsigned a3,
    unsigned b0, unsigned b1)
{
    asm volatile(
        "mma.sync.aligned.m16n8k8.row.col.f32.tf32.tf32.f32 "
        "{%0,%1,%2,%3},{%4,%5,%6,%7},{%8,%9},{%0,%1,%2,%3};"
        : "+f"(d[0]), "+f"(d[1]), "+f"(d[2]), "+f"(d[3])
        : "r"(a0), "r"(a1), "r"(a2), "r"(a3), "r"(b0), "r"(b1));
}

// ---------------------------------------------------------------------------
// prep: fused BN params + zero pooled accumulators (must re-zero every launch)
// ---------------------------------------------------------------------------
__global__ void prep_kernel(
    const float* qg, const float* qb, const float* qm, const float* qv,
    const float* kg, const float* kb, const float* km, const float* kv,
    const float* vg, const float* vb, const float* vm, const float* vv,
    const float* og, const float* ob, const float* om, const float* ov)
{
    int i = blockIdx.x * blockDim.x + threadIdx.x;
    if (i < 1280) {
        const float *G, *B, *M, *V; float f; int r;
        if (i < 256)      { G = qg; B = qb; M = qm; V = qv; f = 0.044194173824159216f; r = i; }
        else if (i < 512) { G = kg; B = kb; M = km; V = kv; f = 1.0f / 1024.0f;        r = i - 256; }
        else if (i < 768) { G = vg; B = vb; M = vm; V = vv; f = 1.0f / 1024.0f;        r = i - 512; }
        else              { G = og; B = ob; M = om; V = ov; f = 1.0f;                  r = i - 768; }
        float s = G[r] * rsqrtf(V[r] + 1e-5f);
        g_pscale[i] = s * f;
        g_pbias[i]  = (B[r] - M[r] * s) * f;
    }
    int z = i - 1280;
    if (z >= 0 && z < HALF * NUM) g_kp[z] = 0.0f;
    z -= HALF * NUM;
    if (z >= 0 && z < NUM * HALF) g_vp[z] = 0.0f;
}

// ---------------------------------------------------------------------------
// QKV via tf32 mma (unchanged from R2)
// ---------------------------------------------------------------------------
__global__ void __launch_bounds__(256) qkv_kernel(
    const float* __restrict__ x, const float* __restrict__ qw,
    const float* __restrict__ kw, const float* __restrict__ vw)
{
    __shared__ float As[32][132];
    __shared__ float Bs[32][68];

    const int t = threadIdx.x, lane = t & 31, warp = t >> 5;
    const int wm = (warp & 3) * 32, wn = (warp >> 2) * 32;
    const int g = lane >> 2, t4 = lane & 3;
    const int oc0  = blockIdx.x * 64;
    const int pix0 = blockIdx.y * 128;

    const float* Wp; int ocr;
    if (oc0 < 256)      { Wp = qw; ocr = oc0; }
    else if (oc0 < 512) { Wp = kw; ocr = oc0 - 256; }
    else                { Wp = vw; ocr = oc0 - 512; }

    float acc[2][4][4];
#pragma unroll
    for (int mi = 0; mi < 2; mi++)
#pragma unroll
        for (int nj = 0; nj < 4; nj++)
#pragma unroll
            for (int e = 0; e < 4; e++) acc[mi][nj][e] = 0.0f;

    const int am = (lane) * 4;
    const int ak = warp;
    const int boc = t & 63, bk = (t >> 6) * 8;

    for (int k0 = 0; k0 < CIN; k0 += 32) {
#pragma unroll
        for (int u = 0; u < 4; u++) {
            int kr = ak + u * 8;
            float4 v = *(const float4*)(x + (size_t)(k0 + kr) * HW + pix0 + am);
            As[kr][am]     = t32(v.x);
            As[kr][am + 1] = t32(v.y);
            As[kr][am + 2] = t32(v.z);
            As[kr][am + 3] = t32(v.w);
        }
#pragma unroll
        for (int u = 0; u < 2; u++) {
            float4 v = *(const float4*)(Wp + (size_t)(ocr + boc) * CIN + k0 + bk + u * 4);
            Bs[bk + u * 4][boc]     = t32(v.x);
            Bs[bk + u * 4 + 1][boc] = t32(v.y);
            Bs[bk + u * 4 + 2][boc] = t32(v.z);
            Bs[bk + u * 4 + 3][boc] = t32(v.w);
        }
        __syncthreads();
#pragma unroll
        for (int kk = 0; kk < 32; kk += 8) {
            unsigned a[2][4], b[4][2];
#pragma unroll
            for (int mi = 0; mi < 2; mi++) {
                int mb = wm + mi * 16 + g;
                a[mi][0] = __float_as_uint(As[kk + t4][mb]);
                a[mi][1] = __float_as_uint(As[kk + t4][mb + 8]);
                a[mi][2] = __float_as_uint(As[kk + t4 + 4][mb]);
                a[mi][3] = __float_as_uint(As[kk + t4 + 4][mb + 8]);
            }
#pragma unroll
            for (int nj = 0; nj < 4; nj++) {
                int nb = wn + nj * 8 + g;
                b[nj][0] = __float_as_uint(Bs[kk + t4][nb]);
                b[nj][1] = __float_as_uint(Bs[kk + t4 + 4][nb]);
            }
#pragma unroll
            for (int mi = 0; mi < 2; mi++)
#pragma unroll
                for (int nj = 0; nj < 4; nj++)
                    mma8(acc[mi][nj], a[mi][0], a[mi][1], a[mi][2], a[mi][3],
                         b[nj][0], b[nj][1]);
        }
        __syncthreads();
    }

    if (oc0 < 256) {
#pragma unroll
        for (int mi = 0; mi < 2; mi++)
#pragma unroll
            for (int h2 = 0; h2 < 2; h2++) {
                int pix = pix0 + wm + mi * 16 + g + h2 * 8;
                int h = pix >> 8, w = pix & 255;
                int pn = (((h >> 5) << 3) + (w >> 5)) * NPP + ((h & 31) << 5) + (w & 31);
#pragma unroll
                for (int nj = 0; nj < 4; nj++) {
                    int col = oc0 + wn + nj * 8 + t4 * 2;
                    float v0 = fmaxf(fmaf(acc[mi][nj][h2 * 2],     g_pscale[col],     g_pbias[col]),     0.0f);
                    float v1 = fmaxf(fmaf(acc[mi][nj][h2 * 2 + 1], g_pscale[col + 1], g_pbias[col + 1]), 0.0f);
                    *(float2*)&g_q[(size_t)pn * HALF + col] = make_float2(v0, v1);
                }
            }
    } else {
        int h0 = pix0 >> 8;
        int p = ((h0 >> 5) << 3) + (((pix0 & 255) + wm) >> 5);
        float part[4][2];
#pragma unroll
        for (int nj = 0; nj < 4; nj++) {
            int col = oc0 + wn + nj * 8 + t4 * 2;
            float s0 = g_pscale[col], b0 = g_pbias[col];
            float s1 = g_pscale[col + 1], b1 = g_pbias[col + 1];
            float p0 = 0.0f, p1 = 0.0f;
#pragma unroll
            for (int mi = 0; mi < 2; mi++)
#pragma unroll
                for (int h2 = 0; h2 < 2; h2++) {
                    p0 += fmaxf(fmaf(acc[mi][nj][h2 * 2],     s0, b0), 0.0f);
                    p1 += fmaxf(fmaf(acc[mi][nj][h2 * 2 + 1], s1, b1), 0.0f);
                }
            part[nj][0] = p0; part[nj][1] = p1;
        }
#pragma unroll
        for (int m_ = 4; m_ <= 16; m_ <<= 1)
#pragma unroll
            for (int nj = 0; nj < 4; nj++) {
                part[nj][0] += __shfl_xor_sync(0xffffffffu, part[nj][0], m_);
                part[nj][1] += __shfl_xor_sync(0xffffffffu, part[nj][1], m_);
            }
        if (lane < 4) {
#pragma unroll
            for (int nj = 0; nj < 4; nj++) {
                int col = wn + nj * 8 + lane * 2;
                if (oc0 < 512) {
                    int o2 = oc0 - 256 + col;
                    atomicAdd(&g_kp[o2 * NUM + p],       part[nj][0]);
                    atomicAdd(&g_kp[(o2 + 1) * NUM + p], part[nj][1]);
                } else {
                    int o2 = oc0 - 512 + col;
                    atomicAdd(&g_vp[p * HALF + o2],     part[nj][0]);
                    atomicAdd(&g_vp[p * HALF + o2 + 1], part[nj][1]);
                }
            }
        }
    }
}

// ---------------------------------------------------------------------------
// attn[pn][m] = q[pn][:] . kp[:][m], tf32 mma (unchanged from R2)
// ---------------------------------------------------------------------------
__global__ void __launch_bounds__(256) attnqk_kernel()
{
    __shared__ float As[32][132];
    __shared__ float Bs[32][68];

    const int t = threadIdx.x, lane = t & 31, warp = t >> 5;
    const int wm = (warp & 3) * 32, wn = (warp >> 2) * 32;
    const int g = lane >> 2, t4 = lane & 3;
    const int pn0 = blockIdx.x * 128;

    float acc[2][4][4];
#pragma unroll
    for (int mi = 0; mi < 2; mi++)
#pragma unroll
        for (int nj = 0; nj < 4; nj++)
#pragma unroll
            for (int e = 0; e < 4; e++) acc[mi][nj][e] = 0.0f;

    const int am2 = t & 127, ac = (t >> 7) * 16;
    const int bn4 = (t & 15) * 4, bk2 = t >> 4;

    for (int k0 = 0; k0 < HALF; k0 += 32) {
#pragma unroll
        for (int u = 0; u < 4; u++) {
            float4 v = *(const float4*)(g_q + (size_t)(pn0 + am2) * HALF + k0 + ac + u * 4);
            As[ac + u * 4][am2]     = t32(v.x);
            As[ac + u * 4 + 1][am2] = t32(v.y);
            As[ac + u * 4 + 2][am2] = t32(v.z);
            As[ac + u * 4 + 3][am2] = t32(v.w);
        }
#pragma unroll
        for (int u = 0; u < 2; u++) {
            int kr = bk2 + u * 16;
            float4 v = *(const float4*)(g_kp + (size_t)(k0 + kr) * NUM + bn4);
            Bs[kr][bn4]     = t32(v.x);
            Bs[kr][bn4 + 1] = t32(v.y);
            Bs[kr][bn4 + 2] = t32(v.z);
            Bs[kr][bn4 + 3] = t32(v.w);
        }
        __syncthreads();
#pragma unroll
        for (int kk = 0; kk < 32; kk += 8) {
            unsigned a[2][4], b[4][2];
#pragma unroll
            for (int mi = 0; mi < 2; mi++) {
                int mb = wm + mi * 16 + g;
                a[mi][0] = __float_as_uint(As[kk + t4][mb]);
                a[mi][1] = __float_as_uint(As[kk + t4][mb + 8]);
                a[mi][2] = __float_as_uint(As[kk + t4 + 4][mb]);
                a[mi][3] = __float_as_uint(As[kk + t4 + 4][mb + 8]);
            }
#pragma unroll
            for (int nj = 0; nj < 4; nj++) {
                int nb = wn + nj * 8 + g;
                b[nj][0] = __float_as_uint(Bs[kk + t4][nb]);
                b[nj][1] = __float_as_uint(Bs[kk + t4 + 4][nb]);
            }
#pragma unroll
            for (int mi = 0; mi < 2; mi++)
#pragma unroll
                for (int nj = 0; nj < 4; nj++)
                    mma8(acc[mi][nj], a[mi][0], a[mi][1], a[mi][2], a[mi][3],
                         b[nj][0], b[nj][1]);
        }
        __syncthreads();
    }

#pragma unroll
    for (int mi = 0; mi < 2; mi++)
#pragma unroll
        for (int h2 = 0; h2 < 2; h2++) {
            int row = pn0 + wm + mi * 16 + g + h2 * 8;
#pragma unroll
            for (int nj = 0; nj < 4; nj++) {
                int col = wn + nj * 8 + t4 * 2;
                *(float2*)&g_attn[(size_t)row * NUM + col] =
                    make_float2(acc[mi][nj][h2 * 2], acc[mi][nj][h2 * 2 + 1]);
            }
        }
}

// ---------------------------------------------------------------------------
// corr (tensor-core version): per block = 128 rows of one patch, 8 warps x 16
// rows. Flash self-attn over 16 j-tiles: S via split-tf32 (fp32 accuracy),
// softmax warp-local, O += P@V in tf32. Then softmax(attn+corr/l) and F@vp.
// smem: Qs[64][132] raw, Ks[64][68] raw, Vs[64][68] tf32, Ps[128][68] tf32.
// ---------------------------------------------------------------------------
__global__ void __launch_bounds__(256, 2) corr_kernel()
{
    extern __shared__ float sm[];
    float* Qs = sm;                       // [64 d][QSTR] raw attn, Qs[d][nl]
    float* Ks = Qs + 64 * QSTR;           // [64 d][CDP]  raw,     Ks[d][jl]
    float* Vs = Ks + 64 * CDP;            // [64 j][CDP]  tf32,    Vs[j][d]
    float* Ps = Vs + 64 * CDP;            // [128 n][CDP] tf32 (warp-private 16-row slices)

    const int t = threadIdx.x, lane = t & 31, warp = t >> 5;
    const int g = lane >> 2, t4 = lane & 3;
    const int rm0 = warp * 16;
    const int n0 = blockIdx.x * 128;
    const int p  = blockIdx.y;
    const float* ab = g_attn + (size_t)p * NPP * NUM;

    // load Q tile (raw fp32, transposed): thread t -> row nl=t>>1, d0=(t&1)*32
    {
        int nl = t >> 1, d0 = (t & 1) * 32;
#pragma unroll
        for (int u = 0; u < 8; u++) {
            int d = d0 + u * 4;
            float4 v = *(const float4*)(ab + (size_t)(n0 + nl) * NUM + d);
            Qs[(d    ) * QSTR + nl] = v.x;
            Qs[(d + 1) * QSTR + nl] = v.y;
            Qs[(d + 2) * QSTR + nl] = v.z;
            Qs[(d + 3) * QSTR + nl] = v.w;
        }
    }

    float mi[2] = {-FLT_MAX, -FLT_MAX}, li[2] = {0.0f, 0.0f};
    float o[8][4];
#pragma unroll
    for (int nj = 0; nj < 8; nj++)
#pragma unroll
        for (int e = 0; e < 4; e++) o[nj][e] = 0.0f;

    for (int jt = 0; jt < 16; jt++) {
        __syncthreads();
        // load K (raw, transposed) and V (tf32, natural): jl=t>>2, c0=(t&3)*16
        {
            int jl = t >> 2, c0 = (t & 3) * 16;
#pragma unroll
            for (int u = 0; u < 4; u++) {
                int d = c0 + u * 4;
                float4 v = *(const float4*)(ab + (size_t)(jt * 64 + jl) * NUM + d);
                Ks[(d    ) * CDP + jl] = v.x;
                Ks[(d + 1) * CDP + jl] = v.y;
                Ks[(d + 2) * CDP + jl] = v.z;
                Ks[(d + 3) * CDP + jl] = v.w;
                float4 tv = make_float4(t32(v.x), t32(v.y), t32(v.z), t32(v.w));
                *(float4*)&Vs[jl * CDP + d] = tv;
            }
        }
        __syncthreads();

        // S = Q Kt with 2-term tf32 split (3 mma passes)
        float s[8][4];
#pragma unroll
        for (int nj = 0; nj < 8; nj++)
#pragma unroll
            for (int e = 0; e < 4; e++) s[nj][e] = 0.0f;

#pragma unroll
        for (int ks = 0; ks < 8; ks++) {
            int kb = ks * 8;
            float qa0 = Qs[(kb + t4) * QSTR + rm0 + g];
            float qa1 = Qs[(kb + t4) * QSTR + rm0 + 8 + g];
            float qa2 = Qs[(kb + t4 + 4) * QSTR + rm0 + g];
            float qa3 = Qs[(kb + t4 + 4) * QSTR + rm0 + 8 + g];
            float ab0 = t32(qa0), ab1 = t32(qa1), ab2 = t32(qa2), ab3 = t32(qa3);
            float ar0 = t32(qa0 - ab0), ar1 = t32(qa1 - ab1);
            float ar2 = t32(qa2 - ab2), ar3 = t32(qa3 - ab3);
#pragma unroll
            for (int nj = 0; nj < 8; nj++) {
                float kr0 = Ks[(kb + t4) * CDP + nj * 8 + g];
                float kr1 = Ks[(kb + t4 + 4) * CDP + nj * 8 + g];
                float bb0 = t32(kr0), bb1 = t32(kr1);
                float br0 = t32(kr0 - bb0), br1 = t32(kr1 - bb1);
                mma8(s[nj], __float_as_uint(ab0), __float_as_uint(ab1),
                            __float_as_uint(ab2), __float_as_uint(ab3),
                            __float_as_uint(bb0), __float_as_uint(bb1));
                mma8(s[nj], __float_as_uint(ab0), __float_as_uint(ab1),
                            __float_as_uint(ab2), __float_as_uint(ab3),
                            __float_as_uint(br0), __float_as_uint(br1));
                mma8(s[nj], __float_as_uint(ar0), __float_as_uint(ar1),
                            __float_as_uint(ar2), __float_as_uint(ar3),
                            __float_as_uint(bb0), __float_as_uint(bb1));
            }
        }

        // online softmax, warp-local per row (rows: rm0+g, rm0+8+g)
#pragma unroll
        for (int h = 0; h < 2; h++) {
            float rmax = -FLT_MAX;
#pragma unroll
            for (int nj = 0; nj < 8; nj++)
                rmax = fmaxf(rmax, fmaxf(s[nj][2 * h], s[nj][2 * h + 1]));
            rmax = fmaxf(rmax, __shfl_xor_sync(0xffffffffu, rmax, 1));
            rmax = fmaxf(rmax, __shfl_xor_sync(0xffffffffu, rmax, 2));
            float nm = fmaxf(mi[h], rmax);
            float sc = __expf(mi[h] - nm);
            mi[h] = nm;
            float rs = 0.0f;
#pragma unroll
            for (int nj = 0; nj < 8; nj++) {
                float v0 = __expf(s[nj][2 * h]     - nm);
                float v1 = __expf(s[nj][2 * h + 1] - nm);
                s[nj][2 * h] = v0; s[nj][2 * h + 1] = v1;
                rs += v0 + v1;
            }
            rs += __shfl_xor_sync(0xffffffffu, rs, 1);
            rs += __shfl_xor_sync(0xffffffffu, rs, 2);
            li[h] = li[h] * sc + rs;
#pragma unroll
            for (int nj = 0; nj < 8; nj++) {
                o[nj][2 * h]     *= sc;
                o[nj][2 * h + 1] *= sc;
            }
        }

        // store P (tf32) to warp-private Ps slice
#pragma unroll
        for (int h = 0; h < 2; h++)
#pragma unroll
            for (int nj = 0; nj < 8; nj++)
                *(float2*)&Ps[(rm0 + g + h * 8) * CDP + nj * 8 + 2 * t4] =
                    make_float2(t32(s[nj][2 * h]), t32(s[nj][2 * h + 1]));
        __syncwarp();

        // O += P @ V (tf32)
#pragma unroll
        for (int ks = 0; ks < 8; ks++) {
            int kb = ks * 8;
            unsigned a0 = __float_as_uint(Ps[(rm0 + g) * CDP + kb + t4]);
            unsigned a1 = __float_as_uint(Ps[(rm0 + 8 + g) * CDP + kb + t4]);
            unsigned a2 = __float_as_uint(Ps[(rm0 + g) * CDP + kb + t4 + 4]);
            unsigned a3 = __float_as_uint(Ps[(rm0 + 8 + g) * CDP + kb + t4 + 4]);
#pragma unroll
            for (int nj = 0; nj < 8; nj++) {
                unsigned b0 = __float_as_uint(Vs[(kb + t4) * CDP + nj * 8 + g]);
                unsigned b1 = __float_as_uint(Vs[(kb + t4 + 4) * CDP + nj * 8 + g]);
                mma8(o[nj], a0, a1, a2, a3, b0, b1);
            }
        }
    }

    // final: F = softmax(attn + O/li) per row (warp-local), store tf32 to Ps
#pragma unroll
    for (int h = 0; h < 2; h++) {
        int nl = rm0 + g + h * 8;
        float inv = 1.0f / li[h];
        float tv[16];
#pragma unroll
        for (int nj = 0; nj < 8; nj++)
#pragma unroll
            for (int e2 = 0; e2 < 2; e2++) {
                int d = nj * 8 + 2 * t4 + e2;
                tv[nj * 2 + e2] = Qs[d * QSTR + nl] + o[nj][2 * h + e2] * inv;
            }
        float rmax = -FLT_MAX;
#pragma unroll
        for (int l = 0; l < 16; l++) rmax = fmaxf(rmax, tv[l]);
        rmax = fmaxf(rmax, __shfl_xor_sync(0xffffffffu, rmax, 1));
        rmax = fmaxf(rmax, __shfl_xor_sync(0xffffffffu, rmax, 2));
        float rs = 0.0f;
#pragma unroll
        for (int l = 0; l < 16; l++) { tv[l] = __expf(tv[l] - rmax); rs += tv[l]; }
        rs += __shfl_xor_sync(0xffffffffu, rs, 1);
        rs += __shfl_xor_sync(0xffffffffu, rs, 2);
        float is = 1.0f / rs;
#pragma unroll
        for (int nj = 0; nj < 8; nj++)
            *(float2*)&Ps[(rm0 + g + h * 8) * CDP + nj * 8 + 2 * t4] =
                make_float2(t32(tv[nj * 2] * is), t32(tv[nj * 2 + 1] * is));
    }

    // out = F @ vp (4 chunks of 64 channels), write g_mid
    for (int ch = 0; ch < 4; ch++) {
        __syncthreads();
        {
            int m = t >> 2, c0 = (t & 3) * 16;
#pragma unroll
            for (int u = 0; u < 4; u++) {
                float4 v = *(const float4*)(g_vp + (size_t)m * HALF + ch * 64 + c0 + u * 4);
                float4 tv2 = make_float4(t32(v.x), t32(v.y), t32(v.z), t32(v.w));
                *(float4*)&Vs[m * CDP + c0 + u * 4] = tv2;
            }
        }
        __syncthreads();

        float acc[8][4];
#pragma unroll
        for (int nj = 0; nj < 8; nj++)
#pragma unroll
            for (int e = 0; e < 4; e++) acc[nj][e] = 0.0f;
#pragma unroll
        for (int ks = 0; ks < 8; ks++) {
            int kb = ks * 8;
            unsigned a0 = __float_as_uint(Ps[(rm0 + g) * CDP + kb + t4]);
            unsigned a1 = __float_as_uint(Ps[(rm0 + 8 + g) * CDP + kb + t4]);
            unsigned a2 = __float_as_uint(Ps[(rm0 + g) * CDP + kb + t4 + 4]);
            unsigned a3 = __float_as_uint(Ps[(rm0 + 8 + g) * CDP + kb + t4 + 4]);
#pragma unroll
            for (int nj = 0; nj < 8; nj++) {
                unsigned b0 = __float_as_uint(Vs[(kb + t4) * CDP + nj * 8 + g]);
                unsigned b1 = __float_as_uint(Vs[(kb + t4 + 4) * CDP + nj * 8 + g]);
                mma8(acc[nj], a0, a1, a2, a3, b0, b1);
            }
        }
#pragma unroll
        for (int h = 0; h < 2; h++) {
            size_t pn = (size_t)p * NPP + n0 + rm0 + g + h * 8;
#pragma unroll
            for (int nj = 0; nj < 8; nj++) {
                int col = ch * 64 + nj * 8 + 2 * t4;
                *(float2*)&g_mid[pn * HALF + col] =
                    make_float2(acc[nj][2 * h], acc[nj][2 * h + 1]);
            }
        }
    }
}

// ---------------------------------------------------------------------------
// o-proj + BN + ReLU + residual via tf32 mma (unchanged from R2)
// ---------------------------------------------------------------------------
__global__ void __launch_bounds__(256) oproj_kernel(
    const float* __restrict__ x, const float* __restrict__ ow,
    float* __restrict__ out)
{
    __shared__ float As[32][132];
    __shared__ float Bs[32][68];

    const int t = threadIdx.x, lane = t & 31, warp = t >> 5;
    const int wm = (warp & 3) * 32, wn = (warp >> 2) * 32;
    const int g = lane >> 2, t4 = lane & 3;
    const int oc0 = blockIdx.x * 64;
    const int pn0 = blockIdx.y * 128;

    float acc[2][4][4];
#pragma unroll
    for (int mi = 0; mi < 2; mi++)
#pragma unroll
        for (int nj = 0; nj < 4; nj++)
#pragma unroll
            for (int e = 0; e < 4; e++) acc[mi][nj][e] = 0.0f;

    const int am2 = t & 127, ac = (t >> 7) * 16;
    const int boc = t & 63, bk = (t >> 6) * 8;

    for (int k0 = 0; k0 < HALF; k0 += 32) {
#pragma unroll
        for (int u = 0; u < 4; u++) {
            float4 v = *(const float4*)(g_mid + (size_t)(pn0 + am2) * HALF + k0 + ac + u * 4);
            As[ac + u * 4][am2]     = t32(v.x);
            As[ac + u * 4 + 1][am2] = t32(v.y);
            As[ac + u * 4 + 2][am2] = t32(v.z);
            As[ac + u * 4 + 3][am2] = t32(v.w);
        }
#pragma unroll
        for (int u = 0; u < 2; u++) {
            float4 v = *(const float4*)(ow + (size_t)(oc0 + boc) * HALF + k0 + bk + u * 4);
            Bs[bk + u * 4][boc]     = t32(v.x);
            Bs[bk + u * 4 + 1][boc] = t32(v.y);
            Bs[bk + u * 4 + 2][boc] = t32(v.z);
            Bs[bk + u * 4 + 3][boc] = t32(v.w);
        }
        __syncthreads();
#pragma unroll
        for (int kk = 0; kk < 32; kk += 8) {
            unsigned a[2][4], b[4][2];
#pragma unroll
            for (int mi = 0; mi < 2; mi++) {
                int mb = wm + mi * 16 + g;
                a[mi][0] = __float_as_uint(As[kk + t4][mb]);
                a[mi][1] = __float_as_uint(As[kk + t4][mb + 8]);
                a[mi][2] = __float_as_uint(As[kk + t4 + 4][mb]);
                a[mi][3] = __float_as_uint(As[kk + t4 + 4][mb + 8]);
            }
#pragma unroll
            for (int nj = 0; nj < 4; nj++) {
                int nb = wn + nj * 8 + g;
                b[nj][0] = __float_as_uint(Bs[kk + t4][nb]);
                b[nj][1] = __float_as_uint(Bs[kk + t4 + 4][nb]);
            }
#pragma unroll
            for (int mi = 0; mi < 2; mi++)
#pragma unroll
                for (int nj = 0; nj < 4; nj++)
                    mma8(acc[mi][nj], a[mi][0], a[mi][1], a[mi][2], a[mi][3],
                         b[nj][0], b[nj][1]);
        }
        __syncthreads();
    }

#pragma unroll
    for (int mi = 0; mi < 2; mi++)
#pragma unroll
        for (int h2 = 0; h2 < 2; h2++) {
            int pn = pn0 + wm + mi * 16 + g + h2 * 8;
            int p = pn >> 10, n = pn & 1023;
            int h = ((p >> 3) << 5) + (n >> 5);
            int w = ((p & 7) << 5) + (n & 31);
            int base = h * W_IMG + w;
#pragma unroll
            for (int nj = 0; nj < 4; nj++) {
                int oc = oc0 + wn + nj * 8 + t4 * 2;
                float s0 = g_pscale[768 + oc],     b0 = g_pbias[768 + oc];
                float s1 = g_pscale[768 + oc + 1], b1 = g_pbias[768 + oc + 1];
                size_t i0 = (size_t)oc * HW + base;
                size_t i1 = i0 + HW;
                out[i0] = fmaxf(fmaf(acc[mi][nj][h2 * 2],     s0, b0), 0.0f) + x[i0];
                out[i1] = fmaxf(fmaf(acc[mi][nj][h2 * 2 + 1], s1, b1), 0.0f) + x[i1];
            }
        }
}

// ---------------------------------------------------------------------------
extern "C" void kernel_launch(void* const* d_in, const int* in_sizes, int n_in,
                              void* d_out, int out_size)
{
    (void)in_sizes; (void)n_in; (void)out_size;
    const float* x  = (const float*)d_in[0];
    const float* qw = (const float*)d_in[1];
    const float* kw = (const float*)d_in[6];
    const float* vw = (const float*)d_in[11];
    const float* ow = (const float*)d_in[16];

    const int corr_smem = (64 * QSTR + 64 * CDP + 64 * CDP + 128 * CDP) * (int)sizeof(float);
    cudaFuncSetAttribute(corr_kernel,
                         cudaFuncAttributeMaxDynamicSharedMemorySize, corr_smem);

    prep_kernel<<<134, 256>>>(
        (const float*)d_in[2],  (const float*)d_in[3],  (const float*)d_in[4],  (const float*)d_in[5],
        (const float*)d_in[7],  (const float*)d_in[8],  (const float*)d_in[9],  (const float*)d_in[10],
        (const float*)d_in[12], (const float*)d_in[13], (const float*)d_in[14], (const float*)d_in[15],
        (const float*)d_in[17], (const float*)d_in[18], (const float*)d_in[19], (const float*)d_in[20]);

    qkv_kernel<<<dim3(12, 512), 256>>>(x, qw, kw, vw);
    attnqk_kernel<<<512, 256>>>();
    corr_kernel<<<dim3(8, 64), 256, corr_smem>>>();
    oproj_kernel<<<dim3(8, 512), 256>>>(x, ow, (float*)d_out);
}

// round 4
// speedup vs baseline: 3.4006x; 1.6478x over previous
#include <cuda_runtime.h>
#include <math.h>
#include <float.h>

#define HW    65536
#define CIN   512
#define HALF  256
#define NUM   64
#define NPP   1024
#define W_IMG 256
#define CDP   68
#define QSTR  132

// scratch (device globals: allocation-free rule)
__device__ float g_q[NUM * NPP * HALF];       // (pn, ch) q, scaled
__device__ float g_kp[HALF * NUM];            // (ch, patch) pooled k
__device__ float g_vp[NUM * HALF];            // (patch, ch) pooled v
__device__ float g_attn[NUM * NPP * NUM];     // (pn, m)
__device__ float g_mid[NUM * NPP * HALF];     // (pn, ch) attention output
__device__ float g_pscale[1280];              // fused BN scale (q,k,v,o)
__device__ float g_pbias[1280];               // fused BN bias

// ---------------------------------------------------------------------------
__device__ __forceinline__ float t32(float x) {
    asm("cvt.rna.tf32.f32 %0, %0;" : "+f"(x));
    return x;
}
__device__ __forceinline__ void mma8(float* d,
    unsigned a0, unsigned a1, unsigned a2, unsigned a3,
    unsigned b0, unsigned b1)
{
    asm volatile(
        "mma.sync.aligned.m16n8k8.row.col.f32.tf32.tf32.f32 "
        "{%0,%1,%2,%3},{%4,%5,%6,%7},{%8,%9},{%0,%1,%2,%3};"
        : "+f"(d[0]), "+f"(d[1]), "+f"(d[2]), "+f"(d[3])
        : "r"(a0), "r"(a1), "r"(a2), "r"(a3), "r"(b0), "r"(b1));
}
__device__ __forceinline__ void cpa16(float* smem_dst, const float* gsrc) {
    unsigned s = (unsigned)__cvta_generic_to_shared(smem_dst);
    asm volatile("cp.async.cg.shared.global [%0], [%1], 16;\n" :: "r"(s), "l"(gsrc));
}

// ---------------------------------------------------------------------------
// prep: fused BN params + zero pooled accumulators (must re-zero every launch)
// ---------------------------------------------------------------------------
__global__ void prep_kernel(
    const float* qg, const float* qb, const float* qm, const float* qv,
    const float* kg, const float* kb, const float* km, const float* kv,
    const float* vg, const float* vb, const float* vm, const float* vv,
    const float* og, const float* ob, const float* om, const float* ov)
{
    int i = blockIdx.x * blockDim.x + threadIdx.x;
    if (i < 1280) {
        const float *G, *B, *M, *V; float f; int r;
        if (i < 256)      { G = qg; B = qb; M = qm; V = qv; f = 0.044194173824159216f; r = i; }
        else if (i < 512) { G = kg; B = kb; M = km; V = kv; f = 1.0f / 1024.0f;        r = i - 256; }
        else if (i < 768) { G = vg; B = vb; M = vm; V = vv; f = 1.0f / 1024.0f;        r = i - 512; }
        else              { G = og; B = ob; M = om; V = ov; f = 1.0f;                  r = i - 768; }
        float s = G[r] * rsqrtf(V[r] + 1e-5f);
        g_pscale[i] = s * f;
        g_pbias[i]  = (B[r] - M[r] * s) * f;
    }
    int z = i - 1280;
    if (z >= 0 && z < HALF * NUM) g_kp[z] = 0.0f;
    z -= HALF * NUM;
    if (z >= 0 && z < NUM * HALF) g_vp[z] = 0.0f;
}

// ---------------------------------------------------------------------------
// QKV v2: block 128(pix) x 256(oc), K-tile 32, 2-stage cp.async, raw-fp32 tf32.
// grid (3, 512): blockIdx.x = full q / k / v projection.
// 8 warps = 2(m) x 4(n); warp tile 64x64 (mi=4, nj=8) -> 1.0 LDS/mma.
// smem: As[2][32][136] (x, [k][pix]); Bs[2][256][36] (W, [oc][k]).
// ---------------------------------------------------------------------------
#define QKV_SMEM ((2 * 32 * 136 + 2 * 256 * 36) * 4)
__global__ void __launch_bounds__(256, 1) qkv_kernel(
    const float* __restrict__ x, const float* __restrict__ qw,
    const float* __restrict__ kw, const float* __restrict__ vw)
{
    extern __shared__ float smq[];
    float* As = smq;                  // [2][32][136]
    float* Bs = smq + 2 * 32 * 136;   // [2][256][36]

    const int t = threadIdx.x, lane = t & 31, warp = t >> 5;
    const int g = lane >> 2, t4 = lane & 3;
    const int wm = (warp & 1) * 64, wn = (warp >> 1) * 64;
    const int gx = blockIdx.x;
    const int pix0 = blockIdx.y * 128;
    const float* Wp = (gx == 0) ? qw : (gx == 1) ? kw : vw;

    float acc[4][8][4] = {};

    const int a_row = t >> 5, a_c4 = (t & 31) * 4;          // + i*8 rows
    const int b_oc  = t >> 3, b_c4 = (t & 7) * 4;           // + i*32 rows

#define QKV_LOAD(s, k0)                                                        \
    {                                                                          \
        float* as = As + (s) * 32 * 136;                                       \
        float* bs = Bs + (s) * 256 * 36;                                       \
        _Pragma("unroll")                                                      \
        for (int i = 0; i < 4; i++)                                            \
            cpa16(as + (a_row + i * 8) * 136 + a_c4,                           \
                  x + (size_t)((k0) + a_row + i * 8) * HW + pix0 + a_c4);      \
        _Pragma("unroll")                                                      \
        for (int i = 0; i < 8; i++)                                            \
            cpa16(bs + (b_oc + i * 32) * 36 + b_c4,                            \
                  Wp + (size_t)(b_oc + i * 32) * CIN + (k0) + b_c4);           \
        asm volatile("cp.async.commit_group;\n");                              \
    }

    QKV_LOAD(0, 0);
    for (int kt = 0; kt < 16; kt++) {
        int s = kt & 1;
        if (kt < 15) {
            QKV_LOAD(s ^ 1, (kt + 1) * 32);
            asm volatile("cp.async.wait_group 1;\n");
        } else {
            asm volatile("cp.async.wait_group 0;\n");
        }
        __syncthreads();
        const float* as = As + s * 32 * 136;
        const float* bs = Bs + s * 256 * 36;
#pragma unroll
        for (int kk = 0; kk < 32; kk += 8) {
            unsigned a[4][4], b[8][2];
#pragma unroll
            for (int mi = 0; mi < 4; mi++) {
                int mb = wm + mi * 16 + g;
                a[mi][0] = __float_as_uint(as[(kk + t4) * 136 + mb]);
                a[mi][1] = __float_as_uint(as[(kk + t4) * 136 + mb + 8]);
                a[mi][2] = __float_as_uint(as[(kk + t4 + 4) * 136 + mb]);
                a[mi][3] = __float_as_uint(as[(kk + t4 + 4) * 136 + mb + 8]);
            }
#pragma unroll
            for (int nj = 0; nj < 8; nj++) {
                int nb = wn + nj * 8 + g;
                b[nj][0] = __float_as_uint(bs[nb * 36 + kk + t4]);
                b[nj][1] = __float_as_uint(bs[nb * 36 + kk + t4 + 4]);
            }
#pragma unroll
            for (int mi = 0; mi < 4; mi++)
#pragma unroll
                for (int nj = 0; nj < 8; nj++)
                    mma8(acc[mi][nj], a[mi][0], a[mi][1], a[mi][2], a[mi][3],
                         b[nj][0], b[nj][1]);
        }
        __syncthreads();
    }
#undef QKV_LOAD

    if (gx == 0) {
        // q: BN+ReLU (scale includes c^-0.5), write (pn, oc)
#pragma unroll
        for (int mi = 0; mi < 4; mi++)
#pragma unroll
            for (int h2 = 0; h2 < 2; h2++) {
                int pix = pix0 + wm + mi * 16 + g + h2 * 8;
                int h = pix >> 8, w = pix & 255;
                int pn = (((h >> 5) << 3) + (w >> 5)) * NPP + ((h & 31) << 5) + (w & 31);
#pragma unroll
                for (int nj = 0; nj < 8; nj++) {
                    int col = wn + nj * 8 + t4 * 2;
                    float v0 = fmaxf(fmaf(acc[mi][nj][h2 * 2],     g_pscale[col],     g_pbias[col]),     0.0f);
                    float v1 = fmaxf(fmaf(acc[mi][nj][h2 * 2 + 1], g_pscale[col + 1], g_pbias[col + 1]), 0.0f);
                    *(float2*)&g_q[(size_t)pn * HALF + col] = make_float2(v0, v1);
                }
            }
    } else {
        // k/v: BN+ReLU then patch-pool; warp m-range spans 2 patches (pl = mi>>1)
        float part[2][8][2] = {};
#pragma unroll
        for (int mi = 0; mi < 4; mi++) {
            int pl = mi >> 1;
#pragma unroll
            for (int nj = 0; nj < 8; nj++) {
                int col = wn + nj * 8 + t4 * 2;
                float s0 = g_pscale[gx * 256 + col],     b0 = g_pbias[gx * 256 + col];
                float s1 = g_pscale[gx * 256 + col + 1], b1 = g_pbias[gx * 256 + col + 1];
#pragma unroll
                for (int h2 = 0; h2 < 2; h2++) {
                    part[pl][nj][0] += fmaxf(fmaf(acc[mi][nj][h2 * 2],     s0, b0), 0.0f);
                    part[pl][nj][1] += fmaxf(fmaf(acc[mi][nj][h2 * 2 + 1], s1, b1), 0.0f);
                }
            }
        }
#pragma unroll
        for (int m_ = 4; m_ <= 16; m_ <<= 1)
#pragma unroll
            for (int pl = 0; pl < 2; pl++)
#pragma unroll
                for (int nj = 0; nj < 8; nj++) {
                    part[pl][nj][0] += __shfl_xor_sync(0xffffffffu, part[pl][nj][0], m_);
                    part[pl][nj][1] += __shfl_xor_sync(0xffffffffu, part[pl][nj][1], m_);
                }
        if (g == 0) {
            int h0 = pix0 >> 8, w0 = pix0 & 255;
            int pbase = ((h0 >> 5) << 3) + (w0 >> 5);
#pragma unroll
            for (int pl = 0; pl < 2; pl++) {
                int p = pbase + (wm >> 5) + pl;
#pragma unroll
                for (int nj = 0; nj < 8; nj++) {
                    int col = wn + nj * 8 + t4 * 2;
                    if (gx == 1) {
                        atomicAdd(&g_kp[col * NUM + p],       part[pl][nj][0]);
                        atomicAdd(&g_kp[(col + 1) * NUM + p], part[pl][nj][1]);
                    } else {
                        atomicAdd(&g_vp[p * HALF + col],     part[pl][nj][0]);
                        atomicAdd(&g_vp[p * HALF + col + 1], part[pl][nj][1]);
                    }
                }
            }
        }
    }
}

// ---------------------------------------------------------------------------
// attn[pn][m] = q[pn][:] . kp[:][m], tf32 mma (unchanged)
// ---------------------------------------------------------------------------
__global__ void __launch_bounds__(256) attnqk_kernel()
{
    __shared__ float As[32][132];
    __shared__ float Bs[32][68];

    const int t = threadIdx.x, lane = t & 31, warp = t >> 5;
    const int wm = (warp & 3) * 32, wn = (warp >> 2) * 32;
    const int g = lane >> 2, t4 = lane & 3;
    const int pn0 = blockIdx.x * 128;

    float acc[2][4][4] = {};

    const int am2 = t & 127, ac = (t >> 7) * 16;
    const int bn4 = (t & 15) * 4, bk2 = t >> 4;

    for (int k0 = 0; k0 < HALF; k0 += 32) {
#pragma unroll
        for (int u = 0; u < 4; u++) {
            float4 v = *(const float4*)(g_q + (size_t)(pn0 + am2) * HALF + k0 + ac + u * 4);
            As[ac + u * 4][am2]     = v.x;
            As[ac + u * 4 + 1][am2] = v.y;
            As[ac + u * 4 + 2][am2] = v.z;
            As[ac + u * 4 + 3][am2] = v.w;
        }
#pragma unroll
        for (int u = 0; u < 2; u++) {
            int kr = bk2 + u * 16;
            float4 v = *(const float4*)(g_kp + (size_t)(k0 + kr) * NUM + bn4);
            Bs[kr][bn4]     = v.x;
            Bs[kr][bn4 + 1] = v.y;
            Bs[kr][bn4 + 2] = v.z;
            Bs[kr][bn4 + 3] = v.w;
        }
        __syncthreads();
#pragma unroll
        for (int kk = 0; kk < 32; kk += 8) {
            unsigned a[2][4], b[4][2];
#pragma unroll
            for (int mi = 0; mi < 2; mi++) {
                int mb = wm + mi * 16 + g;
                a[mi][0] = __float_as_uint(As[kk + t4][mb]);
                a[mi][1] = __float_as_uint(As[kk + t4][mb + 8]);
                a[mi][2] = __float_as_uint(As[kk + t4 + 4][mb]);
                a[mi][3] = __float_as_uint(As[kk + t4 + 4][mb + 8]);
            }
#pragma unroll
            for (int nj = 0; nj < 4; nj++) {
                int nb = wn + nj * 8 + g;
                b[nj][0] = __float_as_uint(Bs[kk + t4][nb]);
                b[nj][1] = __float_as_uint(Bs[kk + t4 + 4][nb]);
            }
#pragma unroll
            for (int mi = 0; mi < 2; mi++)
#pragma unroll
                for (int nj = 0; nj < 4; nj++)
                    mma8(acc[mi][nj], a[mi][0], a[mi][1], a[mi][2], a[mi][3],
                         b[nj][0], b[nj][1]);
        }
        __syncthreads();
    }

#pragma unroll
    for (int mi = 0; mi < 2; mi++)
#pragma unroll
        for (int h2 = 0; h2 < 2; h2++) {
            int row = pn0 + wm + mi * 16 + g + h2 * 8;
#pragma unroll
            for (int nj = 0; nj < 4; nj++) {
                int col = wn + nj * 8 + t4 * 2;
                *(float2*)&g_attn[(size_t)row * NUM + col] =
                    make_float2(acc[mi][nj][h2 * 2], acc[mi][nj][h2 * 2 + 1]);
            }
        }
}

// ---------------------------------------------------------------------------
// corr (tensor-core, unchanged from R3)
// ---------------------------------------------------------------------------
__global__ void __launch_bounds__(256, 2) corr_kernel()
{
    extern __shared__ float sm[];
    float* Qs = sm;
    float* Ks = Qs + 64 * QSTR;
    float* Vs = Ks + 64 * CDP;
    float* Ps = Vs + 64 * CDP;

    const int t = threadIdx.x, lane = t & 31, warp = t >> 5;
    const int g = lane >> 2, t4 = lane & 3;
    const int rm0 = warp * 16;
    const int n0 = blockIdx.x * 128;
    const int p  = blockIdx.y;
    const float* ab = g_attn + (size_t)p * NPP * NUM;

    {
        int nl = t >> 1, d0 = (t & 1) * 32;
#pragma unroll
        for (int u = 0; u < 8; u++) {
            int d = d0 + u * 4;
            float4 v = *(const float4*)(ab + (size_t)(n0 + nl) * NUM + d);
            Qs[(d    ) * QSTR + nl] = v.x;
            Qs[(d + 1) * QSTR + nl] = v.y;
            Qs[(d + 2) * QSTR + nl] = v.z;
            Qs[(d + 3) * QSTR + nl] = v.w;
        }
    }

    float mi[2] = {-FLT_MAX, -FLT_MAX}, li[2] = {0.0f, 0.0f};
    float o[8][4];
#pragma unroll
    for (int nj = 0; nj < 8; nj++)
#pragma unroll
        for (int e = 0; e < 4; e++) o[nj][e] = 0.0f;

    for (int jt = 0; jt < 16; jt++) {
        __syncthreads();
        {
            int jl = t >> 2, c0 = (t & 3) * 16;
#pragma unroll
            for (int u = 0; u < 4; u++) {
                int d = c0 + u * 4;
                float4 v = *(const float4*)(ab + (size_t)(jt * 64 + jl) * NUM + d);
                Ks[(d    ) * CDP + jl] = v.x;
                Ks[(d + 1) * CDP + jl] = v.y;
                Ks[(d + 2) * CDP + jl] = v.z;
                Ks[(d + 3) * CDP + jl] = v.w;
                float4 tv = make_float4(t32(v.x), t32(v.y), t32(v.z), t32(v.w));
                *(float4*)&Vs[jl * CDP + d] = tv;
            }
        }
        __syncthreads();

        float s[8][4];
#pragma unroll
        for (int nj = 0; nj < 8; nj++)
#pragma unroll
            for (int e = 0; e < 4; e++) s[nj][e] = 0.0f;

#pragma unroll
        for (int ks = 0; ks < 8; ks++) {
            int kb = ks * 8;
            float qa0 = Qs[(kb + t4) * QSTR + rm0 + g];
            float qa1 = Qs[(kb + t4) * QSTR + rm0 + 8 + g];
            float qa2 = Qs[(kb + t4 + 4) * QSTR + rm0 + g];
            float qa3 = Qs[(kb + t4 + 4) * QSTR + rm0 + 8 + g];
            float ab0 = t32(qa0), ab1 = t32(qa1), ab2 = t32(qa2), ab3 = t32(qa3);
            float ar0 = t32(qa0 - ab0), ar1 = t32(qa1 - ab1);
            float ar2 = t32(qa2 - ab2), ar3 = t32(qa3 - ab3);
#pragma unroll
            for (int nj = 0; nj < 8; nj++) {
                float kr0 = Ks[(kb + t4) * CDP + nj * 8 + g];
                float kr1 = Ks[(kb + t4 + 4) * CDP + nj * 8 + g];
                float bb0 = t32(kr0), bb1 = t32(kr1);
                float br0 = t32(kr0 - bb0), br1 = t32(kr1 - bb1);
                mma8(s[nj], __float_as_uint(ab0), __float_as_uint(ab1),
                            __float_as_uint(ab2), __float_as_uint(ab3),
                            __float_as_uint(bb0), __float_as_uint(bb1));
                mma8(s[nj], __float_as_uint(ab0), __float_as_uint(ab1),
                            __float_as_uint(ab2), __float_as_uint(ab3),
                            __float_as_uint(br0), __float_as_uint(br1));
                mma8(s[nj], __float_as_uint(ar0), __float_as_uint(ar1),
                            __float_as_uint(ar2), __float_as_uint(ar3),
                            __float_as_uint(bb0), __float_as_uint(bb1));
            }
        }

#pragma unroll
        for (int h = 0; h < 2; h++) {
            float rmax = -FLT_MAX;
#pragma unroll
            for (int nj = 0; nj < 8; nj++)
                rmax = fmaxf(rmax, fmaxf(s[nj][2 * h], s[nj][2 * h + 1]));
            rmax = fmaxf(rmax, __shfl_xor_sync(0xffffffffu, rmax, 1));
            rmax = fmaxf(rmax, __shfl_xor_sync(0xffffffffu, rmax, 2));
            float nm = fmaxf(mi[h], rmax);
            float sc = __expf(mi[h] - nm);
            mi[h] = nm;
            float rs = 0.0f;
#pragma unroll
            for (int nj = 0; nj < 8; nj++) {
                float v0 = __expf(s[nj][2 * h]     - nm);
                float v1 = __expf(s[nj][2 * h + 1] - nm);
                s[nj][2 * h] = v0; s[nj][2 * h + 1] = v1;
                rs += v0 + v1;
            }
            rs += __shfl_xor_sync(0xffffffffu, rs, 1);
            rs += __shfl_xor_sync(0xffffffffu, rs, 2);
            li[h] = li[h] * sc + rs;
#pragma unroll
            for (int nj = 0; nj < 8; nj++) {
                o[nj][2 * h]     *= sc;
                o[nj][2 * h + 1] *= sc;
            }
        }

#pragma unroll
        for (int h = 0; h < 2; h++)
#pragma unroll
            for (int nj = 0; nj < 8; nj++)
                *(float2*)&Ps[(rm0 + g + h * 8) * CDP + nj * 8 + 2 * t4] =
                    make_float2(t32(s[nj][2 * h]), t32(s[nj][2 * h + 1]));
        __syncwarp();

#pragma unroll
        for (int ks = 0; ks < 8; ks++) {
            int kb = ks * 8;
            unsigned a0 = __float_as_uint(Ps[(rm0 + g) * CDP + kb + t4]);
            unsigned a1 = __float_as_uint(Ps[(rm0 + 8 + g) * CDP + kb + t4]);
            unsigned a2 = __float_as_uint(Ps[(rm0 + g) * CDP + kb + t4 + 4]);
            unsigned a3 = __float_as_uint(Ps[(rm0 + 8 + g) * CDP + kb + t4 + 4]);
#pragma unroll
            for (int nj = 0; nj < 8; nj++) {
                unsigned b0 = __float_as_uint(Vs[(kb + t4) * CDP + nj * 8 + g]);
                unsigned b1 = __float_as_uint(Vs[(kb + t4 + 4) * CDP + nj * 8 + g]);
                mma8(o[nj], a0, a1, a2, a3, b0, b1);
            }
        }
    }

#pragma unroll
    for (int h = 0; h < 2; h++) {
        int nl = rm0 + g + h * 8;
        float inv = 1.0f / li[h];
        float tv[16];
#pragma unroll
        for (int nj = 0; nj < 8; nj++)
#pragma unroll
            for (int e2 = 0; e2 < 2; e2++) {
                int d = nj * 8 + 2 * t4 + e2;
                tv[nj * 2 + e2] = Qs[d * QSTR + nl] + o[nj][2 * h + e2] * inv;
            }
        float rmax = -FLT_MAX;
#pragma unroll
        for (int l = 0; l < 16; l++) rmax = fmaxf(rmax, tv[l]);
        rmax = fmaxf(rmax, __shfl_xor_sync(0xffffffffu, rmax, 1));
        rmax = fmaxf(rmax, __shfl_xor_sync(0xffffffffu, rmax, 2));
        float rs = 0.0f;
#pragma unroll
        for (int l = 0; l < 16; l++) { tv[l] = __expf(tv[l] - rmax); rs += tv[l]; }
        rs += __shfl_xor_sync(0xffffffffu, rs, 1);
        rs += __shfl_xor_sync(0xffffffffu, rs, 2);
        float is = 1.0f / rs;
#pragma unroll
        for (int nj = 0; nj < 8; nj++)
            *(float2*)&Ps[(rm0 + g + h * 8) * CDP + nj * 8 + 2 * t4] =
                make_float2(t32(tv[nj * 2] * is), t32(tv[nj * 2 + 1] * is));
    }

    for (int ch = 0; ch < 4; ch++) {
        __syncthreads();
        {
            int m = t >> 2, c0 = (t & 3) * 16;
#pragma unroll
            for (int u = 0; u < 4; u++) {
                float4 v = *(const float4*)(g_vp + (size_t)m * HALF + ch * 64 + c0 + u * 4);
                float4 tv2 = make_float4(t32(v.x), t32(v.y), t32(v.z), t32(v.w));
                *(float4*)&Vs[m * CDP + c0 + u * 4] = tv2;
            }
        }
        __syncthreads();

        float acc[8][4];
#pragma unroll
        for (int nj = 0; nj < 8; nj++)
#pragma unroll
            for (int e = 0; e < 4; e++) acc[nj][e] = 0.0f;
#pragma unroll
        for (int ks = 0; ks < 8; ks++) {
            int kb = ks * 8;
            unsigned a0 = __float_as_uint(Ps[(rm0 + g) * CDP + kb + t4]);
            unsigned a1 = __float_as_uint(Ps[(rm0 + 8 + g) * CDP + kb + t4]);
            unsigned a2 = __float_as_uint(Ps[(rm0 + g) * CDP + kb + t4 + 4]);
            unsigned a3 = __float_as_uint(Ps[(rm0 + 8 + g) * CDP + kb + t4 + 4]);
#pragma unroll
            for (int nj = 0; nj < 8; nj++) {
                unsigned b0 = __float_as_uint(Vs[(kb + t4) * CDP + nj * 8 + g]);
                unsigned b1 = __float_as_uint(Vs[(kb + t4 + 4) * CDP + nj * 8 + g]);
                mma8(acc[nj], a0, a1, a2, a3, b0, b1);
            }
        }
#pragma unroll
        for (int h = 0; h < 2; h++) {
            size_t pn = (size_t)p * NPP + n0 + rm0 + g + h * 8;
#pragma unroll
            for (int nj = 0; nj < 8; nj++) {
                int col = ch * 64 + nj * 8 + 2 * t4;
                *(float2*)&g_mid[pn * HALF + col] =
                    make_float2(acc[nj][2 * h], acc[nj][2 * h + 1]);
            }
        }
    }
}

// ---------------------------------------------------------------------------
// o-proj v2: block 128(pn) x 256(oc), K=256, 2-stage cp.async, raw-fp32 tf32.
// grid (2, 512). smem: As[2][128][36] (mid, [pn][k]); Bs[2][256][36] ([oc][k]).
// ---------------------------------------------------------------------------
#define OPR_SMEM ((2 * 128 * 36 + 2 * 256 * 36) * 4)
__global__ void __launch_bounds__(256, 1) oproj_kernel(
    const float* __restrict__ x, const float* __restrict__ ow,
    float* __restrict__ out)
{
    extern __shared__ float smo[];
    float* As = smo;                   // [2][128][36]
    float* Bs = smo + 2 * 128 * 36;    // [2][256][36]

    const int t = threadIdx.x, lane = t & 31, warp = t >> 5;
    const int g = lane >> 2, t4 = lane & 3;
    const int wm = (warp & 1) * 64, wn = (warp >> 1) * 64;
    const int ocr = blockIdx.x * 256;
    const int pn0 = blockIdx.y * 128;

    float acc[4][8][4] = {};

    const int a_row = t >> 3, a_c4 = (t & 7) * 4;   // + i*32 rows (4 iters)
    const int b_oc  = t >> 3, b_c4 = (t & 7) * 4;   // + i*32 rows (8 iters)

#define OPR_LOAD(s, k0)                                                        \
    {                                                                          \
        float* as = As + (s) * 128 * 36;                                       \
        float* bs = Bs + (s) * 256 * 36;                                       \
        _Pragma("unroll")                                                      \
        for (int i = 0; i < 4; i++)                                            \
            cpa16(as + (a_row + i * 32) * 36 + a_c4,                           \
                  g_mid + (size_t)(pn0 + a_row + i * 32) * HALF + (k0) + a_c4);\
        _Pragma("unroll")                                                      \
        for (int i = 0; i < 8; i++)                                            \
            cpa16(bs + (b_oc + i * 32) * 36 + b_c4,                            \
                  ow + (size_t)(ocr + b_oc + i * 32) * HALF + (k0) + b_c4);    \
        asm volatile("cp.async.commit_group;\n");                              \
    }

    OPR_LOAD(0, 0);
    for (int kt = 0; kt < 8; kt++) {
        int s = kt & 1;
        if (kt < 7) {
            OPR_LOAD(s ^ 1, (kt + 1) * 32);
            asm volatile("cp.async.wait_group 1;\n");
        } else {
            asm volatile("cp.async.wait_group 0;\n");
        }
        __syncthreads();
        const float* as = As + s * 128 * 36;
        const float* bs = Bs + s * 256 * 36;
#pragma unroll
        for (int kk = 0; kk < 32; kk += 8) {
            unsigned a[4][4], b[8][2];
#pragma unroll
            for (int mi = 0; mi < 4; mi++) {
                int mb = wm + mi * 16 + g;
                a[mi][0] = __float_as_uint(as[mb * 36 + kk + t4]);
                a[mi][1] = __float_as_uint(as[(mb + 8) * 36 + kk + t4]);
                a[mi][2] = __float_as_uint(as[mb * 36 + kk + t4 + 4]);
                a[mi][3] = __float_as_uint(as[(mb + 8) * 36 + kk + t4 + 4]);
            }
#pragma unroll
            for (int nj = 0; nj < 8; nj++) {
                int nb = wn + nj * 8 + g;
                b[nj][0] = __float_as_uint(bs[nb * 36 + kk + t4]);
                b[nj][1] = __float_as_uint(bs[nb * 36 + kk + t4 + 4]);
            }
#pragma unroll
            for (int mi = 0; mi < 4; mi++)
#pragma unroll
                for (int nj = 0; nj < 8; nj++)
                    mma8(acc[mi][nj], a[mi][0], a[mi][1], a[mi][2], a[mi][3],
                         b[nj][0], b[nj][1]);
        }
        __syncthreads();
    }
#undef OPR_LOAD

#pragma unroll
    for (int mi = 0; mi < 4; mi++)
#pragma unroll
        for (int h2 = 0; h2 < 2; h2++) {
            int pn = pn0 + wm + mi * 16 + g + h2 * 8;
            int p = pn >> 10, n = pn & 1023;
            int h = ((p >> 3) << 5) + (n >> 5);
            int w = ((p & 7) << 5) + (n & 31);
            int base = h * W_IMG + w;
#pragma unroll
            for (int nj = 0; nj < 8; nj++) {
                int oc = ocr + wn + nj * 8 + t4 * 2;
                float s0 = g_pscale[768 + oc],     b0 = g_pbias[768 + oc];
                float s1 = g_pscale[768 + oc + 1], b1 = g_pbias[768 + oc + 1];
                size_t i0 = (size_t)oc * HW + base;
                size_t i1 = i0 + HW;
                out[i0] = fmaxf(fmaf(acc[mi][nj][h2 * 2],     s0, b0), 0.0f) + x[i0];
                out[i1] = fmaxf(fmaf(acc[mi][nj][h2 * 2 + 1], s1, b1), 0.0f) + x[i1];
            }
        }
}

// ---------------------------------------------------------------------------
extern "C" void kernel_launch(void* const* d_in, const int* in_sizes, int n_in,
                              void* d_out, int out_size)
{
    (void)in_sizes; (void)n_in; (void)out_size;
    const float* x  = (const float*)d_in[0];
    const float* qw = (const float*)d_in[1];
    const float* kw = (const float*)d_in[6];
    const float* vw = (const float*)d_in[11];
    const float* ow = (const float*)d_in[16];

    const int corr_smem = (64 * QSTR + 64 * CDP + 64 * CDP + 128 * CDP) * (int)sizeof(float);
    cudaFuncSetAttribute(corr_kernel,
                         cudaFuncAttributeMaxDynamicSharedMemorySize, corr_smem);
    cudaFuncSetAttribute(qkv_kernel,
                         cudaFuncAttributeMaxDynamicSharedMemorySize, QKV_SMEM);
    cudaFuncSetAttribute(oproj_kernel,
                         cudaFuncAttributeMaxDynamicSharedMemorySize, OPR_SMEM);

    prep_kernel<<<134, 256>>>(
        (const float*)d_in[2],  (const float*)d_in[3],  (const float*)d_in[4],  (const float*)d_in[5],
        (const float*)d_in[7],  (const float*)d_in[8],  (const float*)d_in[9],  (const float*)d_in[10],
        (const float*)d_in[12], (const float*)d_in[13], (const float*)d_in[14], (const float*)d_in[15],
        (const float*)d_in[17], (const float*)d_in[18], (const float*)d_in[19], (const float*)d_in[20]);

    qkv_kernel<<<dim3(3, 512), 256, QKV_SMEM>>>(x, qw, kw, vw);
    attnqk_kernel<<<512, 256>>>();
    corr_kernel<<<dim3(8, 64), 256, corr_smem>>>();
    oproj_kernel<<<dim3(2, 512), 256, OPR_SMEM>>>(x, ow, (float*)d_out);
}

// round 5
// speedup vs baseline: 3.4735x; 1.0214x over previous
#include <cuda_runtime.h>
#include <math.h>
#include <float.h>

#define HW    65536
#define CIN   512
#define HALF  256
#define NUM   64
#define NPP   1024
#define W_IMG 256
#define KP    72                     // pair-layout row pitch (floats)

// scratch (device globals: allocation-free rule)
__device__ float g_q[NUM * NPP * HALF];       // (pn, ch) q, scaled
__device__ float g_kp[HALF * NUM];            // (ch, patch) pooled k
__device__ float g_vp[NUM * HALF];            // (patch, ch) pooled v
__device__ float g_attn[NUM * NPP * NUM];     // (pn, m)
__device__ float g_mid[NUM * NPP * HALF];     // (pn, ch) attention output
__device__ float g_pscale[1280];              // fused BN scale (q,k,v,o)
__device__ float g_pbias[1280];               // fused BN bias

// ---------------------------------------------------------------------------
__device__ __forceinline__ float t32(float x) {
    asm("cvt.rna.tf32.f32 %0, %0;" : "+f"(x));
    return x;
}
__device__ __forceinline__ void mma8(float* d,
    unsigned a0, unsigned a1, unsigned a2, unsigned a3,
    unsigned b0, unsigned b1)
{
    asm volatile(
        "mma.sync.aligned.m16n8k8.row.col.f32.tf32.tf32.f32 "
        "{%0,%1,%2,%3},{%4,%5,%6,%7},{%8,%9},{%0,%1,%2,%3};"
        : "+f"(d[0]), "+f"(d[1]), "+f"(d[2]), "+f"(d[3])
        : "r"(a0), "r"(a1), "r"(a2), "r"(a3), "r"(b0), "r"(b1));
}
__device__ __forceinline__ void cpa16(float* smem_dst, const float* gsrc) {
    unsigned s = (unsigned)__cvta_generic_to_shared(smem_dst);
    asm volatile("cp.async.cg.shared.global [%0], [%1], 16;\n" :: "r"(s), "l"(gsrc));
}
// pair-perm within each 8-block: k -> (k&3)*2 + ((k>>2)&1); so offsets
// (t4*2, t4*2+1) hold (k=t4, k=t4+4) — one LDS.64 per mma B/A fragment pair.
__device__ __forceinline__ int perm8(int k) {
    return (k & ~7) + ((k & 3) * 2) + ((k >> 2) & 1);
}

// ---------------------------------------------------------------------------
// prep: fused BN params + zero pooled accumulators (must re-zero every launch)
// ---------------------------------------------------------------------------
__global__ void prep_kernel(
    const float* qg, const float* qb, const float* qm, const float* qv,
    const float* kg, const float* kb, const float* km, const float* kv,
    const float* vg, const float* vb, const float* vm, const float* vv,
    const float* og, const float* ob, const float* om, const float* ov)
{
    int i = blockIdx.x * blockDim.x + threadIdx.x;
    if (i < 1280) {
        const float *G, *B, *M, *V; float f; int r;
        if (i < 256)      { G = qg; B = qb; M = qm; V = qv; f = 0.044194173824159216f; r = i; }
        else if (i < 512) { G = kg; B = kb; M = km; V = kv; f = 1.0f / 1024.0f;        r = i - 256; }
        else if (i < 768) { G = vg; B = vb; M = vm; V = vv; f = 1.0f / 1024.0f;        r = i - 512; }
        else              { G = og; B = ob; M = om; V = ov; f = 1.0f;                  r = i - 768; }
        float s = G[r] * rsqrtf(V[r] + 1e-5f);
        g_pscale[i] = s * f;
        g_pbias[i]  = (B[r] - M[r] * s) * f;
    }
    int z = i - 1280;
    if (z >= 0 && z < HALF * NUM) g_kp[z] = 0.0f;
    z -= HALF * NUM;
    if (z >= 0 && z < NUM * HALF) g_vp[z] = 0.0f;
}

// ---------------------------------------------------------------------------
// QKV v2 (unchanged from R4)
// ---------------------------------------------------------------------------
#define QKV_SMEM ((2 * 32 * 136 + 2 * 256 * 36) * 4)
__global__ void __launch_bounds__(256, 1) qkv_kernel(
    const float* __restrict__ x, const float* __restrict__ qw,
    const float* __restrict__ kw, const float* __restrict__ vw)
{
    extern __shared__ float smq[];
    float* As = smq;                  // [2][32][136]
    float* Bs = smq + 2 * 32 * 136;   // [2][256][36]

    const int t = threadIdx.x, lane = t & 31, warp = t >> 5;
    const int g = lane >> 2, t4 = lane & 3;
    const int wm = (warp & 1) * 64, wn = (warp >> 1) * 64;
    const int gx = blockIdx.x;
    const int pix0 = blockIdx.y * 128;
    const float* Wp = (gx == 0) ? qw : (gx == 1) ? kw : vw;

    float acc[4][8][4] = {};

    const int a_row = t >> 5, a_c4 = (t & 31) * 4;
    const int b_oc  = t >> 3, b_c4 = (t & 7) * 4;

#define QKV_LOAD(s, k0)                                                        \
    {                                                                          \
        float* as = As + (s) * 32 * 136;                                       \
        float* bs = Bs + (s) * 256 * 36;                                       \
        _Pragma("unroll")                                                      \
        for (int i = 0; i < 4; i++)                                            \
            cpa16(as + (a_row + i * 8) * 136 + a_c4,                           \
                  x + (size_t)((k0) + a_row + i * 8) * HW + pix0 + a_c4);      \
        _Pragma("unroll")                                                      \
        for (int i = 0; i < 8; i++)                                            \
            cpa16(bs + (b_oc + i * 32) * 36 + b_c4,                            \
                  Wp + (size_t)(b_oc + i * 32) * CIN + (k0) + b_c4);           \
        asm volatile("cp.async.commit_group;\n");                              \
    }

    QKV_LOAD(0, 0);
    for (int kt = 0; kt < 16; kt++) {
        int s = kt & 1;
        if (kt < 15) {
            QKV_LOAD(s ^ 1, (kt + 1) * 32);
            asm volatile("cp.async.wait_group 1;\n");
        } else {
            asm volatile("cp.async.wait_group 0;\n");
        }
        __syncthreads();
        const float* as = As + s * 32 * 136;
        const float* bs = Bs + s * 256 * 36;
#pragma unroll
        for (int kk = 0; kk < 32; kk += 8) {
            unsigned a[4][4], b[8][2];
#pragma unroll
            for (int mi = 0; mi < 4; mi++) {
                int mb = wm + mi * 16 + g;
                a[mi][0] = __float_as_uint(as[(kk + t4) * 136 + mb]);
                a[mi][1] = __float_as_uint(as[(kk + t4) * 136 + mb + 8]);
                a[mi][2] = __float_as_uint(as[(kk + t4 + 4) * 136 + mb]);
                a[mi][3] = __float_as_uint(as[(kk + t4 + 4) * 136 + mb + 8]);
            }
#pragma unroll
            for (int nj = 0; nj < 8; nj++) {
                int nb = wn + nj * 8 + g;
                b[nj][0] = __float_as_uint(bs[nb * 36 + kk + t4]);
                b[nj][1] = __float_as_uint(bs[nb * 36 + kk + t4 + 4]);
            }
#pragma unroll
            for (int mi = 0; mi < 4; mi++)
#pragma unroll
                for (int nj = 0; nj < 8; nj++)
                    mma8(acc[mi][nj], a[mi][0], a[mi][1], a[mi][2], a[mi][3],
                         b[nj][0], b[nj][1]);
        }
        __syncthreads();
    }
#undef QKV_LOAD

    if (gx == 0) {
#pragma unroll
        for (int mi = 0; mi < 4; mi++)
#pragma unroll
            for (int h2 = 0; h2 < 2; h2++) {
                int pix = pix0 + wm + mi * 16 + g + h2 * 8;
                int h = pix >> 8, w = pix & 255;
                int pn = (((h >> 5) << 3) + (w >> 5)) * NPP + ((h & 31) << 5) + (w & 31);
#pragma unroll
                for (int nj = 0; nj < 8; nj++) {
                    int col = wn + nj * 8 + t4 * 2;
                    float v0 = fmaxf(fmaf(acc[mi][nj][h2 * 2],     g_pscale[col],     g_pbias[col]),     0.0f);
                    float v1 = fmaxf(fmaf(acc[mi][nj][h2 * 2 + 1], g_pscale[col + 1], g_pbias[col + 1]), 0.0f);
                    *(float2*)&g_q[(size_t)pn * HALF + col] = make_float2(v0, v1);
                }
            }
    } else {
        float part[2][8][2] = {};
#pragma unroll
        for (int mi = 0; mi < 4; mi++) {
            int pl = mi >> 1;
#pragma unroll
            for (int nj = 0; nj < 8; nj++) {
                int col = wn + nj * 8 + t4 * 2;
                float s0 = g_pscale[gx * 256 + col],     b0 = g_pbias[gx * 256 + col];
                float s1 = g_pscale[gx * 256 + col + 1], b1 = g_pbias[gx * 256 + col + 1];
#pragma unroll
                for (int h2 = 0; h2 < 2; h2++) {
                    part[pl][nj][0] += fmaxf(fmaf(acc[mi][nj][h2 * 2],     s0, b0), 0.0f);
                    part[pl][nj][1] += fmaxf(fmaf(acc[mi][nj][h2 * 2 + 1], s1, b1), 0.0f);
                }
            }
        }
#pragma unroll
        for (int m_ = 4; m_ <= 16; m_ <<= 1)
#pragma unroll
            for (int pl = 0; pl < 2; pl++)
#pragma unroll
                for (int nj = 0; nj < 8; nj++) {
                    part[pl][nj][0] += __shfl_xor_sync(0xffffffffu, part[pl][nj][0], m_);
                    part[pl][nj][1] += __shfl_xor_sync(0xffffffffu, part[pl][nj][1], m_);
                }
        if (g == 0) {
            int h0 = pix0 >> 8, w0 = pix0 & 255;
            int pbase = ((h0 >> 5) << 3) + (w0 >> 5);
#pragma unroll
            for (int pl = 0; pl < 2; pl++) {
                int p = pbase + (wm >> 5) + pl;
#pragma unroll
                for (int nj = 0; nj < 8; nj++) {
                    int col = wn + nj * 8 + t4 * 2;
                    if (gx == 1) {
                        atomicAdd(&g_kp[col * NUM + p],       part[pl][nj][0]);
                        atomicAdd(&g_kp[(col + 1) * NUM + p], part[pl][nj][1]);
                    } else {
                        atomicAdd(&g_vp[p * HALF + col],     part[pl][nj][0]);
                        atomicAdd(&g_vp[p * HALF + col + 1], part[pl][nj][1]);
                    }
                }
            }
        }
    }
}

// ---------------------------------------------------------------------------
// attn[pn][m] = q[pn][:] . kp[:][m], tf32 mma (unchanged)
// ---------------------------------------------------------------------------
__global__ void __launch_bounds__(256) attnqk_kernel()
{
    __shared__ float As[32][132];
    __shared__ float Bs[32][68];

    const int t = threadIdx.x, lane = t & 31, warp = t >> 5;
    const int wm = (warp & 3) * 32, wn = (warp >> 2) * 32;
    const int g = lane >> 2, t4 = lane & 3;
    const int pn0 = blockIdx.x * 128;

    float acc[2][4][4] = {};

    const int am2 = t & 127, ac = (t >> 7) * 16;
    const int bn4 = (t & 15) * 4, bk2 = t >> 4;

    for (int k0 = 0; k0 < HALF; k0 += 32) {
#pragma unroll
        for (int u = 0; u < 4; u++) {
            float4 v = *(const float4*)(g_q + (size_t)(pn0 + am2) * HALF + k0 + ac + u * 4);
            As[ac + u * 4][am2]     = v.x;
            As[ac + u * 4 + 1][am2] = v.y;
            As[ac + u * 4 + 2][am2] = v.z;
            As[ac + u * 4 + 3][am2] = v.w;
        }
#pragma unroll
        for (int u = 0; u < 2; u++) {
            int kr = bk2 + u * 16;
            float4 v = *(const float4*)(g_kp + (size_t)(k0 + kr) * NUM + bn4);
            Bs[kr][bn4]     = v.x;
            Bs[kr][bn4 + 1] = v.y;
            Bs[kr][bn4 + 2] = v.z;
            Bs[kr][bn4 + 3] = v.w;
        }
        __syncthreads();
#pragma unroll
        for (int kk = 0; kk < 32; kk += 8) {
            unsigned a[2][4], b[4][2];
#pragma unroll
            for (int mi = 0; mi < 2; mi++) {
                int mb = wm + mi * 16 + g;
                a[mi][0] = __float_as_uint(As[kk + t4][mb]);
                a[mi][1] = __float_as_uint(As[kk + t4][mb + 8]);
                a[mi][2] = __float_as_uint(As[kk + t4 + 4][mb]);
                a[mi][3] = __float_as_uint(As[kk + t4 + 4][mb + 8]);
            }
#pragma unroll
            for (int nj = 0; nj < 4; nj++) {
                int nb = wn + nj * 8 + g;
                b[nj][0] = __float_as_uint(Bs[kk + t4][nb]);
                b[nj][1] = __float_as_uint(Bs[kk + t4 + 4][nb]);
            }
#pragma unroll
            for (int mi = 0; mi < 2; mi++)
#pragma unroll
                for (int nj = 0; nj < 4; nj++)
                    mma8(acc[mi][nj], a[mi][0], a[mi][1], a[mi][2], a[mi][3],
                         b[nj][0], b[nj][1]);
        }
        __syncthreads();
    }

#pragma unroll
    for (int mi = 0; mi < 2; mi++)
#pragma unroll
        for (int h2 = 0; h2 < 2; h2++) {
            int row = pn0 + wm + mi * 16 + g + h2 * 8;
#pragma unroll
            for (int nj = 0; nj < 4; nj++) {
                int col = wn + nj * 8 + t4 * 2;
                *(float2*)&g_attn[(size_t)row * NUM + col] =
                    make_float2(acc[mi][nj][h2 * 2], acc[mi][nj][h2 * 2 + 1]);
            }
        }
}

// ---------------------------------------------------------------------------
// corr v3: 128 rows/block, 8 warps x 16 rows. Pair-permuted smem layouts so
// every mma fragment pair is one LDS.64 (conflict-free @ pitch 72). Q frags
// in registers; K split (big/res) precomputed at tile load. Q raw re-read and
// final attn add go straight to gmem (L2-hot).
// smem: Kb[64][72] (j, dperm), Kr same, Vs[64][72] (d, jperm), Ps[128][72].
// ---------------------------------------------------------------------------
#define CORR_SMEM ((3 * 64 * KP + 128 * KP) * 4)
__global__ void __launch_bounds__(256, 2) corr_kernel()
{
    extern __shared__ float sm[];
    float* Kb = sm;                    // [64 j][KP] big(attn[j][d]) at perm(d)
    float* Kr = Kb + 64 * KP;          // [64 j][KP] res
    float* Vs = Kr + 64 * KP;          // [64 d][KP] big at perm(j)
    float* Ps = Vs + 64 * KP;          // [128 row][KP] P/F at perm(j|m)

    const int t = threadIdx.x, lane = t & 31, warp = t >> 5;
    const int g = lane >> 2, t4 = lane & 3;
    const int rm0 = warp * 16;
    const int n0 = blockIdx.x * 128;
    const int p  = blockIdx.y;
    const float* ab = g_attn + (size_t)p * NPP * NUM;

    const int row0 = n0 + rm0 + g, row1 = row0 + 8;
    const int pp0 = perm8(2 * t4), pp1 = perm8(2 * t4 + 1);   // P-store positions

    // Q fragments -> registers (raw fp32)
    float qa[8][4];
#pragma unroll
    for (int ks = 0; ks < 8; ks++) {
        int c = ks * 8 + t4;
        qa[ks][0] = ab[(size_t)row0 * NUM + c];
        qa[ks][1] = ab[(size_t)row1 * NUM + c];
        qa[ks][2] = ab[(size_t)row0 * NUM + c + 4];
        qa[ks][3] = ab[(size_t)row1 * NUM + c + 4];
    }

    float mi[2] = {-FLT_MAX, -FLT_MAX}, li[2] = {0.0f, 0.0f};
    float o[8][4] = {};

    const int lj = t >> 2, ld0 = (t & 3) * 16;    // loader mapping
    const int lpj = perm8(lj);

    for (int jt = 0; jt < 16; jt++) {
        __syncthreads();
        // tile load: split K into big/res (perm d), V big transposed (perm j)
        {
            const float* src = ab + (size_t)(jt * 64 + lj) * NUM + ld0;
            float* kbr = Kb + lj * KP;
            float* krr = Kr + lj * KP;
#pragma unroll
            for (int u = 0; u < 4; u++) {
                float4 v = *(const float4*)(src + u * 4);
                float vv[4] = {v.x, v.y, v.z, v.w};
#pragma unroll
                for (int c2 = 0; c2 < 4; c2++) {
                    int d = ld0 + u * 4 + c2;
                    float big = t32(vv[c2]);
                    float res = t32(vv[c2] - big);
                    int pd = perm8(d);
                    kbr[pd] = big;
                    krr[pd] = res;
                    Vs[d * KP + lpj] = big;
                }
            }
        }
        __syncthreads();

        // S = Q Kt, 2-term split (3 mma passes), B frags via LDS.64 pairs
        float s[8][4] = {};
#pragma unroll
        for (int ks = 0; ks < 8; ks++) {
            float ab0 = t32(qa[ks][0]), ab1 = t32(qa[ks][1]);
            float ab2 = t32(qa[ks][2]), ab3 = t32(qa[ks][3]);
            float ar0 = t32(qa[ks][0] - ab0), ar1 = t32(qa[ks][1] - ab1);
            float ar2 = t32(qa[ks][2] - ab2), ar3 = t32(qa[ks][3] - ab3);
            unsigned ua0 = __float_as_uint(ab0), ua1 = __float_as_uint(ab1);
            unsigned ua2 = __float_as_uint(ab2), ua3 = __float_as_uint(ab3);
            unsigned ur0 = __float_as_uint(ar0), ur1 = __float_as_uint(ar1);
            unsigned ur2 = __float_as_uint(ar2), ur3 = __float_as_uint(ar3);
            int ko = ks * 8 + t4 * 2;
#pragma unroll
            for (int nj = 0; nj < 8; nj++) {
                int nrow = (nj * 8 + g) * KP + ko;
                float2 bb = *(const float2*)&Kb[nrow];
                float2 br = *(const float2*)&Kr[nrow];
                unsigned ub0 = __float_as_uint(bb.x), ub1 = __float_as_uint(bb.y);
                mma8(s[nj], ua0, ua1, ua2, ua3, ub0, ub1);
                mma8(s[nj], ua0, ua1, ua2, ua3,
                     __float_as_uint(br.x), __float_as_uint(br.y));
                mma8(s[nj], ur0, ur1, ur2, ur3, ub0, ub1);
            }
        }

        // online softmax (warp-local rows)
#pragma unroll
        for (int h = 0; h < 2; h++) {
            float rmax = -FLT_MAX;
#pragma unroll
            for (int nj = 0; nj < 8; nj++)
                rmax = fmaxf(rmax, fmaxf(s[nj][2 * h], s[nj][2 * h + 1]));
            rmax = fmaxf(rmax, __shfl_xor_sync(0xffffffffu, rmax, 1));
            rmax = fmaxf(rmax, __shfl_xor_sync(0xffffffffu, rmax, 2));
            float nm = fmaxf(mi[h], rmax);
            float sc = __expf(mi[h] - nm);
            mi[h] = nm;
            float rs = 0.0f;
#pragma unroll
            for (int nj = 0; nj < 8; nj++) {
                float v0 = __expf(s[nj][2 * h]     - nm);
                float v1 = __expf(s[nj][2 * h + 1] - nm);
                s[nj][2 * h] = v0; s[nj][2 * h + 1] = v1;
                rs += v0 + v1;
            }
            rs += __shfl_xor_sync(0xffffffffu, rs, 1);
            rs += __shfl_xor_sync(0xffffffffu, rs, 2);
            li[h] = li[h] * sc + rs;
#pragma unroll
            for (int nj = 0; nj < 8; nj++) {
                o[nj][2 * h]     *= sc;
                o[nj][2 * h + 1] *= sc;
            }
        }

        // store P (tf32) into pair-perm Ps (warp-private rows)
#pragma unroll
        for (int h = 0; h < 2; h++) {
            int rb = (rm0 + g + h * 8) * KP;
#pragma unroll
            for (int nj = 0; nj < 8; nj++) {
                Ps[rb + nj * 8 + pp0] = t32(s[nj][2 * h]);
                Ps[rb + nj * 8 + pp1] = t32(s[nj][2 * h + 1]);
            }
        }
        __syncwarp();

        // O += P @ V (A frags from Ps pairs, B frags from Vs pairs)
#pragma unroll
        for (int ks = 0; ks < 8; ks++) {
            int ko = ks * 8 + t4 * 2;
            float2 aA = *(const float2*)&Ps[(rm0 + g) * KP + ko];
            float2 aB = *(const float2*)&Ps[(rm0 + 8 + g) * KP + ko];
            unsigned a0 = __float_as_uint(aA.x), a1 = __float_as_uint(aB.x);
            unsigned a2 = __float_as_uint(aA.y), a3 = __float_as_uint(aB.y);
#pragma unroll
            for (int nj = 0; nj < 8; nj++) {
                float2 bv = *(const float2*)&Vs[(nj * 8 + g) * KP + ko];
                mma8(o[nj], a0, a1, a2, a3,
                     __float_as_uint(bv.x), __float_as_uint(bv.y));
            }
        }
    }

    // final: F = softmax(attn + O/li) per row; attn re-read from gmem
#pragma unroll
    for (int h = 0; h < 2; h++) {
        int row = (h == 0) ? row0 : row1;
        float inv = 1.0f / li[h];
        float tv[16];
#pragma unroll
        for (int nj = 0; nj < 8; nj++) {
            float2 av = *(const float2*)(ab + (size_t)row * NUM + nj * 8 + 2 * t4);
            tv[nj * 2]     = av.x + o[nj][2 * h]     * inv;
            tv[nj * 2 + 1] = av.y + o[nj][2 * h + 1] * inv;
        }
        float rmax = -FLT_MAX;
#pragma unroll
        for (int l = 0; l < 16; l++) rmax = fmaxf(rmax, tv[l]);
        rmax = fmaxf(rmax, __shfl_xor_sync(0xffffffffu, rmax, 1));
        rmax = fmaxf(rmax, __shfl_xor_sync(0xffffffffu, rmax, 2));
        float rs = 0.0f;
#pragma unroll
        for (int l = 0; l < 16; l++) { tv[l] = __expf(tv[l] - rmax); rs += tv[l]; }
        rs += __shfl_xor_sync(0xffffffffu, rs, 1);
        rs += __shfl_xor_sync(0xffffffffu, rs, 2);
        float is = 1.0f / rs;
        int rb = (rm0 + g + h * 8) * KP;
#pragma unroll
        for (int nj = 0; nj < 8; nj++) {
            Ps[rb + nj * 8 + pp0] = t32(tv[nj * 2] * is);
            Ps[rb + nj * 8 + pp1] = t32(tv[nj * 2 + 1] * is);
        }
    }

    // out = F @ vp (4 chunks of 64 channels) -> g_mid
    for (int ch = 0; ch < 4; ch++) {
        __syncthreads();
        {   // load vp chunk into Vs pair layout: Vs[c][perm(m)]
            const float* src = g_vp + (size_t)lj * HALF + ch * 64 + ld0;
#pragma unroll
            for (int u = 0; u < 4; u++) {
                float4 v = *(const float4*)(src + u * 4);
                float vv[4] = {v.x, v.y, v.z, v.w};
#pragma unroll
                for (int c2 = 0; c2 < 4; c2++)
                    Vs[(ld0 + u * 4 + c2) * KP + lpj] = t32(vv[c2]);
            }
        }
        __syncthreads();

        float acc[8][4] = {};
#pragma unroll
        for (int ks = 0; ks < 8; ks++) {
            int ko = ks * 8 + t4 * 2;
            float2 aA = *(const float2*)&Ps[(rm0 + g) * KP + ko];
            float2 aB = *(const float2*)&Ps[(rm0 + 8 + g) * KP + ko];
            unsigned a0 = __float_as_uint(aA.x), a1 = __float_as_uint(aB.x);
            unsigned a2 = __float_as_uint(aA.y), a3 = __float_as_uint(aB.y);
#pragma unroll
            for (int nj = 0; nj < 8; nj++) {
                float2 bv = *(const float2*)&Vs[(nj * 8 + g) * KP + ko];
                mma8(acc[nj], a0, a1, a2, a3,
                     __float_as_uint(bv.x), __float_as_uint(bv.y));
            }
        }
#pragma unroll
        for (int h = 0; h < 2; h++) {
            size_t pn = (size_t)p * NPP + n0 + rm0 + g + h * 8;
#pragma unroll
            for (int nj = 0; nj < 8; nj++) {
                int col = ch * 64 + nj * 8 + 2 * t4;
                *(float2*)&g_mid[pn * HALF + col] =
                    make_float2(acc[nj][2 * h], acc[nj][2 * h + 1]);
            }
        }
    }
}

// ---------------------------------------------------------------------------
// o-proj v2 (unchanged from R4)
// ---------------------------------------------------------------------------
#define OPR_SMEM ((2 * 128 * 36 + 2 * 256 * 36) * 4)
__global__ void __launch_bounds__(256, 1) oproj_kernel(
    const float* __restrict__ x, const float* __restrict__ ow,
    float* __restrict__ out)
{
    extern __shared__ float smo[];
    float* As = smo;                   // [2][128][36]
    float* Bs = smo + 2 * 128 * 36;    // [2][256][36]

    const int t = threadIdx.x, lane = t & 31, warp = t >> 5;
    const int g = lane >> 2, t4 = lane & 3;
    const int wm = (warp & 1) * 64, wn = (warp >> 1) * 64;
    const int ocr = blockIdx.x * 256;
    const int pn0 = blockIdx.y * 128;

    float acc[4][8][4] = {};

    const int a_row = t >> 3, a_c4 = (t & 7) * 4;
    const int b_oc  = t >> 3, b_c4 = (t & 7) * 4;

#define OPR_LOAD(s, k0)                                                        \
    {                                                                          \
        float* as = As + (s) * 128 * 36;                                       \
        float* bs = Bs + (s) * 256 * 36;                                       \
        _Pragma("unroll")                                                      \
        for (int i = 0; i < 4; i++)                                            \
            cpa16(as + (a_row + i * 32) * 36 + a_c4,                           \
                  g_mid + (size_t)(pn0 + a_row + i * 32) * HALF + (k0) + a_c4);\
        _Pragma("unroll")                                                      \
        for (int i = 0; i < 8; i++)                                            \
            cpa16(bs + (b_oc + i * 32) * 36 + b_c4,                            \
                  ow + (size_t)(ocr + b_oc + i * 32) * HALF + (k0) + b_c4);    \
        asm volatile("cp.async.commit_group;\n");                              \
    }

    OPR_LOAD(0, 0);
    for (int kt = 0; kt < 8; kt++) {
        int s = kt & 1;
        if (kt < 7) {
            OPR_LOAD(s ^ 1, (kt + 1) * 32);
            asm volatile("cp.async.wait_group 1;\n");
        } else {
            asm volatile("cp.async.wait_group 0;\n");
        }
        __syncthreads();
        const float* as = As + s * 128 * 36;
        const float* bs = Bs + s * 256 * 36;
#pragma unroll
        for (int kk = 0; kk < 32; kk += 8) {
            unsigned a[4][4], b[8][2];
#pragma unroll
            for (int mi = 0; mi < 4; mi++) {
                int mb = wm + mi * 16 + g;
                a[mi][0] = __float_as_uint(as[mb * 36 + kk + t4]);
                a[mi][1] = __float_as_uint(as[(mb + 8) * 36 + kk + t4]);
                a[mi][2] = __float_as_uint(as[mb * 36 + kk + t4 + 4]);
                a[mi][3] = __float_as_uint(as[(mb + 8) * 36 + kk + t4 + 4]);
            }
#pragma unroll
            for (int nj = 0; nj < 8; nj++) {
                int nb = wn + nj * 8 + g;
                b[nj][0] = __float_as_uint(bs[nb * 36 + kk + t4]);
                b[nj][1] = __float_as_uint(bs[nb * 36 + kk + t4 + 4]);
            }
#pragma unroll
            for (int mi = 0; mi < 4; mi++)
#pragma unroll
                for (int nj = 0; nj < 8; nj++)
                    mma8(acc[mi][nj], a[mi][0], a[mi][1], a[mi][2], a[mi][3],
                         b[nj][0], b[nj][1]);
        }
        __syncthreads();
    }
#undef OPR_LOAD

#pragma unroll
    for (int mi = 0; mi < 4; mi++)
#pragma unroll
        for (int h2 = 0; h2 < 2; h2++) {
            int pn = pn0 + wm + mi * 16 + g + h2 * 8;
            int p = pn >> 10, n = pn & 1023;
            int h = ((p >> 3) << 5) + (n >> 5);
            int w = ((p & 7) << 5) + (n & 31);
            int base = h * W_IMG + w;
#pragma unroll
            for (int nj = 0; nj < 8; nj++) {
                int oc = ocr + wn + nj * 8 + t4 * 2;
                float s0 = g_pscale[768 + oc],     b0 = g_pbias[768 + oc];
                float s1 = g_pscale[768 + oc + 1], b1 = g_pbias[768 + oc + 1];
                size_t i0 = (size_t)oc * HW + base;
                size_t i1 = i0 + HW;
                out[i0] = fmaxf(fmaf(acc[mi][nj][h2 * 2],     s0, b0), 0.0f) + x[i0];
                out[i1] = fmaxf(fmaf(acc[mi][nj][h2 * 2 + 1], s1, b1), 0.0f) + x[i1];
            }
        }
}

// ---------------------------------------------------------------------------
extern "C" void kernel_launch(void* const* d_in, const int* in_sizes, int n_in,
                              void* d_out, int out_size)
{
    (void)in_sizes; (void)n_in; (void)out_size;
    const float* x  = (const float*)d_in[0];
    const float* qw = (const float*)d_in[1];
    const float* kw = (const float*)d_in[6];
    const float* vw = (const float*)d_in[11];
    const float* ow = (const float*)d_in[16];

    cudaFuncSetAttribute(corr_kernel,
                         cudaFuncAttributeMaxDynamicSharedMemorySize, CORR_SMEM);
    cudaFuncSetAttribute(qkv_kernel,
                         cudaFuncAttributeMaxDynamicSharedMemorySize, QKV_SMEM);
    cudaFuncSetAttribute(oproj_kernel,
                         cudaFuncAttributeMaxDynamicSharedMemorySize, OPR_SMEM);

    prep_kernel<<<134, 256>>>(
        (const float*)d_in[2],  (const float*)d_in[3],  (const float*)d_in[4],  (const float*)d_in[5],
        (const float*)d_in[7],  (const float*)d_in[8],  (const float*)d_in[9],  (const float*)d_in[10],
        (const float*)d_in[12], (const float*)d_in[13], (const float*)d_in[14], (const float*)d_in[15],
        (const float*)d_in[17], (const float*)d_in[18], (const float*)d_in[19], (const float*)d_in[20]);

    qkv_kernel<<<dim3(3, 512), 256, QKV_SMEM>>>(x, qw, kw, vw);
    attnqk_kernel<<<512, 256>>>();
    corr_kernel<<<dim3(8, 64), 256, CORR_SMEM>>>();
    oproj_kernel<<<dim3(2, 512), 256, OPR_SMEM>>>(x, ow, (float*)d_out);
}

// round 6
// speedup vs baseline: 4.0486x; 1.1656x over previous
#include <cuda_runtime.h>
#include <cuda_bf16.h>
#include <math.h>
#include <float.h>

#define HW    65536
#define CIN   512
#define HALF  256
#define NUM   64
#define NPP   1024
#define W_IMG 256
#define KP    72     // Ps pitch (floats)
#define KBP   40     // Kb/Kr pitch (u32)
#define VTP   72     // Vt pitch (floats)

// scratch (device globals: allocation-free rule)
__device__ float    g_q[NUM * NPP * HALF];    // (pn, ch) q, scaled
__device__ float    g_kp[HALF * NUM];         // (ch, patch) pooled k
__device__ float    g_vp[NUM * HALF];         // (patch, ch) pooled v
__device__ float    g_attn[NUM * NPP * NUM];  // (pn, m) raw fp32
__device__ unsigned g_ab32[NUM * NPP * 32];   // attn bf16-big, pair-packed+permuted
__device__ unsigned g_ar32[NUM * NPP * 32];   // attn bf16-res, pair-packed+permuted
__device__ float    g_av[NUM * NPP * NUM];    // attn rna-tf32 (V operand)
__device__ float    g_mid[NUM * NPP * HALF];  // (pn, ch) attention output
__device__ float    g_pscale[1280];
__device__ float    g_pbias[1280];

// ---------------------------------------------------------------------------
__device__ __forceinline__ float t32(float x) {
    asm("cvt.rna.tf32.f32 %0, %0;" : "+f"(x));
    return x;
}
__device__ __forceinline__ void mma8(float* d,
    unsigned a0, unsigned a1, unsigned a2, unsigned a3,
    unsigned b0, unsigned b1)
{
    asm volatile(
        "mma.sync.aligned.m16n8k8.row.col.f32.tf32.tf32.f32 "
        "{%0,%1,%2,%3},{%4,%5,%6,%7},{%8,%9},{%0,%1,%2,%3};"
        : "+f"(d[0]), "+f"(d[1]), "+f"(d[2]), "+f"(d[3])
        : "r"(a0), "r"(a1), "r"(a2), "r"(a3), "r"(b0), "r"(b1));
}
__device__ __forceinline__ void mmabf(float* d,
    unsigned a0, unsigned a1, unsigned a2, unsigned a3,
    unsigned b0, unsigned b1)
{
    asm volatile(
        "mma.sync.aligned.m16n8k16.row.col.f32.bf16.bf16.f32 "
        "{%0,%1,%2,%3},{%4,%5,%6,%7},{%8,%9},{%0,%1,%2,%3};"
        : "+f"(d[0]), "+f"(d[1]), "+f"(d[2]), "+f"(d[3])
        : "r"(a0), "r"(a1), "r"(a2), "r"(a3), "r"(b0), "r"(b1));
}
__device__ __forceinline__ void cpa16(void* smem_dst, const void* gsrc) {
    unsigned s = (unsigned)__cvta_generic_to_shared(smem_dst);
    asm volatile("cp.async.cg.shared.global [%0], [%1], 16;\n" :: "r"(s), "l"(gsrc));
}
__device__ __forceinline__ int perm8(int k) {
    return (k & ~7) + ((k & 3) * 2) + ((k >> 2) & 1);
}

// ---------------------------------------------------------------------------
// prep (unchanged)
// ---------------------------------------------------------------------------
__global__ void prep_kernel(
    const float* qg, const float* qb, const float* qm, const float* qv,
    const float* kg, const float* kb, const float* km, const float* kv,
    const float* vg, const float* vb, const float* vm, const float* vv,
    const float* og, const float* ob, const float* om, const float* ov)
{
    int i = blockIdx.x * blockDim.x + threadIdx.x;
    if (i < 1280) {
        const float *G, *B, *M, *V; float f; int r;
        if (i < 256)      { G = qg; B = qb; M = qm; V = qv; f = 0.044194173824159216f; r = i; }
        else if (i < 512) { G = kg; B = kb; M = km; V = kv; f = 1.0f / 1024.0f;        r = i - 256; }
        else if (i < 768) { G = vg; B = vb; M = vm; V = vv; f = 1.0f / 1024.0f;        r = i - 512; }
        else              { G = og; B = ob; M = om; V = ov; f = 1.0f;                  r = i - 768; }
        float s = G[r] * rsqrtf(V[r] + 1e-5f);
        g_pscale[i] = s * f;
        g_pbias[i]  = (B[r] - M[r] * s) * f;
    }
    int z = i - 1280;
    if (z >= 0 && z < HALF * NUM) g_kp[z] = 0.0f;
    z -= HALF * NUM;
    if (z >= 0 && z < NUM * HALF) g_vp[z] = 0.0f;
}

// ---------------------------------------------------------------------------
// QKV v2 (unchanged from R4)
// ---------------------------------------------------------------------------
#define QKV_SMEM ((2 * 32 * 136 + 2 * 256 * 36) * 4)
__global__ void __launch_bounds__(256, 1) qkv_kernel(
    const float* __restrict__ x, const float* __restrict__ qw,
    const float* __restrict__ kw, const float* __restrict__ vw)
{
    extern __shared__ float smq[];
    float* As = smq;
    float* Bs = smq + 2 * 32 * 136;

    const int t = threadIdx.x, lane = t & 31, warp = t >> 5;
    const int g = lane >> 2, t4 = lane & 3;
    const int wm = (warp & 1) * 64, wn = (warp >> 1) * 64;
    const int gx = blockIdx.x;
    const int pix0 = blockIdx.y * 128;
    const float* Wp = (gx == 0) ? qw : (gx == 1) ? kw : vw;

    float acc[4][8][4] = {};

    const int a_row = t >> 5, a_c4 = (t & 31) * 4;
    const int b_oc  = t >> 3, b_c4 = (t & 7) * 4;

#define QKV_LOAD(s, k0)                                                        \
    {                                                                          \
        float* as = As + (s) * 32 * 136;                                       \
        float* bs = Bs + (s) * 256 * 36;                                       \
        _Pragma("unroll")                                                      \
        for (int i = 0; i < 4; i++)                                            \
            cpa16(as + (a_row + i * 8) * 136 + a_c4,                           \
                  x + (size_t)((k0) + a_row + i * 8) * HW + pix0 + a_c4);      \
        _Pragma("unroll")                                                      \
        for (int i = 0; i < 8; i++)                                            \
            cpa16(bs + (b_oc + i * 32) * 36 + b_c4,                            \
                  Wp + (size_t)(b_oc + i * 32) * CIN + (k0) + b_c4);           \
        asm volatile("cp.async.commit_group;\n");                              \
    }

    QKV_LOAD(0, 0);
    for (int kt = 0; kt < 16; kt++) {
        int s = kt & 1;
        if (kt < 15) {
            QKV_LOAD(s ^ 1, (kt + 1) * 32);
            asm volatile("cp.async.wait_group 1;\n");
        } else {
            asm volatile("cp.async.wait_group 0;\n");
        }
        __syncthreads();
        const float* as = As + s * 32 * 136;
        const float* bs = Bs + s * 256 * 36;
#pragma unroll
        for (int kk = 0; kk < 32; kk += 8) {
            unsigned a[4][4], b[8][2];
#pragma unroll
            for (int mi = 0; mi < 4; mi++) {
                int mb = wm + mi * 16 + g;
                a[mi][0] = __float_as_uint(as[(kk + t4) * 136 + mb]);
                a[mi][1] = __float_as_uint(as[(kk + t4) * 136 + mb + 8]);
                a[mi][2] = __float_as_uint(as[(kk + t4 + 4) * 136 + mb]);
                a[mi][3] = __float_as_uint(as[(kk + t4 + 4) * 136 + mb + 8]);
            }
#pragma unroll
            for (int nj = 0; nj < 8; nj++) {
                int nb = wn + nj * 8 + g;
                b[nj][0] = __float_as_uint(bs[nb * 36 + kk + t4]);
                b[nj][1] = __float_as_uint(bs[nb * 36 + kk + t4 + 4]);
            }
#pragma unroll
            for (int mi = 0; mi < 4; mi++)
#pragma unroll
                for (int nj = 0; nj < 8; nj++)
                    mma8(acc[mi][nj], a[mi][0], a[mi][1], a[mi][2], a[mi][3],
                         b[nj][0], b[nj][1]);
        }
        __syncthreads();
    }
#undef QKV_LOAD

    if (gx == 0) {
#pragma unroll
        for (int mi = 0; mi < 4; mi++)
#pragma unroll
            for (int h2 = 0; h2 < 2; h2++) {
                int pix = pix0 + wm + mi * 16 + g + h2 * 8;
                int h = pix >> 8, w = pix & 255;
                int pn = (((h >> 5) << 3) + (w >> 5)) * NPP + ((h & 31) << 5) + (w & 31);
#pragma unroll
                for (int nj = 0; nj < 8; nj++) {
                    int col = wn + nj * 8 + t4 * 2;
                    float v0 = fmaxf(fmaf(acc[mi][nj][h2 * 2],     g_pscale[col],     g_pbias[col]),     0.0f);
                    float v1 = fmaxf(fmaf(acc[mi][nj][h2 * 2 + 1], g_pscale[col + 1], g_pbias[col + 1]), 0.0f);
                    *(float2*)&g_q[(size_t)pn * HALF + col] = make_float2(v0, v1);
                }
            }
    } else {
        float part[2][8][2] = {};
#pragma unroll
        for (int mi = 0; mi < 4; mi++) {
            int pl = mi >> 1;
#pragma unroll
            for (int nj = 0; nj < 8; nj++) {
                int col = wn + nj * 8 + t4 * 2;
                float s0 = g_pscale[gx * 256 + col],     b0 = g_pbias[gx * 256 + col];
                float s1 = g_pscale[gx * 256 + col + 1], b1 = g_pbias[gx * 256 + col + 1];
#pragma unroll
                for (int h2 = 0; h2 < 2; h2++) {
                    part[pl][nj][0] += fmaxf(fmaf(acc[mi][nj][h2 * 2],     s0, b0), 0.0f);
                    part[pl][nj][1] += fmaxf(fmaf(acc[mi][nj][h2 * 2 + 1], s1, b1), 0.0f);
                }
            }
        }
#pragma unroll
        for (int m_ = 4; m_ <= 16; m_ <<= 1)
#pragma unroll
            for (int pl = 0; pl < 2; pl++)
#pragma unroll
                for (int nj = 0; nj < 8; nj++) {
                    part[pl][nj][0] += __shfl_xor_sync(0xffffffffu, part[pl][nj][0], m_);
                    part[pl][nj][1] += __shfl_xor_sync(0xffffffffu, part[pl][nj][1], m_);
                }
        if (g == 0) {
            int h0 = pix0 >> 8, w0 = pix0 & 255;
            int pbase = ((h0 >> 5) << 3) + (w0 >> 5);
#pragma unroll
            for (int pl = 0; pl < 2; pl++) {
                int p = pbase + (wm >> 5) + pl;
#pragma unroll
                for (int nj = 0; nj < 8; nj++) {
                    int col = wn + nj * 8 + t4 * 2;
                    if (gx == 1) {
                        atomicAdd(&g_kp[col * NUM + p],       part[pl][nj][0]);
                        atomicAdd(&g_kp[(col + 1) * NUM + p], part[pl][nj][1]);
                    } else {
                        atomicAdd(&g_vp[p * HALF + col],     part[pl][nj][0]);
                        atomicAdd(&g_vp[p * HALF + col + 1], part[pl][nj][1]);
                    }
                }
            }
        }
    }
}

// ---------------------------------------------------------------------------
// attnqk: mma GEMM + epilogue now ALSO writes bf16 big/res (packed, permuted)
// and rna-tf32 copy for corr's async tile loads.
// ---------------------------------------------------------------------------
__global__ void __launch_bounds__(256) attnqk_kernel()
{
    __shared__ float As[32][132];
    __shared__ float Bs[32][68];

    const int t = threadIdx.x, lane = t & 31, warp = t >> 5;
    const int wm = (warp & 3) * 32, wn = (warp >> 2) * 32;
    const int g = lane >> 2, t4 = lane & 3;
    const int pn0 = blockIdx.x * 128;

    float acc[2][4][4] = {};

    const int am2 = t & 127, ac = (t >> 7) * 16;
    const int bn4 = (t & 15) * 4, bk2 = t >> 4;

    for (int k0 = 0; k0 < HALF; k0 += 32) {
#pragma unroll
        for (int u = 0; u < 4; u++) {
            float4 v = *(const float4*)(g_q + (size_t)(pn0 + am2) * HALF + k0 + ac + u * 4);
            As[ac + u * 4][am2]     = v.x;
            As[ac + u * 4 + 1][am2] = v.y;
            As[ac + u * 4 + 2][am2] = v.z;
            As[ac + u * 4 + 3][am2] = v.w;
        }
#pragma unroll
        for (int u = 0; u < 2; u++) {
            int kr = bk2 + u * 16;
            float4 v = *(const float4*)(g_kp + (size_t)(k0 + kr) * NUM + bn4);
            Bs[kr][bn4]     = v.x;
            Bs[kr][bn4 + 1] = v.y;
            Bs[kr][bn4 + 2] = v.z;
            Bs[kr][bn4 + 3] = v.w;
        }
        __syncthreads();
#pragma unroll
        for (int kk = 0; kk < 32; kk += 8) {
            unsigned a[2][4], b[4][2];
#pragma unroll
            for (int mi = 0; mi < 2; mi++) {
                int mb = wm + mi * 16 + g;
                a[mi][0] = __float_as_uint(As[kk + t4][mb]);
                a[mi][1] = __float_as_uint(As[kk + t4][mb + 8]);
                a[mi][2] = __float_as_uint(As[kk + t4 + 4][mb]);
                a[mi][3] = __float_as_uint(As[kk + t4 + 4][mb + 8]);
            }
#pragma unroll
            for (int nj = 0; nj < 4; nj++) {
                int nb = wn + nj * 8 + g;
                b[nj][0] = __float_as_uint(Bs[kk + t4][nb]);
                b[nj][1] = __float_as_uint(Bs[kk + t4 + 4][nb]);
            }
#pragma unroll
            for (int mi = 0; mi < 2; mi++)
#pragma unroll
                for (int nj = 0; nj < 4; nj++)
                    mma8(acc[mi][nj], a[mi][0], a[mi][1], a[mi][2], a[mi][3],
                         b[nj][0], b[nj][1]);
        }
        __syncthreads();
    }

#pragma unroll
    for (int mi = 0; mi < 2; mi++)
#pragma unroll
        for (int h2 = 0; h2 < 2; h2++) {
            int row = pn0 + wm + mi * 16 + g + h2 * 8;
#pragma unroll
            for (int nj = 0; nj < 4; nj++) {
                int col = wn + nj * 8 + t4 * 2;
                float v0 = acc[mi][nj][h2 * 2], v1 = acc[mi][nj][h2 * 2 + 1];
                *(float2*)&g_attn[(size_t)row * NUM + col] = make_float2(v0, v1);
                *(float2*)&g_av[(size_t)row * NUM + col]   = make_float2(t32(v0), t32(v1));
                // bf16 split, packed pairs, stored at permuted pair position
                __nv_bfloat16 b0 = __float2bfloat16_rn(v0);
                __nv_bfloat16 b1 = __float2bfloat16_rn(v1);
                float r0 = v0 - __bfloat162float(b0);
                float r1 = v1 - __bfloat162float(b1);
                __nv_bfloat16 c0 = __float2bfloat16_rn(r0);
                __nv_bfloat16 c1 = __float2bfloat16_rn(r1);
                unsigned pb = (unsigned)__bfloat16_as_ushort(b0) |
                              ((unsigned)__bfloat16_as_ushort(b1) << 16);
                unsigned pr = (unsigned)__bfloat16_as_ushort(c0) |
                              ((unsigned)__bfloat16_as_ushort(c1) << 16);
                int P = col >> 1;
                int permP = (P & ~7) | ((P & 3) << 1) | ((P >> 2) & 1);
                g_ab32[(size_t)row * 32 + permP] = pb;
                g_ar32[(size_t)row * 32 + permP] = pr;
            }
        }
}

// ---------------------------------------------------------------------------
// corr v4: double-buffered cp.async tiles (pre-split bf16 big/res + tf32 V),
// S via 3-pass bf16 m16n8k16 (half the S mma count), PV in tf32. Q big/res
// fragments preloaded to registers from gmem (pre-permuted, so plain LDG.64).
// ---------------------------------------------------------------------------
#define CORR_SMEM ((4 * 64 * KBP + 2 * 64 * VTP + 128 * KP) * 4)
__global__ void __launch_bounds__(256, 2) corr_kernel()
{
    extern __shared__ float sm[];
    unsigned* KbA = (unsigned*)sm;           // [2][64][KBP] bf16-big pairs
    unsigned* KrA = KbA + 2 * 64 * KBP;      // [2][64][KBP] bf16-res pairs
    float*    VtA = (float*)(KrA + 2 * 64 * KBP);  // [2][64][VTP] tf32 V
    float*    Ps  = VtA + 2 * 64 * VTP;      // [128][KP]

    const int t = threadIdx.x, lane = t & 31, warp = t >> 5;
    const int g = lane >> 2, t4 = lane & 3;
    const int rm0 = warp * 16;
    const int n0 = blockIdx.x * 128;
    const int p  = blockIdx.y;
    const float*    ab   = g_attn + (size_t)p * NPP * NUM;
    const unsigned* abig = g_ab32 + (size_t)p * NPP * 32;
    const unsigned* ares = g_ar32 + (size_t)p * NPP * 32;
    const float*    av   = g_av   + (size_t)p * NPP * NUM;

    const int row0 = n0 + rm0 + g, row1 = row0 + 8;
    const int pp0 = perm8(2 * t4), pp1 = perm8(2 * t4 + 1);

    // Q fragments (bf16 big/res, packed pairs) -> registers
    unsigned qb[4][4], qr[4][4];
#pragma unroll
    for (int c = 0; c < 4; c++) {
        int base = 8 * c + 2 * t4;
        uint2 v0 = *(const uint2*)&abig[(size_t)row0 * 32 + base];
        uint2 v1 = *(const uint2*)&abig[(size_t)row1 * 32 + base];
        qb[c][0] = v0.x; qb[c][2] = v0.y;
        qb[c][1] = v1.x; qb[c][3] = v1.y;
        uint2 w0 = *(const uint2*)&ares[(size_t)row0 * 32 + base];
        uint2 w1 = *(const uint2*)&ares[(size_t)row1 * 32 + base];
        qr[c][0] = w0.x; qr[c][2] = w0.y;
        qr[c][1] = w1.x; qr[c][3] = w1.y;
    }

    const int kr8 = t >> 3, ko8 = t & 7;     // K loads: 2 rows each
    const int vrow = t >> 2, vo16 = (t & 3); // V loads: 4 segs each

#define CORR_LOAD(s, jt)                                                       \
    {                                                                          \
        unsigned* kb = KbA + (s) * 64 * KBP;                                   \
        unsigned* kr = KrA + (s) * 64 * KBP;                                   \
        float*    vt = VtA + (s) * 64 * VTP;                                   \
        _Pragma("unroll")                                                      \
        for (int i = 0; i < 2; i++) {                                          \
            int r = kr8 + i * 32;                                              \
            cpa16(kb + r * KBP + ko8 * 4, abig + ((size_t)(jt) * 64 + r) * 32 + ko8 * 4); \
            cpa16(kr + r * KBP + ko8 * 4, ares + ((size_t)(jt) * 64 + r) * 32 + ko8 * 4); \
        }                                                                      \
        _Pragma("unroll")                                                      \
        for (int i = 0; i < 4; i++) {                                          \
            int o = vo16 * 4 + i;                                              \
            cpa16(vt + vrow * VTP + o * 4, av + ((size_t)(jt) * 64 + vrow) * 64 + o * 4); \
        }                                                                      \
        asm volatile("cp.async.commit_group;\n");                              \
    }

    float mi[2] = {-FLT_MAX, -FLT_MAX}, li[2] = {0.0f, 0.0f};
    float o[8][4] = {};

    CORR_LOAD(0, 0);
    for (int jt = 0; jt < 16; jt++) {
        int s = jt & 1;
        if (jt < 15) {
            CORR_LOAD(s ^ 1, jt + 1);
            asm volatile("cp.async.wait_group 1;\n");
        } else {
            asm volatile("cp.async.wait_group 0;\n");
        }
        __syncthreads();
        const unsigned* kb = KbA + s * 64 * KBP;
        const unsigned* kr = KrA + s * 64 * KBP;
        const float*    vt = VtA + s * 64 * VTP;

        // S = Q Kt via 3-pass bf16 split
        float sa[8][4] = {};
#pragma unroll
        for (int c = 0; c < 4; c++) {
            int ko = c * 8 + 2 * t4;
#pragma unroll
            for (int nj = 0; nj < 8; nj++) {
                int rb = (nj * 8 + g) * KBP + ko;
                uint2 bb = *(const uint2*)&kb[rb];
                uint2 br = *(const uint2*)&kr[rb];
                mmabf(sa[nj], qb[c][0], qb[c][1], qb[c][2], qb[c][3], bb.x, bb.y);
                mmabf(sa[nj], qb[c][0], qb[c][1], qb[c][2], qb[c][3], br.x, br.y);
                mmabf(sa[nj], qr[c][0], qr[c][1], qr[c][2], qr[c][3], bb.x, bb.y);
            }
        }

        // online softmax (warp-local rows)
#pragma unroll
        for (int h = 0; h < 2; h++) {
            float rmax = -FLT_MAX;
#pragma unroll
            for (int nj = 0; nj < 8; nj++)
                rmax = fmaxf(rmax, fmaxf(sa[nj][2 * h], sa[nj][2 * h + 1]));
            rmax = fmaxf(rmax, __shfl_xor_sync(0xffffffffu, rmax, 1));
            rmax = fmaxf(rmax, __shfl_xor_sync(0xffffffffu, rmax, 2));
            float nm = fmaxf(mi[h], rmax);
            float sc = __expf(mi[h] - nm);
            mi[h] = nm;
            float rs = 0.0f;
#pragma unroll
            for (int nj = 0; nj < 8; nj++) {
                float v0 = __expf(sa[nj][2 * h]     - nm);
                float v1 = __expf(sa[nj][2 * h + 1] - nm);
                sa[nj][2 * h] = v0; sa[nj][2 * h + 1] = v1;
                rs += v0 + v1;
            }
            rs += __shfl_xor_sync(0xffffffffu, rs, 1);
            rs += __shfl_xor_sync(0xffffffffu, rs, 2);
            li[h] = li[h] * sc + rs;
#pragma unroll
            for (int nj = 0; nj < 8; nj++) {
                o[nj][2 * h]     *= sc;
                o[nj][2 * h + 1] *= sc;
            }
        }

        // store P (tf32) into pair-perm Ps (warp-private rows)
#pragma unroll
        for (int h = 0; h < 2; h++) {
            int rb = (rm0 + g + h * 8) * KP;
#pragma unroll
            for (int nj = 0; nj < 8; nj++) {
                Ps[rb + nj * 8 + pp0] = t32(sa[nj][2 * h]);
                Ps[rb + nj * 8 + pp1] = t32(sa[nj][2 * h + 1]);
            }
        }
        __syncwarp();

        // O += P @ V (tf32; V natural layout [j][VTP])
#pragma unroll
        for (int ks = 0; ks < 8; ks++) {
            int ko = ks * 8 + t4 * 2;
            float2 aA = *(const float2*)&Ps[(rm0 + g) * KP + ko];
            float2 aB = *(const float2*)&Ps[(rm0 + 8 + g) * KP + ko];
            unsigned a0 = __float_as_uint(aA.x), a1 = __float_as_uint(aB.x);
            unsigned a2 = __float_as_uint(aA.y), a3 = __float_as_uint(aB.y);
#pragma unroll
            for (int nj = 0; nj < 8; nj++) {
                unsigned b0 = __float_as_uint(vt[(ks * 8 + t4) * VTP + nj * 8 + g]);
                unsigned b1 = __float_as_uint(vt[(ks * 8 + t4 + 4) * VTP + nj * 8 + g]);
                mma8(o[nj], a0, a1, a2, a3, b0, b1);
            }
        }
        __syncthreads();
    }
#undef CORR_LOAD

    // final: F = softmax(attn + O/li) per row; attn re-read from gmem
#pragma unroll
    for (int h = 0; h < 2; h++) {
        int row = (h == 0) ? row0 : row1;
        float inv = 1.0f / li[h];
        float tv[16];
#pragma unroll
        for (int nj = 0; nj < 8; nj++) {
            float2 avv = *(const float2*)(ab + (size_t)row * NUM + nj * 8 + 2 * t4);
            tv[nj * 2]     = avv.x + o[nj][2 * h]     * inv;
            tv[nj * 2 + 1] = avv.y + o[nj][2 * h + 1] * inv;
        }
        float rmax = -FLT_MAX;
#pragma unroll
        for (int l = 0; l < 16; l++) rmax = fmaxf(rmax, tv[l]);
        rmax = fmaxf(rmax, __shfl_xor_sync(0xffffffffu, rmax, 1));
        rmax = fmaxf(rmax, __shfl_xor_sync(0xffffffffu, rmax, 2));
        float rs = 0.0f;
#pragma unroll
        for (int l = 0; l < 16; l++) { tv[l] = __expf(tv[l] - rmax); rs += tv[l]; }
        rs += __shfl_xor_sync(0xffffffffu, rs, 1);
        rs += __shfl_xor_sync(0xffffffffu, rs, 2);
        float is = 1.0f / rs;
        int rb = (rm0 + g + h * 8) * KP;
#pragma unroll
        for (int nj = 0; nj < 8; nj++) {
            Ps[rb + nj * 8 + pp0] = t32(tv[nj * 2] * is);
            Ps[rb + nj * 8 + pp1] = t32(tv[nj * 2 + 1] * is);
        }
    }

    // out = F @ vp (4 chunks of 64 channels) -> g_mid; Vs scratch = VtA buf 0
    float* Vs = VtA;
    const int lj = t >> 2, ld0 = (t & 3) * 16;
    const int lpj = perm8(lj);
    for (int ch = 0; ch < 4; ch++) {
        __syncthreads();
        {
            const float* src = g_vp + (size_t)lj * HALF + ch * 64 + ld0;
#pragma unroll
            for (int u = 0; u < 4; u++) {
                float4 v = *(const float4*)(src + u * 4);
                float vv[4] = {v.x, v.y, v.z, v.w};
#pragma unroll
                for (int c2 = 0; c2 < 4; c2++)
                    Vs[(ld0 + u * 4 + c2) * VTP + lpj] = t32(vv[c2]);
            }
        }
        __syncthreads();

        float acc[8][4] = {};
#pragma unroll
        for (int ks = 0; ks < 8; ks++) {
            int ko = ks * 8 + t4 * 2;
            float2 aA = *(const float2*)&Ps[(rm0 + g) * KP + ko];
            float2 aB = *(const float2*)&Ps[(rm0 + 8 + g) * KP + ko];
            unsigned a0 = __float_as_uint(aA.x), a1 = __float_as_uint(aB.x);
            unsigned a2 = __float_as_uint(aA.y), a3 = __float_as_uint(aB.y);
#pragma unroll
            for (int nj = 0; nj < 8; nj++) {
                float2 bv = *(const float2*)&Vs[(nj * 8 + g) * VTP + ks * 8 + 2 * t4];
                mma8(acc[nj], a0, a1, a2, a3,
                     __float_as_uint(bv.x), __float_as_uint(bv.y));
            }
        }
#pragma unroll
        for (int h = 0; h < 2; h++) {
            size_t pn = (size_t)p * NPP + n0 + rm0 + g + h * 8;
#pragma unroll
            for (int nj = 0; nj < 8; nj++) {
                int col = ch * 64 + nj * 8 + 2 * t4;
                *(float2*)&g_mid[pn * HALF + col] =
                    make_float2(acc[nj][2 * h], acc[nj][2 * h + 1]);
            }
        }
    }
}

// ---------------------------------------------------------------------------
// o-proj v2 (unchanged from R4)
// ---------------------------------------------------------------------------
#define OPR_SMEM ((2 * 128 * 36 + 2 * 256 * 36) * 4)
__global__ void __launch_bounds__(256, 1) oproj_kernel(
    const float* __restrict__ x, const float* __restrict__ ow,
    float* __restrict__ out)
{
    extern __shared__ float smo[];
    float* As = smo;
    float* Bs = smo + 2 * 128 * 36;

    const int t = threadIdx.x, lane = t & 31, warp = t >> 5;
    const int g = lane >> 2, t4 = lane & 3;
    const int wm = (warp & 1) * 64, wn = (warp >> 1) * 64;
    const int ocr = blockIdx.x * 256;
    const int pn0 = blockIdx.y * 128;

    float acc[4][8][4] = {};

    const int a_row = t >> 3, a_c4 = (t & 7) * 4;
    const int b_oc  = t >> 3, b_c4 = (t & 7) * 4;

#define OPR_LOAD(s, k0)                                                        \
    {                                                                          \
        float* as = As + (s) * 128 * 36;                                       \
        float* bs = Bs + (s) * 256 * 36;                                       \
        _Pragma("unroll")                                                      \
        for (int i = 0; i < 4; i++)                                            \
            cpa16(as + (a_row + i * 32) * 36 + a_c4,                           \
                  g_mid + (size_t)(pn0 + a_row + i * 32) * HALF + (k0) + a_c4);\
        _Pragma("unroll")                                                      \
        for (int i = 0; i < 8; i++)                                            \
            cpa16(bs + (b_oc + i * 32) * 36 + b_c4,                            \
                  ow + (size_t)(ocr + b_oc + i * 32) * HALF + (k0) + b_c4);    \
        asm volatile("cp.async.commit_group;\n");                              \
    }

    OPR_LOAD(0, 0);
    for (int kt = 0; kt < 8; kt++) {
        int s = kt & 1;
        if (kt < 7) {
            OPR_LOAD(s ^ 1, (kt + 1) * 32);
            asm volatile("cp.async.wait_group 1;\n");
        } else {
            asm volatile("cp.async.wait_group 0;\n");
        }
        __syncthreads();
        const float* as = As + s * 128 * 36;
        const float* bs = Bs + s * 256 * 36;
#pragma unroll
        for (int kk = 0; kk < 32; kk += 8) {
            unsigned a[4][4], b[8][2];
#pragma unroll
            for (int mi = 0; mi < 4; mi++) {
                int mb = wm + mi * 16 + g;
                a[mi][0] = __float_as_uint(as[mb * 36 + kk + t4]);
                a[mi][1] = __float_as_uint(as[(mb + 8) * 36 + kk + t4]);
                a[mi][2] = __float_as_uint(as[mb * 36 + kk + t4 + 4]);
                a[mi][3] = __float_as_uint(as[(mb + 8) * 36 + kk + t4 + 4]);
            }
#pragma unroll
            for (int nj = 0; nj < 8; nj++) {
                int nb = wn + nj * 8 + g;
                b[nj][0] = __float_as_uint(bs[nb * 36 + kk + t4]);
                b[nj][1] = __float_as_uint(bs[nb * 36 + kk + t4 + 4]);
            }
#pragma unroll
            for (int mi = 0; mi < 4; mi++)
#pragma unroll
                for (int nj = 0; nj < 8; nj++)
                    mma8(acc[mi][nj], a[mi][0], a[mi][1], a[mi][2], a[mi][3],
                         b[nj][0], b[nj][1]);
        }
        __syncthreads();
    }
#undef OPR_LOAD

#pragma unroll
    for (int mi = 0; mi < 4; mi++)
#pragma unroll
        for (int h2 = 0; h2 < 2; h2++) {
            int pn = pn0 + wm + mi * 16 + g + h2 * 8;
            int p = pn >> 10, n = pn & 1023;
            int h = ((p >> 3) << 5) + (n >> 5);
            int w = ((p & 7) << 5) + (n & 31);
            int base = h * W_IMG + w;
#pragma unroll
            for (int nj = 0; nj < 8; nj++) {
                int oc = ocr + wn + nj * 8 + t4 * 2;
                float s0 = g_pscale[768 + oc],     b0 = g_pbias[768 + oc];
                float s1 = g_pscale[768 + oc + 1], b1 = g_pbias[768 + oc + 1];
                size_t i0 = (size_t)oc * HW + base;
                size_t i1 = i0 + HW;
                out[i0] = fmaxf(fmaf(acc[mi][nj][h2 * 2],     s0, b0), 0.0f) + x[i0];
                out[i1] = fmaxf(fmaf(acc[mi][nj][h2 * 2 + 1], s1, b1), 0.0f) + x[i1];
            }
        }
}

// ---------------------------------------------------------------------------
extern "C" void kernel_launch(void* const* d_in, const int* in_sizes, int n_in,
                              void* d_out, int out_size)
{
    (void)in_sizes; (void)n_in; (void)out_size;
    const float* x  = (const float*)d_in[0];
    const float* qw = (const float*)d_in[1];
    const float* kw = (const float*)d_in[6];
    const float* vw = (const float*)d_in[11];
    const float* ow = (const float*)d_in[16];

    cudaFuncSetAttribute(corr_kernel,
                         cudaFuncAttributeMaxDynamicSharedMemorySize, CORR_SMEM);
    cudaFuncSetAttribute(qkv_kernel,
                         cudaFuncAttributeMaxDynamicSharedMemorySize, QKV_SMEM);
    cudaFuncSetAttribute(oproj_kernel,
                         cudaFuncAttributeMaxDynamicSharedMemorySize, OPR_SMEM);

    prep_kernel<<<134, 256>>>(
        (const float*)d_in[2],  (const float*)d_in[3],  (const float*)d_in[4],  (const float*)d_in[5],
        (const float*)d_in[7],  (const float*)d_in[8],  (const float*)d_in[9],  (const float*)d_in[10],
        (const float*)d_in[12], (const float*)d_in[13], (const float*)d_in[14], (const float*)d_in[15],
        (const float*)d_in[17], (const float*)d_in[18], (const float*)d_in[19], (const float*)d_in[20]);

    qkv_kernel<<<dim3(3, 512), 256, QKV_SMEM>>>(x, qw, kw, vw);
    attnqk_kernel<<<512, 256>>>();
    corr_kernel<<<dim3(8, 64), 256, CORR_SMEM>>>();
    oproj_kernel<<<dim3(2, 512), 256, OPR_SMEM>>>(x, ow, (float*)d_out);
}

// round 7
// speedup vs baseline: 4.3198x; 1.0670x over previous
#include <cuda_runtime.h>
#include <cuda_bf16.h>
#include <math.h>
#include <float.h>

#define HW    65536
#define CIN   512
#define HALF  256
#define NUM   64
#define NPP   1024
#define W_IMG 256
#define KP    72     // Ps pitch (floats)
#define KBP   40     // Kb/Kr pitch (u32)
#define VTP   72     // Vt pitch (floats)

// scratch (device globals: allocation-free rule)
__device__ float    g_q[NUM * NPP * HALF];    // (pn, ch) q, scaled
__device__ float    g_kp[HALF * NUM];         // (ch, patch) pooled k
__device__ float    g_vp[NUM * HALF];         // (patch, ch) pooled v
__device__ float    g_attn[NUM * NPP * NUM];  // (pn, m) raw fp32
__device__ unsigned g_ab32[NUM * NPP * 32];   // attn bf16-big, pair-packed+permuted
__device__ unsigned g_ar32[NUM * NPP * 32];   // attn bf16-res, pair-packed+permuted
__device__ float    g_av[NUM * NPP * NUM];    // attn rna-tf32 (V operand)
__device__ float    g_mid[NUM * NPP * HALF];  // (pn, ch) attention output
__device__ float    g_pscale[1280];
__device__ float    g_pbias[1280];

// ---------------------------------------------------------------------------
__device__ __forceinline__ float t32(float x) {
    asm("cvt.rna.tf32.f32 %0, %0;" : "+f"(x));
    return x;
}
__device__ __forceinline__ void mma8(float* d,
    unsigned a0, unsigned a1, unsigned a2, unsigned a3,
    unsigned b0, unsigned b1)
{
    asm volatile(
        "mma.sync.aligned.m16n8k8.row.col.f32.tf32.tf32.f32 "
        "{%0,%1,%2,%3},{%4,%5,%6,%7},{%8,%9},{%0,%1,%2,%3};"
        : "+f"(d[0]), "+f"(d[1]), "+f"(d[2]), "+f"(d[3])
        : "r"(a0), "r"(a1), "r"(a2), "r"(a3), "r"(b0), "r"(b1));
}
__device__ __forceinline__ void mmabf(float* d,
    unsigned a0, unsigned a1, unsigned a2, unsigned a3,
    unsigned b0, unsigned b1)
{
    asm volatile(
        "mma.sync.aligned.m16n8k16.row.col.f32.bf16.bf16.f32 "
        "{%0,%1,%2,%3},{%4,%5,%6,%7},{%8,%9},{%0,%1,%2,%3};"
        : "+f"(d[0]), "+f"(d[1]), "+f"(d[2]), "+f"(d[3])
        : "r"(a0), "r"(a1), "r"(a2), "r"(a3), "r"(b0), "r"(b1));
}
__device__ __forceinline__ void cpa16(void* smem_dst, const void* gsrc) {
    unsigned s = (unsigned)__cvta_generic_to_shared(smem_dst);
    asm volatile("cp.async.cg.shared.global [%0], [%1], 16;\n" :: "r"(s), "l"(gsrc));
}
__device__ __forceinline__ int perm8(int k) {
    return (k & ~7) + ((k & 3) * 2) + ((k >> 2) & 1);
}

// ---------------------------------------------------------------------------
// prep (unchanged)
// ---------------------------------------------------------------------------
__global__ void prep_kernel(
    const float* qg, const float* qb, const float* qm, const float* qv,
    const float* kg, const float* kb, const float* km, const float* kv,
    const float* vg, const float* vb, const float* vm, const float* vv,
    const float* og, const float* ob, const float* om, const float* ov)
{
    int i = blockIdx.x * blockDim.x + threadIdx.x;
    if (i < 1280) {
        const float *G, *B, *M, *V; float f; int r;
        if (i < 256)      { G = qg; B = qb; M = qm; V = qv; f = 0.044194173824159216f; r = i; }
        else if (i < 512) { G = kg; B = kb; M = km; V = kv; f = 1.0f / 1024.0f;        r = i - 256; }
        else if (i < 768) { G = vg; B = vb; M = vm; V = vv; f = 1.0f / 1024.0f;        r = i - 512; }
        else              { G = og; B = ob; M = om; V = ov; f = 1.0f;                  r = i - 768; }
        float s = G[r] * rsqrtf(V[r] + 1e-5f);
        g_pscale[i] = s * f;
        g_pbias[i]  = (B[r] - M[r] * s) * f;
    }
    int z = i - 1280;
    if (z >= 0 && z < HALF * NUM) g_kp[z] = 0.0f;
    z -= HALF * NUM;
    if (z >= 0 && z < NUM * HALF) g_vp[z] = 0.0f;
}

// ---------------------------------------------------------------------------
// QKV v3: block 128(pix) x 128(oc), 2 blocks/SM. grid (6, 512):
// gx>>1 = projection (q/k/v), gx&1 = oc half. 8 warps = 2(m) x 4(n),
// warp tile 64x32. 2-stage cp.async, raw-fp32 tf32.
// ---------------------------------------------------------------------------
#define QKV_SMEM ((2 * 32 * 136 + 2 * 128 * 36) * 4)
__global__ void __launch_bounds__(256, 2) qkv_kernel(
    const float* __restrict__ x, const float* __restrict__ qw,
    const float* __restrict__ kw, const float* __restrict__ vw)
{
    extern __shared__ float smq[];
    float* As = smq;                  // [2][32][136]
    float* Bs = smq + 2 * 32 * 136;   // [2][128][36]

    const int t = threadIdx.x, lane = t & 31, warp = t >> 5;
    const int g = lane >> 2, t4 = lane & 3;
    const int wm = (warp & 1) * 64, wn = (warp >> 1) * 32;
    const int gx = blockIdx.x;
    const int proj = gx >> 1, och = (gx & 1) * 128;
    const int pix0 = blockIdx.y * 128;
    const float* Wp = ((proj == 0) ? qw : (proj == 1) ? kw : vw) + (size_t)och * CIN;

    float acc[4][4][4] = {};

    const int a_row = t >> 5, a_c4 = (t & 31) * 4;          // + i*8 rows
    const int b_oc  = t >> 3, b_c4 = (t & 7) * 4;           // + i*32 rows

#define QKV_LOAD(s, k0)                                                        \
    {                                                                          \
        float* as = As + (s) * 32 * 136;                                       \
        float* bs = Bs + (s) * 128 * 36;                                       \
        _Pragma("unroll")                                                      \
        for (int i = 0; i < 4; i++)                                            \
            cpa16(as + (a_row + i * 8) * 136 + a_c4,                           \
                  x + (size_t)((k0) + a_row + i * 8) * HW + pix0 + a_c4);      \
        _Pragma("unroll")                                                      \
        for (int i = 0; i < 4; i++)                                            \
            cpa16(bs + (b_oc + i * 32) * 36 + b_c4,                            \
                  Wp + (size_t)(b_oc + i * 32) * CIN + (k0) + b_c4);           \
        asm volatile("cp.async.commit_group;\n");                              \
    }

    QKV_LOAD(0, 0);
    for (int kt = 0; kt < 16; kt++) {
        int s = kt & 1;
        if (kt < 15) {
            QKV_LOAD(s ^ 1, (kt + 1) * 32);
            asm volatile("cp.async.wait_group 1;\n");
        } else {
            asm volatile("cp.async.wait_group 0;\n");
        }
        __syncthreads();
        const float* as = As + s * 32 * 136;
        const float* bs = Bs + s * 128 * 36;
#pragma unroll
        for (int kk = 0; kk < 32; kk += 8) {
            unsigned a[4][4], b[4][2];
#pragma unroll
            for (int mi = 0; mi < 4; mi++) {
                int mb = wm + mi * 16 + g;
                a[mi][0] = __float_as_uint(as[(kk + t4) * 136 + mb]);
                a[mi][1] = __float_as_uint(as[(kk + t4) * 136 + mb + 8]);
                a[mi][2] = __float_as_uint(as[(kk + t4 + 4) * 136 + mb]);
                a[mi][3] = __float_as_uint(as[(kk + t4 + 4) * 136 + mb + 8]);
            }
#pragma unroll
            for (int nj = 0; nj < 4; nj++) {
                int nb = wn + nj * 8 + g;
                b[nj][0] = __float_as_uint(bs[nb * 36 + kk + t4]);
                b[nj][1] = __float_as_uint(bs[nb * 36 + kk + t4 + 4]);
            }
#pragma unroll
            for (int mi = 0; mi < 4; mi++)
#pragma unroll
                for (int nj = 0; nj < 4; nj++)
                    mma8(acc[mi][nj], a[mi][0], a[mi][1], a[mi][2], a[mi][3],
                         b[nj][0], b[nj][1]);
        }
        __syncthreads();
    }
#undef QKV_LOAD

    if (proj == 0) {
        // q: BN+ReLU (scale includes c^-0.5), write (pn, oc)
#pragma unroll
        for (int mi = 0; mi < 4; mi++)
#pragma unroll
            for (int h2 = 0; h2 < 2; h2++) {
                int pix = pix0 + wm + mi * 16 + g + h2 * 8;
                int h = pix >> 8, w = pix & 255;
                int pn = (((h >> 5) << 3) + (w >> 5)) * NPP + ((h & 31) << 5) + (w & 31);
#pragma unroll
                for (int nj = 0; nj < 4; nj++) {
                    int col = och + wn + nj * 8 + t4 * 2;
                    float v0 = fmaxf(fmaf(acc[mi][nj][h2 * 2],     g_pscale[col],     g_pbias[col]),     0.0f);
                    float v1 = fmaxf(fmaf(acc[mi][nj][h2 * 2 + 1], g_pscale[col + 1], g_pbias[col + 1]), 0.0f);
                    *(float2*)&g_q[(size_t)pn * HALF + col] = make_float2(v0, v1);
                }
            }
    } else {
        // k/v: BN+ReLU then patch-pool; warp m-range spans 2 patches (pl = mi>>1)
        float part[2][4][2] = {};
#pragma unroll
        for (int mi = 0; mi < 4; mi++) {
            int pl = mi >> 1;
#pragma unroll
            for (int nj = 0; nj < 4; nj++) {
                int sidx = proj * 256 + och + wn + nj * 8 + t4 * 2;
                float s0 = g_pscale[sidx],     b0 = g_pbias[sidx];
                float s1 = g_pscale[sidx + 1], b1 = g_pbias[sidx + 1];
#pragma unroll
                for (int h2 = 0; h2 < 2; h2++) {
                    part[pl][nj][0] += fmaxf(fmaf(acc[mi][nj][h2 * 2],     s0, b0), 0.0f);
                    part[pl][nj][1] += fmaxf(fmaf(acc[mi][nj][h2 * 2 + 1], s1, b1), 0.0f);
                }
            }
        }
#pragma unroll
        for (int m_ = 4; m_ <= 16; m_ <<= 1)
#pragma unroll
            for (int pl = 0; pl < 2; pl++)
#pragma unroll
                for (int nj = 0; nj < 4; nj++) {
                    part[pl][nj][0] += __shfl_xor_sync(0xffffffffu, part[pl][nj][0], m_);
                    part[pl][nj][1] += __shfl_xor_sync(0xffffffffu, part[pl][nj][1], m_);
                }
        if (g == 0) {
            int h0 = pix0 >> 8, w0 = pix0 & 255;
            int pbase = ((h0 >> 5) << 3) + (w0 >> 5);
#pragma unroll
            for (int pl = 0; pl < 2; pl++) {
                int p = pbase + (wm >> 5) + pl;
#pragma unroll
                for (int nj = 0; nj < 4; nj++) {
                    int oc2 = och + wn + nj * 8 + t4 * 2;
                    if (proj == 1) {
                        atomicAdd(&g_kp[oc2 * NUM + p],       part[pl][nj][0]);
                        atomicAdd(&g_kp[(oc2 + 1) * NUM + p], part[pl][nj][1]);
                    } else {
                        atomicAdd(&g_vp[p * HALF + oc2],     part[pl][nj][0]);
                        atomicAdd(&g_vp[p * HALF + oc2 + 1], part[pl][nj][1]);
                    }
                }
            }
        }
    }
}

// ---------------------------------------------------------------------------
// attnqk (unchanged from R6): mma GEMM + epilogue writes attn, tf32 copy,
// bf16 big/res packed+permuted.
// ---------------------------------------------------------------------------
__global__ void __launch_bounds__(256) attnqk_kernel()
{
    __shared__ float As[32][132];
    __shared__ float Bs[32][68];

    const int t = threadIdx.x, lane = t & 31, warp = t >> 5;
    const int wm = (warp & 3) * 32, wn = (warp >> 2) * 32;
    const int g = lane >> 2, t4 = lane & 3;
    const int pn0 = blockIdx.x * 128;

    float acc[2][4][4] = {};

    const int am2 = t & 127, ac = (t >> 7) * 16;
    const int bn4 = (t & 15) * 4, bk2 = t >> 4;

    for (int k0 = 0; k0 < HALF; k0 += 32) {
#pragma unroll
        for (int u = 0; u < 4; u++) {
            float4 v = *(const float4*)(g_q + (size_t)(pn0 + am2) * HALF + k0 + ac + u * 4);
            As[ac + u * 4][am2]     = v.x;
            As[ac + u * 4 + 1][am2] = v.y;
            As[ac + u * 4 + 2][am2] = v.z;
            As[ac + u * 4 + 3][am2] = v.w;
        }
#pragma unroll
        for (int u = 0; u < 2; u++) {
            int kr = bk2 + u * 16;
            float4 v = *(const float4*)(g_kp + (size_t)(k0 + kr) * NUM + bn4);
            Bs[kr][bn4]     = v.x;
            Bs[kr][bn4 + 1] = v.y;
            Bs[kr][bn4 + 2] = v.z;
            Bs[kr][bn4 + 3] = v.w;
        }
        __syncthreads();
#pragma unroll
        for (int kk = 0; kk < 32; kk += 8) {
            unsigned a[2][4], b[4][2];
#pragma unroll
            for (int mi = 0; mi < 2; mi++) {
                int mb = wm + mi * 16 + g;
                a[mi][0] = __float_as_uint(As[kk + t4][mb]);
                a[mi][1] = __float_as_uint(As[kk + t4][mb + 8]);
                a[mi][2] = __float_as_uint(As[kk + t4 + 4][mb]);
                a[mi][3] = __float_as_uint(As[kk + t4 + 4][mb + 8]);
            }
#pragma unroll
            for (int nj = 0; nj < 4; nj++) {
                int nb = wn + nj * 8 + g;
                b[nj][0] = __float_as_uint(Bs[kk + t4][nb]);
                b[nj][1] = __float_as_uint(Bs[kk + t4 + 4][nb]);
            }
#pragma unroll
            for (int mi = 0; mi < 2; mi++)
#pragma unroll
                for (int nj = 0; nj < 4; nj++)
                    mma8(acc[mi][nj], a[mi][0], a[mi][1], a[mi][2], a[mi][3],
                         b[nj][0], b[nj][1]);
        }
        __syncthreads();
    }

#pragma unroll
    for (int mi = 0; mi < 2; mi++)
#pragma unroll
        for (int h2 = 0; h2 < 2; h2++) {
            int row = pn0 + wm + mi * 16 + g + h2 * 8;
#pragma unroll
            for (int nj = 0; nj < 4; nj++) {
                int col = wn + nj * 8 + t4 * 2;
                float v0 = acc[mi][nj][h2 * 2], v1 = acc[mi][nj][h2 * 2 + 1];
                *(float2*)&g_attn[(size_t)row * NUM + col] = make_float2(v0, v1);
                *(float2*)&g_av[(size_t)row * NUM + col]   = make_float2(t32(v0), t32(v1));
                __nv_bfloat16 b0 = __float2bfloat16_rn(v0);
                __nv_bfloat16 b1 = __float2bfloat16_rn(v1);
                float r0 = v0 - __bfloat162float(b0);
                float r1 = v1 - __bfloat162float(b1);
                __nv_bfloat16 c0 = __float2bfloat16_rn(r0);
                __nv_bfloat16 c1 = __float2bfloat16_rn(r1);
                unsigned pb = (unsigned)__bfloat16_as_ushort(b0) |
                              ((unsigned)__bfloat16_as_ushort(b1) << 16);
                unsigned pr = (unsigned)__bfloat16_as_ushort(c0) |
                              ((unsigned)__bfloat16_as_ushort(c1) << 16);
                int P = col >> 1;
                int permP = (P & ~7) | ((P & 3) << 1) | ((P >> 2) & 1);
                g_ab32[(size_t)row * 32 + permP] = pb;
                g_ar32[(size_t)row * 32 + permP] = pr;
            }
        }
}

// ---------------------------------------------------------------------------
// corr v4 (unchanged from R6)
// ---------------------------------------------------------------------------
#define CORR_SMEM ((4 * 64 * KBP + 2 * 64 * VTP + 128 * KP) * 4)
__global__ void __launch_bounds__(256, 2) corr_kernel()
{
    extern __shared__ float sm[];
    unsigned* KbA = (unsigned*)sm;
    unsigned* KrA = KbA + 2 * 64 * KBP;
    float*    VtA = (float*)(KrA + 2 * 64 * KBP);
    float*    Ps  = VtA + 2 * 64 * VTP;

    const int t = threadIdx.x, lane = t & 31, warp = t >> 5;
    const int g = lane >> 2, t4 = lane & 3;
    const int rm0 = warp * 16;
    const int n0 = blockIdx.x * 128;
    const int p  = blockIdx.y;
    const float*    ab   = g_attn + (size_t)p * NPP * NUM;
    const unsigned* abig = g_ab32 + (size_t)p * NPP * 32;
    const unsigned* ares = g_ar32 + (size_t)p * NPP * 32;
    const float*    av   = g_av   + (size_t)p * NPP * NUM;

    const int row0 = n0 + rm0 + g, row1 = row0 + 8;
    const int pp0 = perm8(2 * t4), pp1 = perm8(2 * t4 + 1);

    unsigned qb[4][4], qr[4][4];
#pragma unroll
    for (int c = 0; c < 4; c++) {
        int base = 8 * c + 2 * t4;
        uint2 v0 = *(const uint2*)&abig[(size_t)row0 * 32 + base];
        uint2 v1 = *(const uint2*)&abig[(size_t)row1 * 32 + base];
        qb[c][0] = v0.x; qb[c][2] = v0.y;
        qb[c][1] = v1.x; qb[c][3] = v1.y;
        uint2 w0 = *(const uint2*)&ares[(size_t)row0 * 32 + base];
        uint2 w1 = *(const uint2*)&ares[(size_t)row1 * 32 + base];
        qr[c][0] = w0.x; qr[c][2] = w0.y;
        qr[c][1] = w1.x; qr[c][3] = w1.y;
    }

    const int kr8 = t >> 3, ko8 = t & 7;
    const int vrow = t >> 2, vo16 = (t & 3);

#define CORR_LOAD(s, jt)                                                       \
    {                                                                          \
        unsigned* kb = KbA + (s) * 64 * KBP;                                   \
        unsigned* kr = KrA + (s) * 64 * KBP;                                   \
        float*    vt = VtA + (s) * 64 * VTP;                                   \
        _Pragma("unroll")                                                      \
        for (int i = 0; i < 2; i++) {                                          \
            int r = kr8 + i * 32;                                              \
            cpa16(kb + r * KBP + ko8 * 4, abig + ((size_t)(jt) * 64 + r) * 32 + ko8 * 4); \
            cpa16(kr + r * KBP + ko8 * 4, ares + ((size_t)(jt) * 64 + r) * 32 + ko8 * 4); \
        }                                                                      \
        _Pragma("unroll")                                                      \
        for (int i = 0; i < 4; i++) {                                          \
            int o = vo16 * 4 + i;                                              \
            cpa16(vt + vrow * VTP + o * 4, av + ((size_t)(jt) * 64 + vrow) * 64 + o * 4); \
        }                                                                      \
        asm volatile("cp.async.commit_group;\n");                              \
    }

    float mi[2] = {-FLT_MAX, -FLT_MAX}, li[2] = {0.0f, 0.0f};
    float o[8][4] = {};

    CORR_LOAD(0, 0);
    for (int jt = 0; jt < 16; jt++) {
        int s = jt & 1;
        if (jt < 15) {
            CORR_LOAD(s ^ 1, jt + 1);
            asm volatile("cp.async.wait_group 1;\n");
        } else {
            asm volatile("cp.async.wait_group 0;\n");
        }
        __syncthreads();
        const unsigned* kb = KbA + s * 64 * KBP;
        const unsigned* kr = KrA + s * 64 * KBP;
        const float*    vt = VtA + s * 64 * VTP;

        float sa[8][4] = {};
#pragma unroll
        for (int c = 0; c < 4; c++) {
            int ko = c * 8 + 2 * t4;
#pragma unroll
            for (int nj = 0; nj < 8; nj++) {
                int rb = (nj * 8 + g) * KBP + ko;
                uint2 bb = *(const uint2*)&kb[rb];
                uint2 br = *(const uint2*)&kr[rb];
                mmabf(sa[nj], qb[c][0], qb[c][1], qb[c][2], qb[c][3], bb.x, bb.y);
                mmabf(sa[nj], qb[c][0], qb[c][1], qb[c][2], qb[c][3], br.x, br.y);
                mmabf(sa[nj], qr[c][0], qr[c][1], qr[c][2], qr[c][3], bb.x, bb.y);
            }
        }

#pragma unroll
        for (int h = 0; h < 2; h++) {
            float rmax = -FLT_MAX;
#pragma unroll
            for (int nj = 0; nj < 8; nj++)
                rmax = fmaxf(rmax, fmaxf(sa[nj][2 * h], sa[nj][2 * h + 1]));
            rmax = fmaxf(rmax, __shfl_xor_sync(0xffffffffu, rmax, 1));
            rmax = fmaxf(rmax, __shfl_xor_sync(0xffffffffu, rmax, 2));
            float nm = fmaxf(mi[h], rmax);
            float sc = __expf(mi[h] - nm);
            mi[h] = nm;
            float rs = 0.0f;
#pragma unroll
            for (int nj = 0; nj < 8; nj++) {
                float v0 = __expf(sa[nj][2 * h]     - nm);
                float v1 = __expf(sa[nj][2 * h + 1] - nm);
                sa[nj][2 * h] = v0; sa[nj][2 * h + 1] = v1;
                rs += v0 + v1;
            }
            rs += __shfl_xor_sync(0xffffffffu, rs, 1);
            rs += __shfl_xor_sync(0xffffffffu, rs, 2);
            li[h] = li[h] * sc + rs;
#pragma unroll
            for (int nj = 0; nj < 8; nj++) {
                o[nj][2 * h]     *= sc;
                o[nj][2 * h + 1] *= sc;
            }
        }

#pragma unroll
        for (int h = 0; h < 2; h++) {
            int rb = (rm0 + g + h * 8) * KP;
#pragma unroll
            for (int nj = 0; nj < 8; nj++) {
                Ps[rb + nj * 8 + pp0] = t32(sa[nj][2 * h]);
                Ps[rb + nj * 8 + pp1] = t32(sa[nj][2 * h + 1]);
            }
        }
        __syncwarp();

#pragma unroll
        for (int ks = 0; ks < 8; ks++) {
            int ko = ks * 8 + t4 * 2;
            float2 aA = *(const float2*)&Ps[(rm0 + g) * KP + ko];
            float2 aB = *(const float2*)&Ps[(rm0 + 8 + g) * KP + ko];
            unsigned a0 = __float_as_uint(aA.x), a1 = __float_as_uint(aB.x);
            unsigned a2 = __float_as_uint(aA.y), a3 = __float_as_uint(aB.y);
#pragma unroll
            for (int nj = 0; nj < 8; nj++) {
                unsigned b0 = __float_as_uint(vt[(ks * 8 + t4) * VTP + nj * 8 + g]);
                unsigned b1 = __float_as_uint(vt[(ks * 8 + t4 + 4) * VTP + nj * 8 + g]);
                mma8(o[nj], a0, a1, a2, a3, b0, b1);
            }
        }
        __syncthreads();
    }
#undef CORR_LOAD

#pragma unroll
    for (int h = 0; h < 2; h++) {
        int row = (h == 0) ? row0 : row1;
        float inv = 1.0f / li[h];
        float tv[16];
#pragma unroll
        for (int nj = 0; nj < 8; nj++) {
            float2 avv = *(const float2*)(ab + (size_t)row * NUM + nj * 8 + 2 * t4);
            tv[nj * 2]     = avv.x + o[nj][2 * h]     * inv;
            tv[nj * 2 + 1] = avv.y + o[nj][2 * h + 1] * inv;
        }
        float rmax = -FLT_MAX;
#pragma unroll
        for (int l = 0; l < 16; l++) rmax = fmaxf(rmax, tv[l]);
        rmax = fmaxf(rmax, __shfl_xor_sync(0xffffffffu, rmax, 1));
        rmax = fmaxf(rmax, __shfl_xor_sync(0xffffffffu, rmax, 2));
        float rs = 0.0f;
#pragma unroll
        for (int l = 0; l < 16; l++) { tv[l] = __expf(tv[l] - rmax); rs += tv[l]; }
        rs += __shfl_xor_sync(0xffffffffu, rs, 1);
        rs += __shfl_xor_sync(0xffffffffu, rs, 2);
        float is = 1.0f / rs;
        int rb = (rm0 + g + h * 8) * KP;
#pragma unroll
        for (int nj = 0; nj < 8; nj++) {
            Ps[rb + nj * 8 + pp0] = t32(tv[nj * 2] * is);
            Ps[rb + nj * 8 + pp1] = t32(tv[nj * 2 + 1] * is);
        }
    }

    float* Vs = VtA;
    const int lj = t >> 2, ld0 = (t & 3) * 16;
    const int lpj = perm8(lj);
    for (int ch = 0; ch < 4; ch++) {
        __syncthreads();
        {
            const float* src = g_vp + (size_t)lj * HALF + ch * 64 + ld0;
#pragma unroll
            for (int u = 0; u < 4; u++) {
                float4 v = *(const float4*)(src + u * 4);
                float vv[4] = {v.x, v.y, v.z, v.w};
#pragma unroll
                for (int c2 = 0; c2 < 4; c2++)
                    Vs[(ld0 + u * 4 + c2) * VTP + lpj] = t32(vv[c2]);
            }
        }
        __syncthreads();

        float acc[8][4] = {};
#pragma unroll
        for (int ks = 0; ks < 8; ks++) {
            int ko = ks * 8 + t4 * 2;
            float2 aA = *(const float2*)&Ps[(rm0 + g) * KP + ko];
            float2 aB = *(const float2*)&Ps[(rm0 + 8 + g) * KP + ko];
            unsigned a0 = __float_as_uint(aA.x), a1 = __float_as_uint(aB.x);
            unsigned a2 = __float_as_uint(aA.y), a3 = __float_as_uint(aB.y);
#pragma unroll
            for (int nj = 0; nj < 8; nj++) {
                float2 bv = *(const float2*)&Vs[(nj * 8 + g) * VTP + ks * 8 + 2 * t4];
                mma8(acc[nj], a0, a1, a2, a3,
                     __float_as_uint(bv.x), __float_as_uint(bv.y));
            }
        }
#pragma unroll
        for (int h = 0; h < 2; h++) {
            size_t pn = (size_t)p * NPP + n0 + rm0 + g + h * 8;
#pragma unroll
            for (int nj = 0; nj < 8; nj++) {
                int col = ch * 64 + nj * 8 + 2 * t4;
                *(float2*)&g_mid[pn * HALF + col] =
                    make_float2(acc[nj][2 * h], acc[nj][2 * h + 1]);
            }
        }
    }
}

// ---------------------------------------------------------------------------
// o-proj v3: block 128(pn) x 128(oc), 2 blocks/SM. grid (4, 512).
// ---------------------------------------------------------------------------
#define OPR_SMEM ((2 * 128 * 36 + 2 * 128 * 36) * 4)
__global__ void __launch_bounds__(256, 2) oproj_kernel(
    const float* __restrict__ x, const float* __restrict__ ow,
    float* __restrict__ out)
{
    extern __shared__ float smo[];
    float* As = smo;                   // [2][128][36]
    float* Bs = smo + 2 * 128 * 36;    // [2][128][36]

    const int t = threadIdx.x, lane = t & 31, warp = t >> 5;
    const int g = lane >> 2, t4 = lane & 3;
    const int wm = (warp & 1) * 64, wn = (warp >> 1) * 32;
    const int ocr = blockIdx.x * 128;
    const int pn0 = blockIdx.y * 128;

    float acc[4][4][4] = {};

    const int a_row = t >> 3, a_c4 = (t & 7) * 4;

#define OPR_LOAD(s, k0)                                                        \
    {                                                                          \
        float* as = As + (s) * 128 * 36;                                       \
        float* bs = Bs + (s) * 128 * 36;                                       \
        _Pragma("unroll")                                                      \
        for (int i = 0; i < 4; i++)                                            \
            cpa16(as + (a_row + i * 32) * 36 + a_c4,                           \
                  g_mid + (size_t)(pn0 + a_row + i * 32) * HALF + (k0) + a_c4);\
        _Pragma("unroll")                                                      \
        for (int i = 0; i < 4; i++)                                            \
            cpa16(bs + (a_row + i * 32) * 36 + a_c4,                           \
                  ow + (size_t)(ocr + a_row + i * 32) * HALF + (k0) + a_c4);   \
        asm volatile("cp.async.commit_group;\n");                              \
    }

    OPR_LOAD(0, 0);
    for (int kt = 0; kt < 8; kt++) {
        int s = kt & 1;
        if (kt < 7) {
            OPR_LOAD(s ^ 1, (kt + 1) * 32);
            asm volatile("cp.async.wait_group 1;\n");
        } else {
            asm volatile("cp.async.wait_group 0;\n");
        }
        __syncthreads();
        const float* as = As + s * 128 * 36;
        const float* bs = Bs + s * 128 * 36;
#pragma unroll
        for (int kk = 0; kk < 32; kk += 8) {
            unsigned a[4][4], b[4][2];
#pragma unroll
            for (int mi = 0; mi < 4; mi++) {
                int mb = wm + mi * 16 + g;
                a[mi][0] = __float_as_uint(as[mb * 36 + kk + t4]);
                a[mi][1] = __float_as_uint(as[(mb + 8) * 36 + kk + t4]);
                a[mi][2] = __float_as_uint(as[mb * 36 + kk + t4 + 4]);
                a[mi][3] = __float_as_uint(as[(mb + 8) * 36 + kk + t4 + 4]);
            }
#pragma unroll
            for (int nj = 0; nj < 4; nj++) {
                int nb = wn + nj * 8 + g;
                b[nj][0] = __float_as_uint(bs[nb * 36 + kk + t4]);
                b[nj][1] = __float_as_uint(bs[nb * 36 + kk + t4 + 4]);
            }
#pragma unroll
            for (int mi = 0; mi < 4; mi++)
#pragma unroll
                for (int nj = 0; nj < 4; nj++)
                    mma8(acc[mi][nj], a[mi][0], a[mi][1], a[mi][2], a[mi][3],
                         b[nj][0], b[nj][1]);
        }
        __syncthreads();
    }
#undef OPR_LOAD

#pragma unroll
    for (int mi = 0; mi < 4; mi++)
#pragma unroll
        for (int h2 = 0; h2 < 2; h2++) {
            int pn = pn0 + wm + mi * 16 + g + h2 * 8;
            int p = pn >> 10, n = pn & 1023;
            int h = ((p >> 3) << 5) + (n >> 5);
            int w = ((p & 7) << 5) + (n & 31);
            int base = h * W_IMG + w;
#pragma unroll
            for (int nj = 0; nj < 4; nj++) {
                int oc = ocr + wn + nj * 8 + t4 * 2;
                float s0 = g_pscale[768 + oc],     b0 = g_pbias[768 + oc];
                float s1 = g_pscale[768 + oc + 1], b1 = g_pbias[768 + oc + 1];
                size_t i0 = (size_t)oc * HW + base;
                size_t i1 = i0 + HW;
                out[i0] = fmaxf(fmaf(acc[mi][nj][h2 * 2],     s0, b0), 0.0f) + x[i0];
                out[i1] = fmaxf(fmaf(acc[mi][nj][h2 * 2 + 1], s1, b1), 0.0f) + x[i1];
            }
        }
}

// ---------------------------------------------------------------------------
extern "C" void kernel_launch(void* const* d_in, const int* in_sizes, int n_in,
                              void* d_out, int out_size)
{
    (void)in_sizes; (void)n_in; (void)out_size;
    const float* x  = (const float*)d_in[0];
    const float* qw = (const float*)d_in[1];
    const float* kw = (const float*)d_in[6];
    const float* vw = (const float*)d_in[11];
    const float* ow = (const float*)d_in[16];

    cudaFuncSetAttribute(corr_kernel,
                         cudaFuncAttributeMaxDynamicSharedMemorySize, CORR_SMEM);
    cudaFuncSetAttribute(qkv_kernel,
                         cudaFuncAttributeMaxDynamicSharedMemorySize, QKV_SMEM);
    cudaFuncSetAttribute(oproj_kernel,
                         cudaFuncAttributeMaxDynamicSharedMemorySize, OPR_SMEM);

    prep_kernel<<<134, 256>>>(
        (const float*)d_in[2],  (const float*)d_in[3],  (const float*)d_in[4],  (const float*)d_in[5],
        (const float*)d_in[7],  (const float*)d_in[8],  (const float*)d_in[9],  (const float*)d_in[10],
        (const float*)d_in[12], (const float*)d_in[13], (const float*)d_in[14], (const float*)d_in[15],
        (const float*)d_in[17], (const float*)d_in[18], (const float*)d_in[19], (const float*)d_in[20]);

    qkv_kernel<<<dim3(6, 512), 256, QKV_SMEM>>>(x, qw, kw, vw);
    attnqk_kernel<<<512, 256>>>();
    corr_kernel<<<dim3(8, 64), 256, CORR_SMEM>>>();
    oproj_kernel<<<dim3(4, 512), 256, OPR_SMEM>>>(x, ow, (float*)d_out);
}

// round 8
// speedup vs baseline: 4.4960x; 1.0408x over previous
#include <cuda_runtime.h>
#include <cuda_bf16.h>
#include <math.h>
#include <float.h>

#define HW    65536
#define CIN   512
#define HALF  256
#define NUM   64
#define NPP   1024
#define W_IMG 256
#define KP    72     // Ps pitch (floats)
#define KBRP  80     // interleaved big/res pitch (u32)
#define VTP   72     // Vt pitch (floats)

// scratch (device globals: allocation-free rule)
__device__ float    g_q[NUM * NPP * HALF];    // (pn, ch) q, scaled
__device__ float    g_kp[HALF * NUM];         // (ch, patch) pooled k
__device__ float    g_vp[NUM * HALF];         // (patch, ch) pooled v
__device__ unsigned g_abr[NUM * NPP * 64];    // attn bf16 big/res interleaved blocks
__device__ float    g_avt[NUM * NPP * NUM];   // attn tf32, [p][jt][d][perm(jl)]
__device__ float    g_mid[NUM * NPP * HALF];  // (pn, ch) attention output
__device__ float    g_pscale[1280];
__device__ float    g_pbias[1280];

// ---------------------------------------------------------------------------
__device__ __forceinline__ float t32(float x) {
    asm("cvt.rna.tf32.f32 %0, %0;" : "+f"(x));
    return x;
}
__device__ __forceinline__ void mma8(float* d,
    unsigned a0, unsigned a1, unsigned a2, unsigned a3,
    unsigned b0, unsigned b1)
{
    asm volatile(
        "mma.sync.aligned.m16n8k8.row.col.f32.tf32.tf32.f32 "
        "{%0,%1,%2,%3},{%4,%5,%6,%7},{%8,%9},{%0,%1,%2,%3};"
        : "+f"(d[0]), "+f"(d[1]), "+f"(d[2]), "+f"(d[3])
        : "r"(a0), "r"(a1), "r"(a2), "r"(a3), "r"(b0), "r"(b1));
}
__device__ __forceinline__ void mmabf(float* d,
    unsigned a0, unsigned a1, unsigned a2, unsigned a3,
    unsigned b0, unsigned b1)
{
    asm volatile(
        "mma.sync.aligned.m16n8k16.row.col.f32.bf16.bf16.f32 "
        "{%0,%1,%2,%3},{%4,%5,%6,%7},{%8,%9},{%0,%1,%2,%3};"
        : "+f"(d[0]), "+f"(d[1]), "+f"(d[2]), "+f"(d[3])
        : "r"(a0), "r"(a1), "r"(a2), "r"(a3), "r"(b0), "r"(b1));
}
__device__ __forceinline__ void cpa16(void* smem_dst, const void* gsrc) {
    unsigned s = (unsigned)__cvta_generic_to_shared(smem_dst);
    asm volatile("cp.async.cg.shared.global [%0], [%1], 16;\n" :: "r"(s), "l"(gsrc));
}
__device__ __forceinline__ int perm8(int k) {
    return (k & ~7) + ((k & 3) * 2) + ((k >> 2) & 1);
}
// interleaved-block position of the "big" u32 for value-pair index P (0..31)
__device__ __forceinline__ int posb(int P) {
    return ((P >> 3) * 16) + ((P & 3) * 4) + ((P >> 2) & 1);
}

// ---------------------------------------------------------------------------
// prep (unchanged)
// ---------------------------------------------------------------------------
__global__ void prep_kernel(
    const float* qg, const float* qb, const float* qm, const float* qv,
    const float* kg, const float* kb, const float* km, const float* kv,
    const float* vg, const float* vb, const float* vm, const float* vv,
    const float* og, const float* ob, const float* om, const float* ov)
{
    int i = blockIdx.x * blockDim.x + threadIdx.x;
    if (i < 1280) {
        const float *G, *B, *M, *V; float f; int r;
        if (i < 256)      { G = qg; B = qb; M = qm; V = qv; f = 0.044194173824159216f; r = i; }
        else if (i < 512) { G = kg; B = kb; M = km; V = kv; f = 1.0f / 1024.0f;        r = i - 256; }
        else if (i < 768) { G = vg; B = vb; M = vm; V = vv; f = 1.0f / 1024.0f;        r = i - 512; }
        else              { G = og; B = ob; M = om; V = ov; f = 1.0f;                  r = i - 768; }
        float s = G[r] * rsqrtf(V[r] + 1e-5f);
        g_pscale[i] = s * f;
        g_pbias[i]  = (B[r] - M[r] * s) * f;
    }
    int z = i - 1280;
    if (z >= 0 && z < HALF * NUM) g_kp[z] = 0.0f;
    z -= HALF * NUM;
    if (z >= 0 && z < NUM * HALF) g_vp[z] = 0.0f;
}

// ---------------------------------------------------------------------------
// QKV v3 (unchanged from R7)
// ---------------------------------------------------------------------------
#define QKV_SMEM ((2 * 32 * 136 + 2 * 128 * 36) * 4)
__global__ void __launch_bounds__(256, 2) qkv_kernel(
    const float* __restrict__ x, const float* __restrict__ qw,
    const float* __restrict__ kw, const float* __restrict__ vw)
{
    extern __shared__ float smq[];
    float* As = smq;
    float* Bs = smq + 2 * 32 * 136;

    const int t = threadIdx.x, lane = t & 31, warp = t >> 5;
    const int g = lane >> 2, t4 = lane & 3;
    const int wm = (warp & 1) * 64, wn = (warp >> 1) * 32;
    const int gx = blockIdx.x;
    const int proj = gx >> 1, och = (gx & 1) * 128;
    const int pix0 = blockIdx.y * 128;
    const float* Wp = ((proj == 0) ? qw : (proj == 1) ? kw : vw) + (size_t)och * CIN;

    float acc[4][4][4] = {};

    const int a_row = t >> 5, a_c4 = (t & 31) * 4;
    const int b_oc  = t >> 3, b_c4 = (t & 7) * 4;

#define QKV_LOAD(s, k0)                                                        \
    {                                                                          \
        float* as = As + (s) * 32 * 136;                                       \
        float* bs = Bs + (s) * 128 * 36;                                       \
        _Pragma("unroll")                                                      \
        for (int i = 0; i < 4; i++)                                            \
            cpa16(as + (a_row + i * 8) * 136 + a_c4,                           \
                  x + (size_t)((k0) + a_row + i * 8) * HW + pix0 + a_c4);      \
        _Pragma("unroll")                                                      \
        for (int i = 0; i < 4; i++)                                            \
            cpa16(bs + (b_oc + i * 32) * 36 + b_c4,                            \
                  Wp + (size_t)(b_oc + i * 32) * CIN + (k0) + b_c4);           \
        asm volatile("cp.async.commit_group;\n");                              \
    }

    QKV_LOAD(0, 0);
    for (int kt = 0; kt < 16; kt++) {
        int s = kt & 1;
        if (kt < 15) {
            QKV_LOAD(s ^ 1, (kt + 1) * 32);
            asm volatile("cp.async.wait_group 1;\n");
        } else {
            asm volatile("cp.async.wait_group 0;\n");
        }
        __syncthreads();
        const float* as = As + s * 32 * 136;
        const float* bs = Bs + s * 128 * 36;
#pragma unroll
        for (int kk = 0; kk < 32; kk += 8) {
            unsigned a[4][4], b[4][2];
#pragma unroll
            for (int mi = 0; mi < 4; mi++) {
                int mb = wm + mi * 16 + g;
                a[mi][0] = __float_as_uint(as[(kk + t4) * 136 + mb]);
                a[mi][1] = __float_as_uint(as[(kk + t4) * 136 + mb + 8]);
                a[mi][2] = __float_as_uint(as[(kk + t4 + 4) * 136 + mb]);
                a[mi][3] = __float_as_uint(as[(kk + t4 + 4) * 136 + mb + 8]);
            }
#pragma unroll
            for (int nj = 0; nj < 4; nj++) {
                int nb = wn + nj * 8 + g;
                b[nj][0] = __float_as_uint(bs[nb * 36 + kk + t4]);
                b[nj][1] = __float_as_uint(bs[nb * 36 + kk + t4 + 4]);
            }
#pragma unroll
            for (int mi = 0; mi < 4; mi++)
#pragma unroll
                for (int nj = 0; nj < 4; nj++)
                    mma8(acc[mi][nj], a[mi][0], a[mi][1], a[mi][2], a[mi][3],
                         b[nj][0], b[nj][1]);
        }
        __syncthreads();
    }
#undef QKV_LOAD

    if (proj == 0) {
#pragma unroll
        for (int mi = 0; mi < 4; mi++)
#pragma unroll
            for (int h2 = 0; h2 < 2; h2++) {
                int pix = pix0 + wm + mi * 16 + g + h2 * 8;
                int h = pix >> 8, w = pix & 255;
                int pn = (((h >> 5) << 3) + (w >> 5)) * NPP + ((h & 31) << 5) + (w & 31);
#pragma unroll
                for (int nj = 0; nj < 4; nj++) {
                    int col = och + wn + nj * 8 + t4 * 2;
                    float v0 = fmaxf(fmaf(acc[mi][nj][h2 * 2],     g_pscale[col],     g_pbias[col]),     0.0f);
                    float v1 = fmaxf(fmaf(acc[mi][nj][h2 * 2 + 1], g_pscale[col + 1], g_pbias[col + 1]), 0.0f);
                    *(float2*)&g_q[(size_t)pn * HALF + col] = make_float2(v0, v1);
                }
            }
    } else {
        float part[2][4][2] = {};
#pragma unroll
        for (int mi = 0; mi < 4; mi++) {
            int pl = mi >> 1;
#pragma unroll
            for (int nj = 0; nj < 4; nj++) {
                int sidx = proj * 256 + och + wn + nj * 8 + t4 * 2;
                float s0 = g_pscale[sidx],     b0 = g_pbias[sidx];
                float s1 = g_pscale[sidx + 1], b1 = g_pbias[sidx + 1];
#pragma unroll
                for (int h2 = 0; h2 < 2; h2++) {
                    part[pl][nj][0] += fmaxf(fmaf(acc[mi][nj][h2 * 2],     s0, b0), 0.0f);
                    part[pl][nj][1] += fmaxf(fmaf(acc[mi][nj][h2 * 2 + 1], s1, b1), 0.0f);
                }
            }
        }
#pragma unroll
        for (int m_ = 4; m_ <= 16; m_ <<= 1)
#pragma unroll
            for (int pl = 0; pl < 2; pl++)
#pragma unroll
                for (int nj = 0; nj < 4; nj++) {
                    part[pl][nj][0] += __shfl_xor_sync(0xffffffffu, part[pl][nj][0], m_);
                    part[pl][nj][1] += __shfl_xor_sync(0xffffffffu, part[pl][nj][1], m_);
                }
        if (g == 0) {
            int h0 = pix0 >> 8, w0 = pix0 & 255;
            int pbase = ((h0 >> 5) << 3) + (w0 >> 5);
#pragma unroll
            for (int pl = 0; pl < 2; pl++) {
                int p = pbase + (wm >> 5) + pl;
#pragma unroll
                for (int nj = 0; nj < 4; nj++) {
                    int oc2 = och + wn + nj * 8 + t4 * 2;
                    if (proj == 1) {
                        atomicAdd(&g_kp[oc2 * NUM + p],       part[pl][nj][0]);
                        atomicAdd(&g_kp[(oc2 + 1) * NUM + p], part[pl][nj][1]);
                    } else {
                        atomicAdd(&g_vp[p * HALF + oc2],     part[pl][nj][0]);
                        atomicAdd(&g_vp[p * HALF + oc2 + 1], part[pl][nj][1]);
                    }
                }
            }
        }
    }
}

// ---------------------------------------------------------------------------
// attnqk: GEMM epilogue writes g_abr (interleaved bf16 big/res blocks) and
// g_avt (tf32, transposed+permuted for corr's PV loads). No raw attn array.
// ---------------------------------------------------------------------------
__global__ void __launch_bounds__(256) attnqk_kernel()
{
    __shared__ float As[32][132];
    __shared__ float Bs[32][68];

    const int t = threadIdx.x, lane = t & 31, warp = t >> 5;
    const int wm = (warp & 3) * 32, wn = (warp >> 2) * 32;
    const int g = lane >> 2, t4 = lane & 3;
    const int pn0 = blockIdx.x * 128;

    float acc[2][4][4] = {};

    const int am2 = t & 127, ac = (t >> 7) * 16;
    const int bn4 = (t & 15) * 4, bk2 = t >> 4;

    for (int k0 = 0; k0 < HALF; k0 += 32) {
#pragma unroll
        for (int u = 0; u < 4; u++) {
            float4 v = *(const float4*)(g_q + (size_t)(pn0 + am2) * HALF + k0 + ac + u * 4);
            As[ac + u * 4][am2]     = v.x;
            As[ac + u * 4 + 1][am2] = v.y;
            As[ac + u * 4 + 2][am2] = v.z;
            As[ac + u * 4 + 3][am2] = v.w;
        }
#pragma unroll
        for (int u = 0; u < 2; u++) {
            int kr = bk2 + u * 16;
            float4 v = *(const float4*)(g_kp + (size_t)(k0 + kr) * NUM + bn4);
            Bs[kr][bn4]     = v.x;
            Bs[kr][bn4 + 1] = v.y;
            Bs[kr][bn4 + 2] = v.z;
            Bs[kr][bn4 + 3] = v.w;
        }
        __syncthreads();
#pragma unroll
        for (int kk = 0; kk < 32; kk += 8) {
            unsigned a[2][4], b[4][2];
#pragma unroll
            for (int mi = 0; mi < 2; mi++) {
                int mb = wm + mi * 16 + g;
                a[mi][0] = __float_as_uint(As[kk + t4][mb]);
                a[mi][1] = __float_as_uint(As[kk + t4][mb + 8]);
                a[mi][2] = __float_as_uint(As[kk + t4 + 4][mb]);
                a[mi][3] = __float_as_uint(As[kk + t4 + 4][mb + 8]);
            }
#pragma unroll
            for (int nj = 0; nj < 4; nj++) {
                int nb = wn + nj * 8 + g;
                b[nj][0] = __float_as_uint(Bs[kk + t4][nb]);
                b[nj][1] = __float_as_uint(Bs[kk + t4 + 4][nb]);
            }
#pragma unroll
            for (int mi = 0; mi < 2; mi++)
#pragma unroll
                for (int nj = 0; nj < 4; nj++)
                    mma8(acc[mi][nj], a[mi][0], a[mi][1], a[mi][2], a[mi][3],
                         b[nj][0], b[nj][1]);
        }
        __syncthreads();
    }

#pragma unroll
    for (int mi = 0; mi < 2; mi++)
#pragma unroll
        for (int h2 = 0; h2 < 2; h2++) {
            int row = pn0 + wm + mi * 16 + g + h2 * 8;
            int p = row >> 10, n = row & 1023;
            int jt = n >> 6, jl = n & 63;
            int pj = perm8(jl);
            size_t vtb = ((size_t)p * 16 + jt) * 64;   // avt row-block base (d rows)
#pragma unroll
            for (int nj = 0; nj < 4; nj++) {
                int col = wn + nj * 8 + t4 * 2;
                float v0 = acc[mi][nj][h2 * 2], v1 = acc[mi][nj][h2 * 2 + 1];
                // tf32 V copy, transposed + pair-permuted
                g_avt[(vtb + col)     * 64 + pj] = t32(v0);
                g_avt[(vtb + col + 1) * 64 + pj] = t32(v1);
                // bf16 split into interleaved big/res blocks
                __nv_bfloat16 b0 = __float2bfloat16_rn(v0);
                __nv_bfloat16 b1 = __float2bfloat16_rn(v1);
                float r0 = v0 - __bfloat162float(b0);
                float r1 = v1 - __bfloat162float(b1);
                __nv_bfloat16 c0 = __float2bfloat16_rn(r0);
                __nv_bfloat16 c1 = __float2bfloat16_rn(r1);
                unsigned pb = (unsigned)__bfloat16_as_ushort(b0) |
                              ((unsigned)__bfloat16_as_ushort(b1) << 16);
                unsigned pr = (unsigned)__bfloat16_as_ushort(c0) |
                              ((unsigned)__bfloat16_as_ushort(c1) << 16);
                int P = col >> 1;
                int pbp = posb(P);
                g_abr[(size_t)row * 64 + pbp]     = pb;
                g_abr[(size_t)row * 64 + pbp + 2] = pr;
            }
        }
}

// ---------------------------------------------------------------------------
// corr v5: interleaved big/res K tiles (one LDS.128 per S B-frag), transposed
// V tiles (one LDS.64 per PV B-frag), double-buffered cp.async, 3-pass bf16 S,
// tf32 PV. Final attn reconstructed from big+res (<<16 bit-tricks).
// ---------------------------------------------------------------------------
#define CORR_SMEM ((2 * 64 * KBRP + 2 * 64 * VTP + 128 * KP) * 4)
__global__ void __launch_bounds__(256, 2) corr_kernel()
{
    extern __shared__ float sm[];
    unsigned* KbrA = (unsigned*)sm;                  // [2][64][KBRP] interleaved
    float*    VtA  = (float*)(KbrA + 2 * 64 * KBRP); // [2][64][VTP] tf32 V^T
    float*    Ps   = VtA + 2 * 64 * VTP;             // [128][KP]

    const int t = threadIdx.x, lane = t & 31, warp = t >> 5;
    const int g = lane >> 2, t4 = lane & 3;
    const int rm0 = warp * 16;
    const int n0 = blockIdx.x * 128;
    const int p  = blockIdx.y;
    const unsigned* abr = g_abr + (size_t)p * NPP * 64;
    const float*    avt = g_avt + (size_t)p * NPP * NUM;

    const int rl0 = n0 + rm0 + g, rl1 = rl0 + 8;     // local rows
    const int pp0 = perm8(2 * t4), pp1 = perm8(2 * t4 + 1);

    // Q fragments (bf16 big/res) from interleaved blocks: one uint4 per (c,row)
    unsigned qb[4][4], qr[4][4];
#pragma unroll
    for (int c = 0; c < 4; c++) {
        uint4 u0 = *(const uint4*)&abr[(size_t)rl0 * 64 + c * 16 + 4 * t4];
        uint4 u1 = *(const uint4*)&abr[(size_t)rl1 * 64 + c * 16 + 4 * t4];
        qb[c][0] = u0.x; qb[c][1] = u1.x; qb[c][2] = u0.y; qb[c][3] = u1.y;
        qr[c][0] = u0.z; qr[c][1] = u1.z; qr[c][2] = u0.w; qr[c][3] = u1.w;
    }

    const int lrow = t >> 4, lc4 = (t & 15) * 4;     // loader: 16 chunks/row

#define CORR_LOAD(s, jt)                                                       \
    {                                                                          \
        unsigned* kbr = KbrA + (s) * 64 * KBRP;                                \
        float*    vt  = VtA  + (s) * 64 * VTP;                                 \
        _Pragma("unroll")                                                      \
        for (int i = 0; i < 4; i++) {                                          \
            int r = lrow + i * 16;                                             \
            cpa16(kbr + r * KBRP + lc4, abr + ((size_t)(jt) * 64 + r) * 64 + lc4); \
            cpa16(vt  + r * VTP  + lc4, avt + ((size_t)(jt) * 64 + r) * 64 + lc4); \
        }                                                                      \
        asm volatile("cp.async.commit_group;\n");                              \
    }

    float mi[2] = {-FLT_MAX, -FLT_MAX}, li[2] = {0.0f, 0.0f};
    float o[8][4] = {};

    CORR_LOAD(0, 0);
    for (int jt = 0; jt < 16; jt++) {
        int s = jt & 1;
        if (jt < 15) {
            CORR_LOAD(s ^ 1, jt + 1);
            asm volatile("cp.async.wait_group 1;\n");
        } else {
            asm volatile("cp.async.wait_group 0;\n");
        }
        __syncthreads();
        const unsigned* kbr = KbrA + s * 64 * KBRP;
        const float*    vt  = VtA  + s * 64 * VTP;

        // S = Q Kt via 3-pass bf16 split; B-frags = one LDS.128
        float sa[8][4] = {};
#pragma unroll
        for (int c = 0; c < 4; c++) {
#pragma unroll
            for (int nj = 0; nj < 8; nj++) {
                uint4 b = *(const uint4*)&kbr[(nj * 8 + g) * KBRP + c * 16 + 4 * t4];
                mmabf(sa[nj], qb[c][0], qb[c][1], qb[c][2], qb[c][3], b.x, b.y);
                mmabf(sa[nj], qb[c][0], qb[c][1], qb[c][2], qb[c][3], b.z, b.w);
                mmabf(sa[nj], qr[c][0], qr[c][1], qr[c][2], qr[c][3], b.x, b.y);
            }
        }

        // online softmax (warp-local rows)
#pragma unroll
        for (int h = 0; h < 2; h++) {
            float rmax = -FLT_MAX;
#pragma unroll
            for (int nj = 0; nj < 8; nj++)
                rmax = fmaxf(rmax, fmaxf(sa[nj][2 * h], sa[nj][2 * h + 1]));
            rmax = fmaxf(rmax, __shfl_xor_sync(0xffffffffu, rmax, 1));
            rmax = fmaxf(rmax, __shfl_xor_sync(0xffffffffu, rmax, 2));
            float nm = fmaxf(mi[h], rmax);
            float sc = __expf(mi[h] - nm);
            mi[h] = nm;
            float rs = 0.0f;
#pragma unroll
            for (int nj = 0; nj < 8; nj++) {
                float v0 = __expf(sa[nj][2 * h]     - nm);
                float v1 = __expf(sa[nj][2 * h + 1] - nm);
                sa[nj][2 * h] = v0; sa[nj][2 * h + 1] = v1;
                rs += v0 + v1;
            }
            rs += __shfl_xor_sync(0xffffffffu, rs, 1);
            rs += __shfl_xor_sync(0xffffffffu, rs, 2);
            li[h] = li[h] * sc + rs;
#pragma unroll
            for (int nj = 0; nj < 8; nj++) {
                o[nj][2 * h]     *= sc;
                o[nj][2 * h + 1] *= sc;
            }
        }

        // store P (tf32) into pair-perm Ps (warp-private rows)
#pragma unroll
        for (int h = 0; h < 2; h++) {
            int rb = (rm0 + g + h * 8) * KP;
#pragma unroll
            for (int nj = 0; nj < 8; nj++) {
                Ps[rb + nj * 8 + pp0] = t32(sa[nj][2 * h]);
                Ps[rb + nj * 8 + pp1] = t32(sa[nj][2 * h + 1]);
            }
        }
        __syncwarp();

        // O += P @ V (tf32); B-frags = one LDS.64 from transposed V
#pragma unroll
        for (int ks = 0; ks < 8; ks++) {
            int ko = ks * 8 + t4 * 2;
            float2 aA = *(const float2*)&Ps[(rm0 + g) * KP + ko];
            float2 aB = *(const float2*)&Ps[(rm0 + 8 + g) * KP + ko];
            unsigned a0 = __float_as_uint(aA.x), a1 = __float_as_uint(aB.x);
            unsigned a2 = __float_as_uint(aA.y), a3 = __float_as_uint(aB.y);
#pragma unroll
            for (int nj = 0; nj < 8; nj++) {
                float2 bv = *(const float2*)&vt[(nj * 8 + g) * VTP + ko];
                mma8(o[nj], a0, a1, a2, a3,
                     __float_as_uint(bv.x), __float_as_uint(bv.y));
            }
        }
        __syncthreads();
    }
#undef CORR_LOAD

    // final: F = softmax(attn + O/li); attn reconstructed from big+res
#pragma unroll
    for (int h = 0; h < 2; h++) {
        int rl = (h == 0) ? rl0 : rl1;
        float inv = 1.0f / li[h];
        float tv[16];
#pragma unroll
        for (int nj = 0; nj < 8; nj++) {
            int pbp = posb(nj * 4 + t4);
            unsigned ub = abr[(size_t)rl * 64 + pbp];
            unsigned ur = abr[(size_t)rl * 64 + pbp + 2];
            float a0 = __uint_as_float(ub << 16) + __uint_as_float(ur << 16);
            float a1 = __uint_as_float(ub & 0xffff0000u) + __uint_as_float(ur & 0xffff0000u);
            tv[nj * 2]     = a0 + o[nj][2 * h]     * inv;
            tv[nj * 2 + 1] = a1 + o[nj][2 * h + 1] * inv;
        }
        float rmax = -FLT_MAX;
#pragma unroll
        for (int l = 0; l < 16; l++) rmax = fmaxf(rmax, tv[l]);
        rmax = fmaxf(rmax, __shfl_xor_sync(0xffffffffu, rmax, 1));
        rmax = fmaxf(rmax, __shfl_xor_sync(0xffffffffu, rmax, 2));
        float rs = 0.0f;
#pragma unroll
        for (int l = 0; l < 16; l++) { tv[l] = __expf(tv[l] - rmax); rs += tv[l]; }
        rs += __shfl_xor_sync(0xffffffffu, rs, 1);
        rs += __shfl_xor_sync(0xffffffffu, rs, 2);
        float is = 1.0f / rs;
        int rb = (rm0 + g + h * 8) * KP;
#pragma unroll
        for (int nj = 0; nj < 8; nj++) {
            Ps[rb + nj * 8 + pp0] = t32(tv[nj * 2] * is);
            Ps[rb + nj * 8 + pp1] = t32(tv[nj * 2 + 1] * is);
        }
    }

    // out = F @ vp (4 chunks of 64 channels) -> g_mid; Vt buf 0 as scratch
    float* Vs = VtA;
    const int lj = t >> 2, ld0 = (t & 3) * 16;
    const int lpj = perm8(lj);
    for (int ch = 0; ch < 4; ch++) {
        __syncthreads();
        {
            const float* src = g_vp + (size_t)lj * HALF + ch * 64 + ld0;
#pragma unroll
            for (int u = 0; u < 4; u++) {
                float4 v = *(const float4*)(src + u * 4);
                float vv[4] = {v.x, v.y, v.z, v.w};
#pragma unroll
                for (int c2 = 0; c2 < 4; c2++)
                    Vs[(ld0 + u * 4 + c2) * VTP + lpj] = t32(vv[c2]);
            }
        }
        __syncthreads();

        float acc[8][4] = {};
#pragma unroll
        for (int ks = 0; ks < 8; ks++) {
            int ko = ks * 8 + t4 * 2;
            float2 aA = *(const float2*)&Ps[(rm0 + g) * KP + ko];
            float2 aB = *(const float2*)&Ps[(rm0 + 8 + g) * KP + ko];
            unsigned a0 = __float_as_uint(aA.x), a1 = __float_as_uint(aB.x);
            unsigned a2 = __float_as_uint(aA.y), a3 = __float_as_uint(aB.y);
#pragma unroll
            for (int nj = 0; nj < 8; nj++) {
                float2 bv = *(const float2*)&Vs[(nj * 8 + g) * VTP + ko];
                mma8(acc[nj], a0, a1, a2, a3,
                     __float_as_uint(bv.x), __float_as_uint(bv.y));
            }
        }
#pragma unroll
        for (int h = 0; h < 2; h++) {
            size_t pn = (size_t)p * NPP + n0 + rm0 + g + h * 8;
#pragma unroll
            for (int nj = 0; nj < 8; nj++) {
                int col = ch * 64 + nj * 8 + 2 * t4;
                *(float2*)&g_mid[pn * HALF + col] =
                    make_float2(acc[nj][2 * h], acc[nj][2 * h + 1]);
            }
        }
    }
}

// ---------------------------------------------------------------------------
// o-proj v3 (unchanged from R7)
// ---------------------------------------------------------------------------
#define OPR_SMEM ((2 * 128 * 36 + 2 * 128 * 36) * 4)
__global__ void __launch_bounds__(256, 2) oproj_kernel(
    const float* __restrict__ x, const float* __restrict__ ow,
    float* __restrict__ out)
{
    extern __shared__ float smo[];
    float* As = smo;
    float* Bs = smo + 2 * 128 * 36;

    const int t = threadIdx.x, lane = t & 31, warp = t >> 5;
    const int g = lane >> 2, t4 = lane & 3;
    const int wm = (warp & 1) * 64, wn = (warp >> 1) * 32;
    const int ocr = blockIdx.x * 128;
    const int pn0 = blockIdx.y * 128;

    float acc[4][4][4] = {};

    const int a_row = t >> 3, a_c4 = (t & 7) * 4;

#define OPR_LOAD(s, k0)                                                        \
    {                                                                          \
        float* as = As + (s) * 128 * 36;                                       \
        float* bs = Bs + (s) * 128 * 36;                                       \
        _Pragma("unroll")                                                      \
        for (int i = 0; i < 4; i++)                                            \
            cpa16(as + (a_row + i * 32) * 36 + a_c4,                           \
                  g_mid + (size_t)(pn0 + a_row + i * 32) * HALF + (k0) + a_c4);\
        _Pragma("unroll")                                                      \
        for (int i = 0; i < 4; i++)                                            \
            cpa16(bs + (a_row + i * 32) * 36 + a_c4,                           \
                  ow + (size_t)(ocr + a_row + i * 32) * HALF + (k0) + a_c4);   \
        asm volatile("cp.async.commit_group;\n");                              \
    }

    OPR_LOAD(0, 0);
    for (int kt = 0; kt < 8; kt++) {
        int s = kt & 1;
        if (kt < 7) {
            OPR_LOAD(s ^ 1, (kt + 1) * 32);
            asm volatile("cp.async.wait_group 1;\n");
        } else {
            asm volatile("cp.async.wait_group 0;\n");
        }
        __syncthreads();
        const float* as = As + s * 128 * 36;
        const float* bs = Bs + s * 128 * 36;
#pragma unroll
        for (int kk = 0; kk < 32; kk += 8) {
            unsigned a[4][4], b[4][2];
#pragma unroll
            for (int mi = 0; mi < 4; mi++) {
                int mb = wm + mi * 16 + g;
                a[mi][0] = __float_as_uint(as[mb * 36 + kk + t4]);
                a[mi][1] = __float_as_uint(as[(mb + 8) * 36 + kk + t4]);
                a[mi][2] = __float_as_uint(as[mb * 36 + kk + t4 + 4]);
                a[mi][3] = __float_as_uint(as[(mb + 8) * 36 + kk + t4 + 4]);
            }
#pragma unroll
            for (int nj = 0; nj < 4; nj++) {
                int nb = wn + nj * 8 + g;
                b[nj][0] = __float_as_uint(bs[nb * 36 + kk + t4]);
                b[nj][1] = __float_as_uint(bs[nb * 36 + kk + t4 + 4]);
            }
#pragma unroll
            for (int mi = 0; mi < 4; mi++)
#pragma unroll
                for (int nj = 0; nj < 4; nj++)
                    mma8(acc[mi][nj], a[mi][0], a[mi][1], a[mi][2], a[mi][3],
                         b[nj][0], b[nj][1]);
        }
        __syncthreads();
    }
#undef OPR_LOAD

#pragma unroll
    for (int mi = 0; mi < 4; mi++)
#pragma unroll
        for (int h2 = 0; h2 < 2; h2++) {
            int pn = pn0 + wm + mi * 16 + g + h2 * 8;
            int p = pn >> 10, n = pn & 1023;
            int h = ((p >> 3) << 5) + (n >> 5);
            int w = ((p & 7) << 5) + (n & 31);
            int base = h * W_IMG + w;
#pragma unroll
            for (int nj = 0; nj < 4; nj++) {
                int oc = ocr + wn + nj * 8 + t4 * 2;
                float s0 = g_pscale[768 + oc],     b0 = g_pbias[768 + oc];
                float s1 = g_pscale[768 + oc + 1], b1 = g_pbias[768 + oc + 1];
                size_t i0 = (size_t)oc * HW + base;
                size_t i1 = i0 + HW;
                out[i0] = fmaxf(fmaf(acc[mi][nj][h2 * 2],     s0, b0), 0.0f) + x[i0];
                out[i1] = fmaxf(fmaf(acc[mi][nj][h2 * 2 + 1], s1, b1), 0.0f) + x[i1];
            }
        }
}

// ---------------------------------------------------------------------------
extern "C" void kernel_launch(void* const* d_in, const int* in_sizes, int n_in,
                              void* d_out, int out_size)
{
    (void)in_sizes; (void)n_in; (void)out_size;
    const float* x  = (const float*)d_in[0];
    const float* qw = (const float*)d_in[1];
    const float* kw = (const float*)d_in[6];
    const float* vw = (const float*)d_in[11];
    const float* ow = (const float*)d_in[16];

    cudaFuncSetAttribute(corr_kernel,
                         cudaFuncAttributeMaxDynamicSharedMemorySize, CORR_SMEM);
    cudaFuncSetAttribute(qkv_kernel,
                         cudaFuncAttributeMaxDynamicSharedMemorySize, QKV_SMEM);
    cudaFuncSetAttribute(oproj_kernel,
                         cudaFuncAttributeMaxDynamicSharedMemorySize, OPR_SMEM);

    prep_kernel<<<134, 256>>>(
        (const float*)d_in[2],  (const float*)d_in[3],  (const float*)d_in[4],  (const float*)d_in[5],
        (const float*)d_in[7],  (const float*)d_in[8],  (const float*)d_in[9],  (const float*)d_in[10],
        (const float*)d_in[12], (const float*)d_in[13], (const float*)d_in[14], (const float*)d_in[15],
        (const float*)d_in[17], (const float*)d_in[18], (const float*)d_in[19], (const float*)d_in[20]);

    qkv_kernel<<<dim3(6, 512), 256, QKV_SMEM>>>(x, qw, kw, vw);
    attnqk_kernel<<<512, 256>>>();
    corr_kernel<<<dim3(8, 64), 256, CORR_SMEM>>>();
    oproj_kernel<<<dim3(4, 512), 256, OPR_SMEM>>>(x, ow, (float*)d_out);
}